// round 1
// baseline (speedup 1.0000x reference)
#include <cuda_runtime.h>
#include <cstdint>

// Problem constants
#define BATCH 8
#define CH    512
#define NTOK  1024          // H*W = 32*32
#define C3    1536          // 3*CH
#define GRP   8
#define CPG   64            // CH/GRP
#define GSIZE 65536         // CPG*NTOK elements per (b,g)

// Scratch (device globals: allocation-free rule)
__device__ float g_xn  [BATCH * CH   * NTOK];  // [B, C, N] groupnorm output (residual)
__device__ float g_qkv [BATCH * NTOK * C3  ];  // [B, N, 3C]
__device__ float g_ctx [BATCH * CH   * CH  ];  // [B, C, C]
__device__ float g_out1[BATCH * NTOK * CH  ];  // [B, N, C]

// ---------------------------------------------------------------------------
// GroupNorm: one block per (b, g). Group data is contiguous (256KB).
// Writes xn in [B, C, N] layout (same as input layout).
// ---------------------------------------------------------------------------
__global__ __launch_bounds__(512) void gn_kernel(const float* __restrict__ x,
                                                 const float* __restrict__ gamma,
                                                 const float* __restrict__ beta) {
    int b = blockIdx.x >> 3, g = blockIdx.x & 7;
    size_t off = ((size_t)b * CH + (size_t)g * CPG) * NTOK;
    const float4* xp = reinterpret_cast<const float4*>(x + off);
    float4* op = reinterpret_cast<float4*>(g_xn + off);
    int t = threadIdx.x;

    float s = 0.f, sq = 0.f;
    for (int i = t; i < GSIZE / 4; i += 512) {
        float4 v = xp[i];
        s  += v.x + v.y + v.z + v.w;
        sq += v.x * v.x + v.y * v.y + v.z * v.z + v.w * v.w;
    }
    __shared__ float rs[512], rq[512];
    rs[t] = s; rq[t] = sq;
    __syncthreads();
    for (int o = 256; o >= 1; o >>= 1) {
        if (t < o) { rs[t] += rs[t + o]; rq[t] += rq[t + o]; }
        __syncthreads();
    }
    float mean = rs[0] * (1.f / GSIZE);
    float var  = rq[0] * (1.f / GSIZE) - mean * mean;
    float rstd = rsqrtf(var + 1e-5f);

    for (int i = t; i < GSIZE / 4; i += 512) {
        int c = g * CPG + (i >> 8);                 // (4*i)/NTOK
        float gm = gamma[c] * rstd;
        float bt = beta[c] - mean * gm;
        float4 v = xp[i];
        v.x = v.x * gm + bt; v.y = v.y * gm + bt;
        v.z = v.z * gm + bt; v.w = v.w * gm + bt;
        op[i] = v;
    }
}

// ---------------------------------------------------------------------------
// Generic SGEMM: C[m,n] = sum_k A(m,k)*B(k,n), BM=BN=128, BK=8, 256 thr, 8x8/thr
// A_KC: true  -> A element (m,k) at A[m*lda + k]   (k contiguous)
//       false -> A element (m,k) at A[k*lda + m]   (m contiguous)
// B_KC: true  -> B element (k,n) at B[n*ldb + k]   (k contiguous)
//       false -> B element (k,n) at B[k*ldb + n]   (n contiguous)
// EP 0: C[m*ldc+n] = acc + bias[n]
// EP 1: C[m*ldc+n] = acc
// EP 2: C[n*ldc+m] = acc + bias[n] + resid[n*ldc+m]   (transposed write)
// Grid: (N/128, M/128, batch)
// ---------------------------------------------------------------------------
template <bool A_KC, bool B_KC, int EP>
__global__ __launch_bounds__(256) void sgemm_kernel(
    const float* __restrict__ A, const float* __restrict__ B, float* __restrict__ C,
    int K, int lda, int ldb, int ldc,
    long long sAb, long long sBb, long long sCb,
    const float* __restrict__ bias, const float* __restrict__ resid, long long sRb)
{
    __shared__ float As[8][128];
    __shared__ float Bs[8][128];

    int bz = blockIdx.z;
    A += (size_t)bz * sAb;
    B += (size_t)bz * sBb;
    C += (size_t)bz * sCb;
    const float* R = (EP == 2) ? (resid + (size_t)bz * sRb) : nullptr;

    int m0 = blockIdx.y * 128, n0 = blockIdx.x * 128;
    int tid = threadIdx.x;
    int tx = tid & 15, ty = tid >> 4;

    float acc[8][8];
#pragma unroll
    for (int i = 0; i < 8; i++)
#pragma unroll
        for (int j = 0; j < 8; j++) acc[i][j] = 0.f;

    for (int k0 = 0; k0 < K; k0 += 8) {
        // ---- load A tile ----
        if (!A_KC) {
            int m = (tid & 31) * 4, kk = tid >> 5;
            float4 v = *reinterpret_cast<const float4*>(&A[(size_t)(k0 + kk) * lda + m0 + m]);
            *reinterpret_cast<float4*>(&As[kk][m]) = v;
        } else {
            int kk = (tid & 1) * 4, m = tid >> 1;
            float4 v = *reinterpret_cast<const float4*>(&A[(size_t)(m0 + m) * lda + k0 + kk]);
            As[kk + 0][m] = v.x; As[kk + 1][m] = v.y;
            As[kk + 2][m] = v.z; As[kk + 3][m] = v.w;
        }
        // ---- load B tile ----
        if (!B_KC) {
            int n = (tid & 31) * 4, kk = tid >> 5;
            float4 v = *reinterpret_cast<const float4*>(&B[(size_t)(k0 + kk) * ldb + n0 + n]);
            *reinterpret_cast<float4*>(&Bs[kk][n]) = v;
        } else {
            int kk = (tid & 1) * 4, n = tid >> 1;
            float4 v = *reinterpret_cast<const float4*>(&B[(size_t)(n0 + n) * ldb + k0 + kk]);
            Bs[kk + 0][n] = v.x; Bs[kk + 1][n] = v.y;
            Bs[kk + 2][n] = v.z; Bs[kk + 3][n] = v.w;
        }
        __syncthreads();

#pragma unroll
        for (int kk = 0; kk < 8; kk++) {
            float ra[8], rb[8];
            *reinterpret_cast<float4*>(&ra[0]) = *reinterpret_cast<const float4*>(&As[kk][ty * 8]);
            *reinterpret_cast<float4*>(&ra[4]) = *reinterpret_cast<const float4*>(&As[kk][ty * 8 + 4]);
            *reinterpret_cast<float4*>(&rb[0]) = *reinterpret_cast<const float4*>(&Bs[kk][tx * 8]);
            *reinterpret_cast<float4*>(&rb[4]) = *reinterpret_cast<const float4*>(&Bs[kk][tx * 8 + 4]);
#pragma unroll
            for (int i = 0; i < 8; i++)
#pragma unroll
                for (int j = 0; j < 8; j++) acc[i][j] += ra[i] * rb[j];
        }
        __syncthreads();
    }

    // ---- epilogue ----
    if (EP == 0 || EP == 1) {
        float bv[8];
        if (EP == 0) {
#pragma unroll
            for (int j = 0; j < 8; j++) bv[j] = bias[n0 + tx * 8 + j];
        }
#pragma unroll
        for (int i = 0; i < 8; i++) {
            size_t row = (size_t)(m0 + ty * 8 + i) * ldc + n0 + tx * 8;
#pragma unroll
            for (int jj = 0; jj < 8; jj += 4) {
                float4 o;
                o.x = acc[i][jj + 0] + (EP == 0 ? bv[jj + 0] : 0.f);
                o.y = acc[i][jj + 1] + (EP == 0 ? bv[jj + 1] : 0.f);
                o.z = acc[i][jj + 2] + (EP == 0 ? bv[jj + 2] : 0.f);
                o.w = acc[i][jj + 3] + (EP == 0 ? bv[jj + 3] : 0.f);
                *reinterpret_cast<float4*>(&C[row + jj]) = o;
            }
        }
    } else {  // EP == 2: transposed write + bias + residual
#pragma unroll
        for (int j = 0; j < 8; j++) {
            int n = n0 + tx * 8 + j;
            float bv = bias[n];
            size_t base = (size_t)n * ldc + m0 + ty * 8;
#pragma unroll
            for (int ii = 0; ii < 8; ii += 4) {
                float4 r = *reinterpret_cast<const float4*>(&R[base + ii]);
                float4 o;
                o.x = acc[ii + 0][j] + bv + r.x;
                o.y = acc[ii + 1][j] + bv + r.y;
                o.z = acc[ii + 2][j] + bv + r.z;
                o.w = acc[ii + 3][j] + bv + r.w;
                *reinterpret_cast<float4*>(&C[base + ii]) = o;
            }
        }
    }
}

// ---------------------------------------------------------------------------
// k softmax: per (b,n) row over C=512 channels. One block per row.
// ---------------------------------------------------------------------------
__global__ __launch_bounds__(256) void ksoftmax_kernel() {
    float* row = g_qkv + (size_t)blockIdx.x * C3 + CH;   // k = qkv[..., 512:1024]
    int t = threadIdx.x;
    float a = row[t], b = row[t + 256];
    __shared__ float sm[256];
    sm[t] = fmaxf(a, b);
    __syncthreads();
    for (int o = 128; o >= 1; o >>= 1) {
        if (t < o) sm[t] = fmaxf(sm[t], sm[t + o]);
        __syncthreads();
    }
    float mx = sm[0];
    __syncthreads();
    float ea = __expf(a - mx), eb = __expf(b - mx);
    sm[t] = ea + eb;
    __syncthreads();
    for (int o = 128; o >= 1; o >>= 1) {
        if (t < o) sm[t] += sm[t + o];
        __syncthreads();
    }
    float inv = 1.f / sm[0];
    row[t] = ea * inv;
    row[t + 256] = eb * inv;
}

// ---------------------------------------------------------------------------
// q softmax: per (b,c) column over N=1024 tokens (stride C3 in memory).
// Block handles 32 channels; lanes span channels for coalescing.
// 8 row-chunks of 128 tokens reduced via shared mem. Online max/sum.
// ---------------------------------------------------------------------------
__global__ __launch_bounds__(256) void qsoftmax_kernel() {
    int b  = blockIdx.x >> 4;            // 16 blocks per batch
    int c0 = (blockIdx.x & 15) * 32;
    float* base = g_qkv + (size_t)b * NTOK * C3 + c0;    // q at channel offset 0
    int cl = threadIdx.x & 31, j = threadIdx.x >> 5;     // j in [0,8)

    float mx = -1e30f, sum = 0.f;
    for (int i = 0; i < 128; i++) {
        float v = base[(size_t)(j * 128 + i) * C3 + cl];
        float nm = fmaxf(mx, v);
        sum = sum * __expf(mx - nm) + __expf(v - nm);
        mx = nm;
    }
    __shared__ float sM[8][32], sS[8][32];
    sM[j][cl] = mx; sS[j][cl] = sum;
    __syncthreads();
    if (j == 0) {
        float M = sM[0][cl], S = sS[0][cl];
#pragma unroll
        for (int jj = 1; jj < 8; jj++) {
            float m2 = sM[jj][cl], s2 = sS[jj][cl];
            float nm = fmaxf(M, m2);
            S = S * __expf(M - nm) + s2 * __expf(m2 - nm);
            M = nm;
        }
        sM[0][cl] = M; sS[0][cl] = 1.f / S;
    }
    __syncthreads();
    float M = sM[0][cl], inv = sS[0][cl];
    for (int i = 0; i < 128; i++) {
        size_t idx = (size_t)(j * 128 + i) * C3 + cl;
        base[idx] = __expf(base[idx] - M) * inv;
    }
}

// ---------------------------------------------------------------------------
// Launch
// ---------------------------------------------------------------------------
extern "C" void kernel_launch(void* const* d_in, const int* in_sizes, int n_in,
                              void* d_out, int out_size) {
    const float* x      = (const float*)d_in[0];
    const float* gn_w   = (const float*)d_in[1];
    const float* gn_b   = (const float*)d_in[2];
    const float* qkv_w  = (const float*)d_in[3];
    const float* qkv_b  = (const float*)d_in[4];
    const float* proj_w = (const float*)d_in[5];
    const float* proj_b = (const float*)d_in[6];
    float* out = (float*)d_out;

    void *p_xn, *p_qkv, *p_ctx, *p_out1;
    cudaGetSymbolAddress(&p_xn,  g_xn);
    cudaGetSymbolAddress(&p_qkv, g_qkv);
    cudaGetSymbolAddress(&p_ctx, g_ctx);
    cudaGetSymbolAddress(&p_out1, g_out1);
    float* xn  = (float*)p_xn;
    float* qkv = (float*)p_qkv;
    float* ctx = (float*)p_ctx;
    float* out1 = (float*)p_out1;

    // 1) GroupNorm -> g_xn [B, C, N]
    gn_kernel<<<BATCH * GRP, 512>>>(x, gn_w, gn_b);

    // 2) QKV GEMM: qkv[b,n,d] = sum_c xn[b,c,n] * W[d,c] + bias[d]
    //    A: m-contig (k stride NTOK); B: k-contig (n stride CH); EP0 bias.
    sgemm_kernel<false, true, 0><<<dim3(C3 / 128, NTOK / 128, BATCH), 256>>>(
        xn, qkv_w, qkv, CH, NTOK, CH, C3,
        (long long)CH * NTOK, 0LL, (long long)NTOK * C3,
        qkv_b, nullptr, 0LL);

    // 3) softmaxes (in place on g_qkv)
    ksoftmax_kernel<<<BATCH * NTOK, 256>>>();
    qsoftmax_kernel<<<BATCH * (CH / 32), 256>>>();

    // 4) context[b,c,d] = sum_n k[b,n,c] * v[b,n,d]
    //    A (k-part): m-contig, k stride C3; B (v-part): n-contig, k stride C3.
    sgemm_kernel<false, false, 1><<<dim3(CH / 128, CH / 128, BATCH), 256>>>(
        qkv + CH, qkv + 2 * CH, ctx, NTOK, C3, C3, CH,
        (long long)NTOK * C3, (long long)NTOK * C3, (long long)CH * CH,
        nullptr, nullptr, 0LL);

    // 5) out1[b,n,d] = sum_c q[b,n,c] * ctx[b,c,d]
    //    A (q): k-contig, m stride C3; B: n-contig, k stride CH.
    sgemm_kernel<true, false, 1><<<dim3(CH / 128, NTOK / 128, BATCH), 256>>>(
        qkv, ctx, out1, CH, C3, CH, CH,
        (long long)NTOK * C3, (long long)CH * CH, (long long)NTOK * CH,
        nullptr, nullptr, 0LL);

    // 6) out[b,d,n] = sum_c out1[b,n,c]*proj_w[d,c] + proj_b[d] + xn[b,d,n]
    //    A: k-contig (m stride CH); B: k-contig (n stride CH); EP2 transposed+resid.
    sgemm_kernel<true, true, 2><<<dim3(CH / 128, NTOK / 128, BATCH), 256>>>(
        out1, proj_w, out, CH, CH, CH, NTOK,
        (long long)NTOK * CH, 0LL, (long long)CH * NTOK,
        proj_b, xn, (long long)CH * NTOK);
}

// round 3
// speedup vs baseline: 1.4024x; 1.4024x over previous
#include <cuda_runtime.h>
#include <cuda_bf16.h>
#include <cstdint>

#define BATCH 8
#define CH    512
#define NTOK  1024
#define C3    1536
#define GRP   8
#define CPG   64
#define GSIZE 65536

#define BK    32
#define SAK   34                      // padded row stride (bf16 elems)
#define TILE_ELEMS (128 * SAK)        // one 128xBK tile (hi OR lo)
#define SMEM_SZ (8 * TILE_ELEMS * 2)  // A/B x 2 bufs x (hi,lo), bytes = 69632

// Scratch (device globals; allocation-free rule)
__device__ float g_xn  [BATCH * CH   * NTOK];   // [B, C, N]  groupnorm out (residual)
__device__ float g_qkvT[BATCH * C3   * NTOK];   // [B, 3C, N] q 0..511, k 512..1023, v 1024..1535
__device__ float g_ctxT[BATCH * CH   * CH  ];   // [B, d, c]
__device__ float g_out1[BATCH * NTOK * CH  ];   // [B, n, d]

// ---------------------------------------------------------------------------
// bf16 split helpers
// ---------------------------------------------------------------------------
__device__ __forceinline__ void split_bf16(float x, __nv_bfloat16& h, __nv_bfloat16& l) {
    h = __float2bfloat16_rn(x);
    l = __float2bfloat16_rn(x - __bfloat162float(h));
}

__device__ __forceinline__ void mma16816(float* c, uint32_t a0, uint32_t a1,
                                         uint32_t a2, uint32_t a3,
                                         uint32_t b0, uint32_t b1) {
    asm volatile(
        "mma.sync.aligned.m16n8k16.row.col.f32.bf16.bf16.f32 "
        "{%0,%1,%2,%3},{%4,%5,%6,%7},{%8,%9},{%0,%1,%2,%3};"
        : "+f"(c[0]), "+f"(c[1]), "+f"(c[2]), "+f"(c[3])
        : "r"(a0), "r"(a1), "r"(a2), "r"(a3), "r"(b0), "r"(b1));
}

// ---------------------------------------------------------------------------
// Global -> register staging (4 x float4 per thread = 128 x 32 tile / 256 thr)
// TR=false: element (r,k) at src[(row0+r)*ld + k0+k]      (k contiguous)
// TR=true : element (r,k) at src[(k0+k)*ld + row0+r]      (r contiguous)
// ---------------------------------------------------------------------------
template <bool TR>
__device__ __forceinline__ void load_g(float4* p, const float* __restrict__ src,
                                       int ld, int row0, int k0, int tid) {
#pragma unroll
    for (int it = 0; it < 4; it++) {
        if (!TR) {
            int r = it * 32 + (tid >> 3);
            p[it] = *reinterpret_cast<const float4*>(
                src + (size_t)(row0 + r) * ld + k0 + (tid & 7) * 4);
        } else {
            int r = it * 32 + (tid & 7) * 4;
            p[it] = *reinterpret_cast<const float4*>(
                src + (size_t)(k0 + (tid >> 3)) * ld + row0 + r);
        }
    }
}

// Register -> SMEM (convert to hi/lo). dst points at hi tile; lo at +TILE_ELEMS.
template <bool TR>
__device__ __forceinline__ void store_s(__nv_bfloat16* dst, const float4* p, int tid) {
#pragma unroll
    for (int it = 0; it < 4; it++) {
        float4 v = p[it];
        __nv_bfloat16 h0, h1, h2, h3, l0, l1, l2, l3;
        split_bf16(v.x, h0, l0); split_bf16(v.y, h1, l1);
        split_bf16(v.z, h2, l2); split_bf16(v.w, h3, l3);
        if (!TR) {
            int r = it * 32 + (tid >> 3), k = (tid & 7) * 4;
            __nv_bfloat16* ph = dst + r * SAK + k;
            *reinterpret_cast<__nv_bfloat162*>(ph)     = __nv_bfloat162(h0, h1);
            *reinterpret_cast<__nv_bfloat162*>(ph + 2) = __nv_bfloat162(h2, h3);
            __nv_bfloat16* pl = ph + TILE_ELEMS;
            *reinterpret_cast<__nv_bfloat162*>(pl)     = __nv_bfloat162(l0, l1);
            *reinterpret_cast<__nv_bfloat162*>(pl + 2) = __nv_bfloat162(l2, l3);
        } else {
            int r = it * 32 + (tid & 7) * 4, k = tid >> 3;
            __nv_bfloat16* ph = dst + r * SAK + k;
            ph[0] = h0; ph[SAK] = h1; ph[2 * SAK] = h2; ph[3 * SAK] = h3;
            __nv_bfloat16* pl = ph + TILE_ELEMS;
            pl[0] = l0; pl[SAK] = l1; pl[2 * SAK] = l2; pl[3 * SAK] = l3;
        }
    }
}

// ---------------------------------------------------------------------------
// bf16x3 mma GEMM: D[128m x 128n] = sum_k A(m,k)*B(n,k)
// EP 0: C = acc   EP 1: C = acc + bias[m]   EP 2: C = acc + bias[m] + resid
// Grid (N/128, M/128, batch), 256 threads (8 warps, 2x4 of 64x32 warp tiles).
// ---------------------------------------------------------------------------
template <bool AT, bool BT, int EP>
__global__ __launch_bounds__(256, 1) void gemm_mma(
    const float* __restrict__ A, const float* __restrict__ B, float* __restrict__ C,
    int K, int lda, int ldb, int ldc,
    long long sA, long long sB, long long sC,
    const float* __restrict__ bias, const float* __restrict__ resid, long long sR)
{
    extern __shared__ __nv_bfloat16 sm[];
    __nv_bfloat16* Abuf[2] = { sm,                  sm + 2 * TILE_ELEMS };
    __nv_bfloat16* Bbuf[2] = { sm + 4 * TILE_ELEMS, sm + 6 * TILE_ELEMS };

    const int tid = threadIdx.x;
    const int bz = blockIdx.z;
    A += (size_t)bz * sA;
    B += (size_t)bz * sB;
    C += (size_t)bz * sC;
    const float* R = (EP == 2) ? (resid + (size_t)bz * sR) : nullptr;
    const int m0 = blockIdx.y * 128, n0 = blockIdx.x * 128;

    const int lane = tid & 31, wid = tid >> 5;
    const int g = lane >> 2, tg = lane & 3;
    const int wm = (wid & 1) * 64, wn = (wid >> 1) * 32;

    float acc[4][4][4];
#pragma unroll
    for (int i = 0; i < 4; i++)
#pragma unroll
        for (int j = 0; j < 4; j++)
#pragma unroll
            for (int q = 0; q < 4; q++) acc[i][j][q] = 0.f;

    float4 pa[4], pb[4];
    load_g<AT>(pa, A, lda, m0, 0, tid);
    load_g<BT>(pb, B, ldb, n0, 0, tid);
    store_s<AT>(Abuf[0], pa, tid);
    store_s<BT>(Bbuf[0], pb, tid);
    __syncthreads();

    const int NC = K / BK;
    for (int c = 0; c < NC; c++) {
        if (c + 1 < NC) {
            load_g<AT>(pa, A, lda, m0, (c + 1) * BK, tid);
            load_g<BT>(pb, B, ldb, n0, (c + 1) * BK, tid);
        }
        const __nv_bfloat16* Ah = Abuf[c & 1];
        const __nv_bfloat16* Bh = Bbuf[c & 1];

#pragma unroll
        for (int ks = 0; ks < BK; ks += 16) {
            // B fragments for 4 n-tiles (hi & lo)
            uint32_t bh[4][2], bl[4][2];
#pragma unroll
            for (int nt = 0; nt < 4; nt++) {
                const __nv_bfloat16* bp = Bh + (wn + nt * 8 + g) * SAK + ks + tg * 2;
                bh[nt][0] = *reinterpret_cast<const uint32_t*>(bp);
                bh[nt][1] = *reinterpret_cast<const uint32_t*>(bp + 8);
                bl[nt][0] = *reinterpret_cast<const uint32_t*>(bp + TILE_ELEMS);
                bl[nt][1] = *reinterpret_cast<const uint32_t*>(bp + TILE_ELEMS + 8);
            }
#pragma unroll
            for (int mt = 0; mt < 4; mt++) {
                const __nv_bfloat16* ap = Ah + (wm + mt * 16 + g) * SAK + ks + tg * 2;
                uint32_t ah0 = *reinterpret_cast<const uint32_t*>(ap);
                uint32_t ah1 = *reinterpret_cast<const uint32_t*>(ap + 8 * SAK);
                uint32_t ah2 = *reinterpret_cast<const uint32_t*>(ap + 8);
                uint32_t ah3 = *reinterpret_cast<const uint32_t*>(ap + 8 * SAK + 8);
                uint32_t al0 = *reinterpret_cast<const uint32_t*>(ap + TILE_ELEMS);
                uint32_t al1 = *reinterpret_cast<const uint32_t*>(ap + TILE_ELEMS + 8 * SAK);
                uint32_t al2 = *reinterpret_cast<const uint32_t*>(ap + TILE_ELEMS + 8);
                uint32_t al3 = *reinterpret_cast<const uint32_t*>(ap + TILE_ELEMS + 8 * SAK + 8);
#pragma unroll
                for (int nt = 0; nt < 4; nt++) {
                    mma16816(acc[mt][nt], ah0, ah1, ah2, ah3, bh[nt][0], bh[nt][1]);
                    mma16816(acc[mt][nt], ah0, ah1, ah2, ah3, bl[nt][0], bl[nt][1]);
                    mma16816(acc[mt][nt], al0, al1, al2, al3, bh[nt][0], bh[nt][1]);
                }
            }
        }
        if (c + 1 < NC) {
            __syncthreads();
            store_s<AT>(Abuf[(c + 1) & 1], pa, tid);
            store_s<BT>(Bbuf[(c + 1) & 1], pb, tid);
            __syncthreads();
        }
    }

    // ---- epilogue ----
#pragma unroll
    for (int mt = 0; mt < 4; mt++) {
        int m = m0 + wm + mt * 16 + g;
        float bv0 = (EP >= 1) ? bias[m]     : 0.f;
        float bv1 = (EP >= 1) ? bias[m + 8] : 0.f;
#pragma unroll
        for (int nt = 0; nt < 4; nt++) {
            int n = n0 + wn + nt * 8 + tg * 2;
            float* c = acc[mt][nt];
            size_t i0 = (size_t)m * ldc + n;
            size_t i1 = (size_t)(m + 8) * ldc + n;
            float2 o0, o1;
            o0.x = c[0] + bv0; o0.y = c[1] + bv0;
            o1.x = c[2] + bv1; o1.y = c[3] + bv1;
            if (EP == 2) {
                float2 r0 = *reinterpret_cast<const float2*>(R + i0);
                float2 r1 = *reinterpret_cast<const float2*>(R + i1);
                o0.x += r0.x; o0.y += r0.y;
                o1.x += r1.x; o1.y += r1.y;
            }
            *reinterpret_cast<float2*>(C + i0) = o0;
            *reinterpret_cast<float2*>(C + i1) = o1;
        }
    }
}

// ---------------------------------------------------------------------------
// GroupNorm: one block per (b, g). Writes g_xn in [B, C, N].
// ---------------------------------------------------------------------------
__global__ __launch_bounds__(512) void gn_kernel(const float* __restrict__ x,
                                                 const float* __restrict__ gamma,
                                                 const float* __restrict__ beta) {
    int b = blockIdx.x >> 3, g = blockIdx.x & 7;
    size_t off = ((size_t)b * CH + (size_t)g * CPG) * NTOK;
    const float4* xp = reinterpret_cast<const float4*>(x + off);
    float4* op = reinterpret_cast<float4*>(g_xn + off);
    int t = threadIdx.x;

    float s = 0.f, sq = 0.f;
    for (int i = t; i < GSIZE / 4; i += 512) {
        float4 v = xp[i];
        s  += v.x + v.y + v.z + v.w;
        sq += v.x * v.x + v.y * v.y + v.z * v.z + v.w * v.w;
    }
    __shared__ float rs[512], rq[512];
    rs[t] = s; rq[t] = sq;
    __syncthreads();
    for (int o = 256; o >= 1; o >>= 1) {
        if (t < o) { rs[t] += rs[t + o]; rq[t] += rq[t + o]; }
        __syncthreads();
    }
    float mean = rs[0] * (1.f / GSIZE);
    float var  = rq[0] * (1.f / GSIZE) - mean * mean;
    float rstd = rsqrtf(var + 1e-5f);

    for (int i = t; i < GSIZE / 4; i += 512) {
        int c = g * CPG + (i >> 8);
        float gm = gamma[c] * rstd;
        float bt = beta[c] - mean * gm;
        float4 v = xp[i];
        v.x = v.x * gm + bt; v.y = v.y * gm + bt;
        v.z = v.z * gm + bt; v.w = v.w * gm + bt;
        op[i] = v;
    }
}

// ---------------------------------------------------------------------------
// k softmax: over c (512 rows of k block) for each (b, n). qkvT layout.
// ---------------------------------------------------------------------------
__global__ __launch_bounds__(256) void ksoftmax_kernel() {
    int b = blockIdx.x >> 5;
    int n0 = (blockIdx.x & 31) * 32;
    float* base = g_qkvT + (size_t)b * C3 * NTOK + (size_t)CH * NTOK + n0;
    int lane = threadIdx.x & 31, j = threadIdx.x >> 5;

    float mx = -1e30f, sum = 0.f;
    for (int i = 0; i < 64; i++) {
        float v = base[(size_t)(j * 64 + i) * NTOK + lane];
        float nm = fmaxf(mx, v);
        sum = sum * __expf(mx - nm) + __expf(v - nm);
        mx = nm;
    }
    __shared__ float sM[8][32], sS[8][32];
    sM[j][lane] = mx; sS[j][lane] = sum;
    __syncthreads();
    if (j == 0) {
        float M = sM[0][lane], S = sS[0][lane];
#pragma unroll
        for (int t = 1; t < 8; t++) {
            float m2 = sM[t][lane], s2 = sS[t][lane];
            float nm = fmaxf(M, m2);
            S = S * __expf(M - nm) + s2 * __expf(m2 - nm);
            M = nm;
        }
        sM[0][lane] = M; sS[0][lane] = 1.f / S;
    }
    __syncthreads();
    float M = sM[0][lane], inv = sS[0][lane];
    for (int i = 0; i < 64; i++) {
        size_t idx = (size_t)(j * 64 + i) * NTOK + lane;
        base[idx] = __expf(base[idx] - M) * inv;
    }
}

// ---------------------------------------------------------------------------
// q softmax: over n (contiguous 1024) per (b, c) row of q block.
// ---------------------------------------------------------------------------
__global__ __launch_bounds__(256) void qsoftmax_kernel() {
    float* p = g_qkvT + (size_t)(blockIdx.x >> 9) * C3 * NTOK
                      + (size_t)(blockIdx.x & 511) * NTOK;
    int t = threadIdx.x;
    float4 v = reinterpret_cast<float4*>(p)[t];
    float mx = fmaxf(fmaxf(v.x, v.y), fmaxf(v.z, v.w));
    __shared__ float sh[256];
    sh[t] = mx;
    __syncthreads();
    for (int o = 128; o >= 1; o >>= 1) {
        if (t < o) sh[t] = fmaxf(sh[t], sh[t + o]);
        __syncthreads();
    }
    float M = sh[0];
    __syncthreads();
    float e0 = __expf(v.x - M), e1 = __expf(v.y - M);
    float e2 = __expf(v.z - M), e3 = __expf(v.w - M);
    sh[t] = e0 + e1 + e2 + e3;
    __syncthreads();
    for (int o = 128; o >= 1; o >>= 1) {
        if (t < o) sh[t] += sh[t + o];
        __syncthreads();
    }
    float inv = 1.f / sh[0];
    float4 o4; o4.x = e0 * inv; o4.y = e1 * inv; o4.z = e2 * inv; o4.w = e3 * inv;
    reinterpret_cast<float4*>(p)[t] = o4;
}

// ---------------------------------------------------------------------------
// Launch
// ---------------------------------------------------------------------------
extern "C" void kernel_launch(void* const* d_in, const int* in_sizes, int n_in,
                              void* d_out, int out_size) {
    const float* x      = (const float*)d_in[0];
    const float* gn_w   = (const float*)d_in[1];
    const float* gn_b   = (const float*)d_in[2];
    const float* qkv_w  = (const float*)d_in[3];
    const float* qkv_b  = (const float*)d_in[4];
    const float* proj_w = (const float*)d_in[5];
    const float* proj_b = (const float*)d_in[6];
    float* out = (float*)d_out;

    void *p_xn, *p_qkvT, *p_ctxT, *p_out1;
    cudaGetSymbolAddress(&p_xn,   g_xn);
    cudaGetSymbolAddress(&p_qkvT, g_qkvT);
    cudaGetSymbolAddress(&p_ctxT, g_ctxT);
    cudaGetSymbolAddress(&p_out1, g_out1);
    float* xn   = (float*)p_xn;
    float* qkvT = (float*)p_qkvT;
    float* ctxT = (float*)p_ctxT;
    float* out1 = (float*)p_out1;

    cudaFuncSetAttribute(gemm_mma<false, true,  1>, cudaFuncAttributeMaxDynamicSharedMemorySize, SMEM_SZ);
    cudaFuncSetAttribute(gemm_mma<false, false, 0>, cudaFuncAttributeMaxDynamicSharedMemorySize, SMEM_SZ);
    cudaFuncSetAttribute(gemm_mma<true,  false, 0>, cudaFuncAttributeMaxDynamicSharedMemorySize, SMEM_SZ);
    cudaFuncSetAttribute(gemm_mma<false, false, 2>, cudaFuncAttributeMaxDynamicSharedMemorySize, SMEM_SZ);

    // 1) GroupNorm -> g_xn [B, C, N]
    gn_kernel<<<BATCH * GRP, 512>>>(x, gn_w, gn_b);

    // 2) qkvT[b,d,n] = sum_c W[d,c]*xn[b,c,n] + qkv_b[d]   (M=1536, N=1024, K=512)
    gemm_mma<false, true, 1><<<dim3(NTOK / 128, C3 / 128, BATCH), 256, SMEM_SZ>>>(
        qkv_w, xn, qkvT, CH, CH, NTOK, NTOK,
        0LL, (long long)CH * NTOK, (long long)C3 * NTOK,
        qkv_b, nullptr, 0LL);

    // 3) softmaxes in place on qkvT
    ksoftmax_kernel<<<BATCH * 32, 256>>>();
    qsoftmax_kernel<<<BATCH * CH, 256>>>();

    // 4) ctxT[b,d,c] = sum_n v_T[d,n]*k_T[c,n]   (M=512, N=512, K=1024)
    gemm_mma<false, false, 0><<<dim3(CH / 128, CH / 128, BATCH), 256, SMEM_SZ>>>(
        qkvT + (size_t)2 * CH * NTOK, qkvT + (size_t)CH * NTOK, ctxT,
        NTOK, NTOK, NTOK, CH,
        (long long)C3 * NTOK, (long long)C3 * NTOK, (long long)CH * CH,
        nullptr, nullptr, 0LL);

    // 5) out1[b,n,d] = sum_c q_T[c,n]*ctxT[d,c]   (M=1024, N=512, K=512)
    gemm_mma<true, false, 0><<<dim3(CH / 128, NTOK / 128, BATCH), 256, SMEM_SZ>>>(
        qkvT, ctxT, out1, CH, NTOK, CH, CH,
        (long long)C3 * NTOK, (long long)CH * CH, (long long)NTOK * CH,
        nullptr, nullptr, 0LL);

    // 6) out[b,d,n] = sum_c proj_w[d,c]*out1[b,n,c] + proj_b[d] + xn[b,d,n]
    gemm_mma<false, false, 2><<<dim3(NTOK / 128, CH / 128, BATCH), 256, SMEM_SZ>>>(
        proj_w, out1, out, CH, CH, CH, NTOK,
        0LL, (long long)NTOK * CH, (long long)CH * NTOK,
        proj_b, xn, (long long)CH * NTOK);
}

// round 4
// speedup vs baseline: 1.6947x; 1.2084x over previous
#include <cuda_runtime.h>
#include <cuda_bf16.h>
#include <cstdint>

#define BATCH 8
#define CH    512
#define NTOK  1024
#define C3    1536
#define GRP   8
#define CPG   64
#define GSIZE 65536

#define BK    32
#define SAK   40                       // padded smem row stride (bf16): 80B, mult of 16
#define PL    (128 * SAK)              // plane elems
#define GSM_BYTES (8 * PL * 2)         // 2 bufs x 4 planes = 81920 B

// ---------------- scratch (device globals) ----------------
__device__ float g_xn  [BATCH * CH * NTOK];            // fp32 residual [B,C,N]
__device__ float g_qkvT[BATCH * C3 * NTOK];            // fp32 GEMM1 out [B,3C,N]
__device__ __nv_bfloat16 g_xnTh[BATCH * NTOK * CH];    // xn^T hi [B,N,C]
__device__ __nv_bfloat16 g_xnTl[BATCH * NTOK * CH];
__device__ __nv_bfloat16 g_w1h[C3 * CH], g_w1l[C3 * CH];
__device__ __nv_bfloat16 g_w2h[CH * CH], g_w2l[CH * CH];
__device__ __nv_bfloat16 g_kh[BATCH * CH * NTOK], g_kl[BATCH * CH * NTOK];   // [B,C,N]
__device__ __nv_bfloat16 g_vh[BATCH * CH * NTOK], g_vl[BATCH * CH * NTOK];   // [B,C,N]
__device__ __nv_bfloat16 g_qTh[BATCH * NTOK * CH], g_qTl[BATCH * NTOK * CH]; // [B,N,C]
__device__ __nv_bfloat16 g_ch[BATCH * CH * CH],  g_cl[BATCH * CH * CH];      // ctx [B,d,c]
__device__ __nv_bfloat16 g_o1h[BATCH * NTOK * CH], g_o1l[BATCH * NTOK * CH]; // out1 [B,n,d]

// ---------------- helpers ----------------
__device__ __forceinline__ uint32_t smem_u32(const void* p) {
    uint32_t a;
    asm("{ .reg .u64 t; cvta.to.shared.u64 t, %1; cvt.u32.u64 %0, t; }" : "=r"(a) : "l"(p));
    return a;
}
__device__ __forceinline__ void split_bf16(float x, __nv_bfloat16& h, __nv_bfloat16& l) {
    h = __float2bfloat16_rn(x);
    l = __float2bfloat16_rn(x - __bfloat162float(h));
}
__device__ __forceinline__ void mma16816(float* c, uint32_t a0, uint32_t a1,
                                         uint32_t a2, uint32_t a3,
                                         uint32_t b0, uint32_t b1) {
    asm volatile(
        "mma.sync.aligned.m16n8k16.row.col.f32.bf16.bf16.f32 "
        "{%0,%1,%2,%3},{%4,%5,%6,%7},{%8,%9},{%0,%1,%2,%3};"
        : "+f"(c[0]), "+f"(c[1]), "+f"(c[2]), "+f"(c[3])
        : "r"(a0), "r"(a1), "r"(a2), "r"(a3), "r"(b0), "r"(b1));
}
__device__ __forceinline__ void ldm4(uint32_t& r0, uint32_t& r1, uint32_t& r2,
                                     uint32_t& r3, uint32_t a) {
    asm volatile("ldmatrix.sync.aligned.m8n8.x4.shared.b16 {%0,%1,%2,%3}, [%4];"
                 : "=r"(r0), "=r"(r1), "=r"(r2), "=r"(r3) : "r"(a));
}
#define CPA16(d, s) asm volatile("cp.async.cg.shared.global [%0], [%1], 16;" :: "r"(d), "l"(s))

// ---------------------------------------------------------------------------
// bf16x3 tensor-core GEMM, all operands K-contiguous hi/lo planes.
// D[128m x 128n] = sum_k A(m,k)*B(n,k)
// EP 0: write bf16 hi/lo planes (Ch, Cl).  EP 1: fp32 C + bias[m].
// EP 2: fp32 C + bias[m] + resid[m*ldc+n].
// Grid (N/128, M/128, batch). 256 thr (8 warps 2x4, 64x32 warp tiles).
// ---------------------------------------------------------------------------
template <int EP>
__global__ __launch_bounds__(256, 2) void gemm_bf3(
    const __nv_bfloat16* __restrict__ Ah, const __nv_bfloat16* __restrict__ Al,
    const __nv_bfloat16* __restrict__ Bh, const __nv_bfloat16* __restrict__ Bl,
    float* __restrict__ C, __nv_bfloat16* __restrict__ Ch, __nv_bfloat16* __restrict__ Cl,
    int K, int lda, int ldb, int ldc,
    long long sA, long long sB, long long sC,
    const float* __restrict__ bias, const float* __restrict__ resid)
{
    extern __shared__ __nv_bfloat16 smbuf[];
    const uint32_t su = smem_u32(smbuf);
    const int tid = threadIdx.x;
    const int bz = blockIdx.z;
    Ah += (size_t)bz * sA; Al += (size_t)bz * sA;
    Bh += (size_t)bz * sB; Bl += (size_t)bz * sB;
    const int m0 = blockIdx.y * 128, n0 = blockIdx.x * 128;

    const int lane = tid & 31, wid = tid >> 5;
    const int g = lane >> 2, tg = lane & 3;
    const int wm = (wid & 1) * 64, wn = (wid >> 1) * 32;
    const int lr = lane & 15, lc = (lane >> 4) * 8;

    float acc[4][4][4];
#pragma unroll
    for (int i = 0; i < 4; i++)
#pragma unroll
        for (int j = 0; j < 4; j++)
#pragma unroll
            for (int q = 0; q < 4; q++) acc[i][j][q] = 0.f;

    const int fr = tid >> 1;          // fill row
    const int fc = tid & 1;           // fill chunk parity
    const int NC = K / BK;

    // prologue fill buf 0
    {
        const __nv_bfloat16* s0 = Ah + (size_t)(m0 + fr) * lda;
        const __nv_bfloat16* s1 = Al + (size_t)(m0 + fr) * lda;
        const __nv_bfloat16* s2 = Bh + (size_t)(n0 + fr) * ldb;
        const __nv_bfloat16* s3 = Bl + (size_t)(n0 + fr) * ldb;
        uint32_t db = su + (uint32_t)(fr * SAK) * 2u;
#pragma unroll
        for (int i = 0; i < 2; i++) {
            int c = fc + 2 * i;
            uint32_t d = db + (uint32_t)(c * 8) * 2u;
            CPA16(d,               s0 + c * 8);
            CPA16(d + PL * 2,      s1 + c * 8);
            CPA16(d + 2 * PL * 2,  s2 + c * 8);
            CPA16(d + 3 * PL * 2,  s3 + c * 8);
        }
        asm volatile("cp.async.commit_group;");
    }

    for (int c = 0; c < NC; c++) {
        if (c + 1 < NC) {
            int k0 = (c + 1) * BK;
            const __nv_bfloat16* s0 = Ah + (size_t)(m0 + fr) * lda + k0;
            const __nv_bfloat16* s1 = Al + (size_t)(m0 + fr) * lda + k0;
            const __nv_bfloat16* s2 = Bh + (size_t)(n0 + fr) * ldb + k0;
            const __nv_bfloat16* s3 = Bl + (size_t)(n0 + fr) * ldb + k0;
            uint32_t db = su + (uint32_t)(((c + 1) & 1) * 4) * (PL * 2u)
                             + (uint32_t)(fr * SAK) * 2u;
#pragma unroll
            for (int i = 0; i < 2; i++) {
                int cc = fc + 2 * i;
                uint32_t d = db + (uint32_t)(cc * 8) * 2u;
                CPA16(d,               s0 + cc * 8);
                CPA16(d + PL * 2,      s1 + cc * 8);
                CPA16(d + 2 * PL * 2,  s2 + cc * 8);
                CPA16(d + 3 * PL * 2,  s3 + cc * 8);
            }
            asm volatile("cp.async.commit_group;");
            asm volatile("cp.async.wait_group 1;" ::: "memory");
        } else {
            asm volatile("cp.async.commit_group;");
            asm volatile("cp.async.wait_group 0;" ::: "memory");
        }
        __syncthreads();

        const uint32_t ab = su + (uint32_t)((c & 1) * 4) * (PL * 2u);
        const uint32_t Ahs = ab, Als = ab + PL * 2;
        const uint32_t Bhs = ab + 2 * PL * 2, Bls = ab + 3 * PL * 2;

#pragma unroll
        for (int ks = 0; ks < BK; ks += 16) {
            uint32_t Bf[2][8];
#pragma unroll
            for (int pr = 0; pr < 2; pr++) {
                uint32_t off = (uint32_t)((wn + pr * 16 + lr) * SAK + ks + lc) * 2u;
                ldm4(Bf[0][pr * 4 + 0], Bf[0][pr * 4 + 1], Bf[0][pr * 4 + 2], Bf[0][pr * 4 + 3], Bhs + off);
                ldm4(Bf[1][pr * 4 + 0], Bf[1][pr * 4 + 1], Bf[1][pr * 4 + 2], Bf[1][pr * 4 + 3], Bls + off);
            }
#pragma unroll
            for (int mt = 0; mt < 4; mt++) {
                uint32_t off = (uint32_t)((wm + mt * 16 + lr) * SAK + ks + lc) * 2u;
                uint32_t ah0, ah1, ah2, ah3, al0, al1, al2, al3;
                ldm4(ah0, ah1, ah2, ah3, Ahs + off);
                ldm4(al0, al1, al2, al3, Als + off);
#pragma unroll
                for (int nt = 0; nt < 4; nt++) {
                    int i0 = (nt >> 1) * 4 + (nt & 1);
                    uint32_t bh0 = Bf[0][i0], bh1 = Bf[0][i0 + 2];
                    uint32_t bl0 = Bf[1][i0], bl1 = Bf[1][i0 + 2];
                    mma16816(acc[mt][nt], ah0, ah1, ah2, ah3, bh0, bh1);
                    mma16816(acc[mt][nt], ah0, ah1, ah2, ah3, bl0, bl1);
                    mma16816(acc[mt][nt], al0, al1, al2, al3, bh0, bh1);
                }
            }
        }
        __syncthreads();
    }

    // ---- epilogue ----
    if (EP == 0) {
        __nv_bfloat16* Chp = Ch + (size_t)bz * sC;
        __nv_bfloat16* Clp = Cl + (size_t)bz * sC;
#pragma unroll
        for (int mt = 0; mt < 4; mt++) {
            int m = m0 + wm + mt * 16 + g;
#pragma unroll
            for (int nt = 0; nt < 4; nt++) {
                int n = n0 + wn + nt * 8 + tg * 2;
                float* a = acc[mt][nt];
                __nv_bfloat16 h0, h1, h2, h3, l0, l1, l2, l3;
                split_bf16(a[0], h0, l0); split_bf16(a[1], h1, l1);
                split_bf16(a[2], h2, l2); split_bf16(a[3], h3, l3);
                size_t i0 = (size_t)m * ldc + n;
                size_t i1 = (size_t)(m + 8) * ldc + n;
                *reinterpret_cast<__nv_bfloat162*>(Chp + i0) = __nv_bfloat162(h0, h1);
                *reinterpret_cast<__nv_bfloat162*>(Chp + i1) = __nv_bfloat162(h2, h3);
                *reinterpret_cast<__nv_bfloat162*>(Clp + i0) = __nv_bfloat162(l0, l1);
                *reinterpret_cast<__nv_bfloat162*>(Clp + i1) = __nv_bfloat162(l2, l3);
            }
        }
    } else {
        float* Cp = C + (size_t)bz * sC;
        const float* R = (EP == 2) ? (resid + (size_t)bz * sC) : nullptr;
#pragma unroll
        for (int mt = 0; mt < 4; mt++) {
            int m = m0 + wm + mt * 16 + g;
            float bv0 = bias[m], bv1 = bias[m + 8];
#pragma unroll
            for (int nt = 0; nt < 4; nt++) {
                int n = n0 + wn + nt * 8 + tg * 2;
                float* a = acc[mt][nt];
                size_t i0 = (size_t)m * ldc + n;
                size_t i1 = (size_t)(m + 8) * ldc + n;
                float2 o0, o1;
                o0.x = a[0] + bv0; o0.y = a[1] + bv0;
                o1.x = a[2] + bv1; o1.y = a[3] + bv1;
                if (EP == 2) {
                    float2 r0 = *reinterpret_cast<const float2*>(R + i0);
                    float2 r1 = *reinterpret_cast<const float2*>(R + i1);
                    o0.x += r0.x; o0.y += r0.y; o1.x += r1.x; o1.y += r1.y;
                }
                *reinterpret_cast<float2*>(Cp + i0) = o0;
                *reinterpret_cast<float2*>(Cp + i1) = o1;
            }
        }
    }
}

// ---------------------------------------------------------------------------
// GroupNorm: block per (b,g). Writes fp32 g_xn [B,C,N] and bf16 hi/lo
// transposed planes g_xnT [B,N,C] via smem tile transpose.
// ---------------------------------------------------------------------------
__global__ __launch_bounds__(512) void gn_kernel(const float* __restrict__ x,
                                                 const float* __restrict__ gamma,
                                                 const float* __restrict__ beta) {
    int b = blockIdx.x >> 3, g = blockIdx.x & 7;
    size_t off = ((size_t)b * CH + (size_t)g * CPG) * NTOK;
    const float4* xp = reinterpret_cast<const float4*>(x + off);
    float4* gp = reinterpret_cast<float4*>(g_xn + off);
    int t = threadIdx.x;

    __shared__ float rs[512], rq[512];
    float s = 0.f, sq = 0.f;
    for (int i = t; i < GSIZE / 4; i += 512) {
        float4 v = xp[i];
        s  += v.x + v.y + v.z + v.w;
        sq += v.x * v.x + v.y * v.y + v.z * v.z + v.w * v.w;
    }
    rs[t] = s; rq[t] = sq;
    __syncthreads();
    for (int o = 256; o >= 1; o >>= 1) {
        if (t < o) { rs[t] += rs[t + o]; rq[t] += rq[t + o]; }
        __syncthreads();
    }
    float mean = rs[0] * (1.f / GSIZE);
    float var  = rq[0] * (1.f / GSIZE) - mean * mean;
    float rstd = rsqrtf(var + 1e-5f);

    __shared__ __nv_bfloat16 sh[64][72], sl[64][72];   // [n_local][c]
    int c = t >> 3, j0 = (t & 7) * 8;
    float gm = gamma[g * CPG + c] * rstd;
    float bt = beta[g * CPG + c] - mean * gm;
    int nl = t >> 3, chn = t & 7;

    for (int tn = 0; tn < 16; tn++) {
        int base = c * 256 + tn * 16 + (t & 7) * 2;
        float4 v0 = xp[base], v1 = xp[base + 1];
        float y[8] = { v0.x * gm + bt, v0.y * gm + bt, v0.z * gm + bt, v0.w * gm + bt,
                       v1.x * gm + bt, v1.y * gm + bt, v1.z * gm + bt, v1.w * gm + bt };
        float4 w0, w1;
        w0.x = y[0]; w0.y = y[1]; w0.z = y[2]; w0.w = y[3];
        w1.x = y[4]; w1.y = y[5]; w1.z = y[6]; w1.w = y[7];
        gp[base] = w0; gp[base + 1] = w1;
#pragma unroll
        for (int i = 0; i < 8; i++) {
            __nv_bfloat16 h, l;
            split_bf16(y[i], h, l);
            sh[j0 + i][c] = h; sl[j0 + i][c] = l;
        }
        __syncthreads();
        size_t dst = ((size_t)b * NTOK + tn * 64 + nl) * CH + g * CPG + chn * 8;
        *reinterpret_cast<uint4*>(&g_xnTh[dst]) = *reinterpret_cast<uint4*>(&sh[nl][chn * 8]);
        *reinterpret_cast<uint4*>(&g_xnTl[dst]) = *reinterpret_cast<uint4*>(&sl[nl][chn * 8]);
        __syncthreads();
    }
}

// ---------------------------------------------------------------------------
// Weight convert fp32 -> hi/lo bf16 planes.
// ---------------------------------------------------------------------------
__global__ void conv_kernel(const float* __restrict__ src, __nv_bfloat16* __restrict__ h,
                            __nv_bfloat16* __restrict__ l, int n8) {
    int i = blockIdx.x * 256 + threadIdx.x;
    if (i >= n8) return;
    const float4* s = reinterpret_cast<const float4*>(src) + i * 2;
    float4 v0 = s[0], v1 = s[1];
    __nv_bfloat16 hh[8], ll[8];
    split_bf16(v0.x, hh[0], ll[0]); split_bf16(v0.y, hh[1], ll[1]);
    split_bf16(v0.z, hh[2], ll[2]); split_bf16(v0.w, hh[3], ll[3]);
    split_bf16(v1.x, hh[4], ll[4]); split_bf16(v1.y, hh[5], ll[5]);
    split_bf16(v1.z, hh[6], ll[6]); split_bf16(v1.w, hh[7], ll[7]);
    *reinterpret_cast<uint4*>(h + (size_t)i * 8) = *reinterpret_cast<uint4*>(hh);
    *reinterpret_cast<uint4*>(l + (size_t)i * 8) = *reinterpret_cast<uint4*>(ll);
}

// v block convert: qkvT rows 2C..3C -> g_v planes
__global__ void vconv_kernel() {
    size_t gi = (size_t)blockIdx.x * 256 + threadIdx.x;   // over B*CH*NTOK/8
    size_t per = (size_t)CH * NTOK / 8;
    int b = (int)(gi / per);
    size_t r = (gi % per) * 8;
    const float4* s = reinterpret_cast<const float4*>(
        g_qkvT + (size_t)b * C3 * NTOK + (size_t)2 * CH * NTOK + r);
    float4 v0 = s[0], v1 = s[1];
    __nv_bfloat16 hh[8], ll[8];
    split_bf16(v0.x, hh[0], ll[0]); split_bf16(v0.y, hh[1], ll[1]);
    split_bf16(v0.z, hh[2], ll[2]); split_bf16(v0.w, hh[3], ll[3]);
    split_bf16(v1.x, hh[4], ll[4]); split_bf16(v1.y, hh[5], ll[5]);
    split_bf16(v1.z, hh[6], ll[6]); split_bf16(v1.w, hh[7], ll[7]);
    size_t d = (size_t)b * CH * NTOK + r;
    *reinterpret_cast<uint4*>(g_vh + d) = *reinterpret_cast<uint4*>(hh);
    *reinterpret_cast<uint4*>(g_vl + d) = *reinterpret_cast<uint4*>(ll);
}

// ---------------------------------------------------------------------------
// k softmax over c per (b,n); reads fp32 qkvT k block, writes bf16 planes [C,N].
// ---------------------------------------------------------------------------
__global__ __launch_bounds__(256) void ksoftmax_kernel() {
    int b = blockIdx.x >> 5;
    int n0 = (blockIdx.x & 31) * 32;
    const float* base = g_qkvT + (size_t)b * C3 * NTOK + (size_t)CH * NTOK + n0;
    __nv_bfloat16* kh = g_kh + (size_t)b * CH * NTOK + n0;
    __nv_bfloat16* kl = g_kl + (size_t)b * CH * NTOK + n0;
    int lane = threadIdx.x & 31, j = threadIdx.x >> 5;

    float mx = -1e30f, sum = 0.f;
    for (int i = 0; i < 64; i++) {
        float v = base[(size_t)(j * 64 + i) * NTOK + lane];
        float nm = fmaxf(mx, v);
        sum = sum * __expf(mx - nm) + __expf(v - nm);
        mx = nm;
    }
    __shared__ float sM[8][32], sS[8][32];
    sM[j][lane] = mx; sS[j][lane] = sum;
    __syncthreads();
    if (j == 0) {
        float M = sM[0][lane], S = sS[0][lane];
#pragma unroll
        for (int t = 1; t < 8; t++) {
            float m2 = sM[t][lane], s2 = sS[t][lane];
            float nm = fmaxf(M, m2);
            S = S * __expf(M - nm) + s2 * __expf(m2 - nm);
            M = nm;
        }
        sM[0][lane] = M; sS[0][lane] = 1.f / S;
    }
    __syncthreads();
    float M = sM[0][lane], inv = sS[0][lane];
    for (int i = 0; i < 64; i++) {
        size_t idx = (size_t)(j * 64 + i) * NTOK + lane;
        float e = __expf(base[idx] - M) * inv;
        __nv_bfloat16 h, l;
        split_bf16(e, h, l);
        kh[idx] = h; kl[idx] = l;
    }
}

// ---------------------------------------------------------------------------
// q softmax over n per (b,c); writes TRANSPOSED bf16 planes qT [B,N,C].
// Block: (b, 32 c rows). 256 thr.
// ---------------------------------------------------------------------------
__global__ __launch_bounds__(256) void qsoftmax_kernel() {
    int b = blockIdx.x >> 4, c0 = (blockIdx.x & 15) * 32;
    const float* base = g_qkvT + (size_t)b * C3 * NTOK;
    int t = threadIdx.x;
    int cr = t >> 3, sub = t & 7;
    const float4* rp = reinterpret_cast<const float4*>(
        base + (size_t)(c0 + cr) * NTOK + sub * 128);

    float mx = -1e30f, sum = 0.f;
#pragma unroll
    for (int i = 0; i < 32; i++) {
        float4 v = rp[i];
        float m4 = fmaxf(fmaxf(v.x, v.y), fmaxf(v.z, v.w));
        float nm = fmaxf(mx, m4);
        sum = sum * __expf(mx - nm) + __expf(v.x - nm) + __expf(v.y - nm)
            + __expf(v.z - nm) + __expf(v.w - nm);
        mx = nm;
    }
#pragma unroll
    for (int o = 4; o >= 1; o >>= 1) {
        float m2 = __shfl_xor_sync(0xFFFFFFFFu, mx, o);
        float s2 = __shfl_xor_sync(0xFFFFFFFFu, sum, o);
        float nm = fmaxf(mx, m2);
        sum = sum * __expf(mx - nm) + s2 * __expf(m2 - nm);
        mx = nm;
    }
    __shared__ float sM[32], sI[32];
    if (sub == 0) { sM[cr] = mx; sI[cr] = 1.f / sum; }
    __syncthreads();
    float M = sM[cr], inv = sI[cr];

    __shared__ __nv_bfloat16 th[64][40], tl[64][40];   // [n_local][c]
    int nl = t >> 2, chn = t & 3;
    for (int tn = 0; tn < 16; tn++) {
        const float4* sp = reinterpret_cast<const float4*>(
            base + (size_t)(c0 + cr) * NTOK + tn * 64 + sub * 8);
        float4 v0 = sp[0], v1 = sp[1];
        float e[8] = { __expf(v0.x - M) * inv, __expf(v0.y - M) * inv,
                       __expf(v0.z - M) * inv, __expf(v0.w - M) * inv,
                       __expf(v1.x - M) * inv, __expf(v1.y - M) * inv,
                       __expf(v1.z - M) * inv, __expf(v1.w - M) * inv };
#pragma unroll
        for (int i = 0; i < 8; i++) {
            __nv_bfloat16 h, l;
            split_bf16(e[i], h, l);
            th[sub * 8 + i][cr] = h; tl[sub * 8 + i][cr] = l;
        }
        __syncthreads();
        size_t dst = ((size_t)b * NTOK + tn * 64 + nl) * CH + c0 + chn * 8;
        *reinterpret_cast<uint4*>(&g_qTh[dst]) = *reinterpret_cast<uint4*>(&th[nl][chn * 8]);
        *reinterpret_cast<uint4*>(&g_qTl[dst]) = *reinterpret_cast<uint4*>(&tl[nl][chn * 8]);
        __syncthreads();
    }
}

// ---------------------------------------------------------------------------
// Launch
// ---------------------------------------------------------------------------
extern "C" void kernel_launch(void* const* d_in, const int* in_sizes, int n_in,
                              void* d_out, int out_size) {
    const float* x      = (const float*)d_in[0];
    const float* gn_w   = (const float*)d_in[1];
    const float* gn_b   = (const float*)d_in[2];
    const float* qkv_w  = (const float*)d_in[3];
    const float* qkv_b  = (const float*)d_in[4];
    const float* proj_w = (const float*)d_in[5];
    const float* proj_b = (const float*)d_in[6];
    float* out = (float*)d_out;

    // resolve symbols
    void* p;
    cudaGetSymbolAddress(&p, g_xn);   float* xn   = (float*)p;
    cudaGetSymbolAddress(&p, g_qkvT); float* qkvT = (float*)p;
    cudaGetSymbolAddress(&p, g_xnTh); __nv_bfloat16* xnTh = (__nv_bfloat16*)p;
    cudaGetSymbolAddress(&p, g_xnTl); __nv_bfloat16* xnTl = (__nv_bfloat16*)p;
    cudaGetSymbolAddress(&p, g_w1h);  __nv_bfloat16* w1h = (__nv_bfloat16*)p;
    cudaGetSymbolAddress(&p, g_w1l);  __nv_bfloat16* w1l = (__nv_bfloat16*)p;
    cudaGetSymbolAddress(&p, g_w2h);  __nv_bfloat16* w2h = (__nv_bfloat16*)p;
    cudaGetSymbolAddress(&p, g_w2l);  __nv_bfloat16* w2l = (__nv_bfloat16*)p;
    cudaGetSymbolAddress(&p, g_kh);   __nv_bfloat16* kh = (__nv_bfloat16*)p;
    cudaGetSymbolAddress(&p, g_kl);   __nv_bfloat16* kl = (__nv_bfloat16*)p;
    cudaGetSymbolAddress(&p, g_vh);   __nv_bfloat16* vh = (__nv_bfloat16*)p;
    cudaGetSymbolAddress(&p, g_vl);   __nv_bfloat16* vl = (__nv_bfloat16*)p;
    cudaGetSymbolAddress(&p, g_qTh);  __nv_bfloat16* qTh = (__nv_bfloat16*)p;
    cudaGetSymbolAddress(&p, g_qTl);  __nv_bfloat16* qTl = (__nv_bfloat16*)p;
    cudaGetSymbolAddress(&p, g_ch);   __nv_bfloat16* ch = (__nv_bfloat16*)p;
    cudaGetSymbolAddress(&p, g_cl);   __nv_bfloat16* cl = (__nv_bfloat16*)p;
    cudaGetSymbolAddress(&p, g_o1h);  __nv_bfloat16* o1h = (__nv_bfloat16*)p;
    cudaGetSymbolAddress(&p, g_o1l);  __nv_bfloat16* o1l = (__nv_bfloat16*)p;

    cudaFuncSetAttribute(gemm_bf3<0>, cudaFuncAttributeMaxDynamicSharedMemorySize, GSM_BYTES);
    cudaFuncSetAttribute(gemm_bf3<1>, cudaFuncAttributeMaxDynamicSharedMemorySize, GSM_BYTES);
    cudaFuncSetAttribute(gemm_bf3<2>, cudaFuncAttributeMaxDynamicSharedMemorySize, GSM_BYTES);

    // 0) weight conversion (cheap, every launch)
    conv_kernel<<<(C3 * CH / 8 + 255) / 256, 256>>>(qkv_w, w1h, w1l, C3 * CH / 8);
    conv_kernel<<<(CH * CH / 8 + 255) / 256, 256>>>(proj_w, w2h, w2l, CH * CH / 8);

    // 1) GroupNorm -> fp32 residual + transposed bf16 planes
    gn_kernel<<<BATCH * GRP, 512>>>(x, gn_w, gn_b);

    // 2) GEMM1: qkvT[d,n] = sum_c w1[d,c]*xnT[n,c] + b[d]   M=1536 N=1024 K=512
    gemm_bf3<1><<<dim3(NTOK / 128, C3 / 128, BATCH), 256, GSM_BYTES>>>(
        w1h, w1l, xnTh, xnTl, qkvT, nullptr, nullptr,
        CH, CH, CH, NTOK, 0LL, (long long)NTOK * CH, (long long)C3 * NTOK,
        qkv_b, nullptr);

    // 3) softmaxes + v convert -> bf16 planes
    ksoftmax_kernel<<<BATCH * 32, 256>>>();
    vconv_kernel<<<BATCH * CH * NTOK / 8 / 256, 256>>>();
    qsoftmax_kernel<<<BATCH * 16, 256>>>();

    // 4) GEMM2: ctx[d,c] = sum_n v[d,n]*k[c,n]   M=512 N=512 K=1024
    gemm_bf3<0><<<dim3(CH / 128, CH / 128, BATCH), 256, GSM_BYTES>>>(
        vh, vl, kh, kl, nullptr, ch, cl,
        NTOK, NTOK, NTOK, CH,
        (long long)CH * NTOK, (long long)CH * NTOK, (long long)CH * CH,
        nullptr, nullptr);

    // 5) GEMM3: out1[n,d] = sum_c qT[n,c]*ctx[d,c]   M=1024 N=512 K=512
    gemm_bf3<0><<<dim3(CH / 128, NTOK / 128, BATCH), 256, GSM_BYTES>>>(
        qTh, qTl, ch, cl, nullptr, o1h, o1l,
        CH, CH, CH, CH,
        (long long)NTOK * CH, (long long)CH * CH, (long long)NTOK * CH,
        nullptr, nullptr);

    // 6) GEMM4: out[d,n] = sum_c w2[d,c]*out1[n,c] + b[d] + xn[d,n]  M=512 N=1024 K=512
    gemm_bf3<2><<<dim3(NTOK / 128, CH / 128, BATCH), 256, GSM_BYTES>>>(
        w2h, w2l, o1h, o1l, out, nullptr, nullptr,
        CH, CH, CH, NTOK, 0LL, (long long)NTOK * CH, (long long)CH * NTOK,
        proj_b, xn);
}

// round 5
// speedup vs baseline: 2.0882x; 1.2322x over previous
#include <cuda_runtime.h>
#include <cuda_bf16.h>
#include <cstdint>

#define BATCH 8
#define CH    512
#define NTOK  1024
#define C3    1536
#define GRP   8
#define CPG   64
#define GSIZE 65536

// ---------------- scratch (device globals) ----------------
__device__ float g_xn  [BATCH * CH * NTOK];            // fp32 residual [B,C,N]
__device__ float g_qkvT[BATCH * C3 * NTOK];            // fp32 GEMM1 out (q,k rows used)
__device__ __nv_bfloat16 g_xnTh[BATCH * NTOK * CH];    // xn^T hi [B,N,C]
__device__ __nv_bfloat16 g_xnTl[BATCH * NTOK * CH];
__device__ __nv_bfloat16 g_w1h[C3 * CH], g_w1l[C3 * CH];
__device__ __nv_bfloat16 g_w2h[CH * CH], g_w2l[CH * CH];
__device__ __nv_bfloat16 g_kh[BATCH * CH * NTOK], g_kl[BATCH * CH * NTOK];   // [B,C,N]
__device__ __nv_bfloat16 g_vh[BATCH * CH * NTOK], g_vl[BATCH * CH * NTOK];   // [B,C,N]
__device__ __nv_bfloat16 g_qTh[BATCH * NTOK * CH], g_qTl[BATCH * NTOK * CH]; // [B,N,C]
__device__ __nv_bfloat16 g_ch[BATCH * CH * CH],  g_cl[BATCH * CH * CH];      // ctx [B,d,c]
__device__ __nv_bfloat16 g_o1h[BATCH * NTOK * CH], g_o1l[BATCH * NTOK * CH]; // out1 [B,n,d]

// ---------------- helpers ----------------
__device__ __forceinline__ uint32_t smem_u32(const void* p) {
    uint32_t a;
    asm("{ .reg .u64 t; cvta.to.shared.u64 t, %1; cvt.u32.u64 %0, t; }" : "=r"(a) : "l"(p));
    return a;
}
__device__ __forceinline__ void split_bf16(float x, __nv_bfloat16& h, __nv_bfloat16& l) {
    h = __float2bfloat16_rn(x);
    l = __float2bfloat16_rn(x - __bfloat162float(h));
}
__device__ __forceinline__ void mma16816(float* c, uint32_t a0, uint32_t a1,
                                         uint32_t a2, uint32_t a3,
                                         uint32_t b0, uint32_t b1) {
    asm volatile(
        "mma.sync.aligned.m16n8k16.row.col.f32.bf16.bf16.f32 "
        "{%0,%1,%2,%3},{%4,%5,%6,%7},{%8,%9},{%0,%1,%2,%3};"
        : "+f"(c[0]), "+f"(c[1]), "+f"(c[2]), "+f"(c[3])
        : "r"(a0), "r"(a1), "r"(a2), "r"(a3), "r"(b0), "r"(b1));
}
__device__ __forceinline__ void ldm4(uint32_t& r0, uint32_t& r1, uint32_t& r2,
                                     uint32_t& r3, uint32_t a) {
    asm volatile("ldmatrix.sync.aligned.m8n8.x4.shared.b16 {%0,%1,%2,%3}, [%4];"
                 : "=r"(r0), "=r"(r1), "=r"(r2), "=r"(r3) : "r"(a));
}
#define CPA16(d, s) asm volatile("cp.async.cg.shared.global [%0], [%1], 16;" :: "r"(d), "l"(s))
#define CPCOMMIT()  asm volatile("cp.async.commit_group;")
#define CPWAIT1()   asm volatile("cp.async.wait_group 1;" ::: "memory")
#define CPWAIT0()   asm volatile("cp.async.wait_group 0;" ::: "memory")

// swizzled byte offset within a plane: row r (64B rows), 16B chunk c
__device__ __forceinline__ uint32_t swz(int r, int c) {
    return (uint32_t)(r * 64 + ((c ^ ((r >> 1) & 3)) << 4));
}

// ---------------------------------------------------------------------------
// bf16x3 tensor-core GEMM, 3-stage cp.async pipeline, swizzled smem.
// D[BM x BN] = sum_k A(m,k)*B(n,k); BM=128, BN=32*NWT (NWT=4 -> 128, 2 -> 64).
// EP 0: bf16 hi/lo planes out.     EP 2: fp32 + bias[m] + resid.
// EP 3: m0<1024 -> fp32 + bias; m0>=1024 -> bf16 planes at (m-1024) + bias.
// 256 threads, 8 warps (2 x 4), warp tile 64 x (8*NWT).
// ---------------------------------------------------------------------------
template <int NWT, int EP>
__global__ __launch_bounds__(256, 2) void gemm3s(
    const __nv_bfloat16* __restrict__ Ah, const __nv_bfloat16* __restrict__ Al,
    const __nv_bfloat16* __restrict__ Bh, const __nv_bfloat16* __restrict__ Bl,
    float* __restrict__ C, __nv_bfloat16* __restrict__ Ch, __nv_bfloat16* __restrict__ Cl,
    int K, int lda, int ldb, int ldc,
    long long sA, long long sB, long long sC, long long sCp,
    const float* __restrict__ bias, const float* __restrict__ resid)
{
    constexpr int BM = 128, BN = 32 * NWT;
    constexpr int AOB = 0;                 // Ah plane byte offset in stage
    constexpr int ALB = BM * 64;           // Al
    constexpr int BOB = 2 * BM * 64;       // Bh
    constexpr int BLB = 2 * BM * 64 + BN * 64;  // Bl
    constexpr int SSB = (2 * BM + 2 * BN) * 64; // stage bytes
    constexpr int ITA = (2 * BM * 4) / 256;     // A fill iters
    constexpr int ITB = (2 * BN * 4) / 256;     // B fill iters
    constexpr int LPB = BN * 4;                 // chunks per B plane

    extern __shared__ __nv_bfloat16 smbuf[];
    const uint32_t su = smem_u32(smbuf);
    const int tid = threadIdx.x;
    const int bz = blockIdx.z;
    Ah += (size_t)bz * sA; Al += (size_t)bz * sA;
    Bh += (size_t)bz * sB; Bl += (size_t)bz * sB;
    const int m0 = blockIdx.y * BM, n0 = blockIdx.x * BN;

    const int lane = tid & 31, wid = tid >> 5;
    const int g = lane >> 2, tg = lane & 3;
    const int wm = (wid & 1) * 64, wn = (wid >> 1) * (8 * NWT);
    const int lr = lane & 15, lchunk = lane >> 4;   // k sub-chunk (0/1)

    float acc[4][NWT][4];
#pragma unroll
    for (int i = 0; i < 4; i++)
#pragma unroll
        for (int j = 0; j < NWT; j++)
#pragma unroll
            for (int q = 0; q < 4; q++) acc[i][j][q] = 0.f;

    // ---- fill one stage ----
    auto fill = [&](int st, int k0) {
        uint32_t base = su + (uint32_t)(st * SSB);
#pragma unroll
        for (int i = 0; i < ITA; i++) {
            int idx = tid + 256 * i;
            int pl = idx >> 9, rem = idx & 511;
            int row = rem >> 2, ch = rem & 3;
            const __nv_bfloat16* s = (pl ? Al : Ah) + (size_t)(m0 + row) * lda + k0 + ch * 8;
            CPA16(base + (uint32_t)(pl ? ALB : AOB) + swz(row, ch), s);
        }
#pragma unroll
        for (int i = 0; i < ITB; i++) {
            int idx = tid + 256 * i;
            int pl = idx / LPB, rem = idx % LPB;
            int row = rem >> 2, ch = rem & 3;
            const __nv_bfloat16* s = (pl ? Bl : Bh) + (size_t)(n0 + row) * ldb + k0 + ch * 8;
            CPA16(base + (uint32_t)(pl ? BLB : BOB) + swz(row, ch), s);
        }
        CPCOMMIT();
    };

    const int NC = K / 32;
    fill(0, 0);
    fill(1, 32);

    int st = 0;
    for (int c = 0; c < NC; c++) {
        if (c + 1 < NC) { CPWAIT1(); } else { CPWAIT0(); }
        __syncthreads();
        if (c + 2 < NC) {
            int ns = st + 2; if (ns >= 3) ns -= 3;
            fill(ns, (c + 2) * 32);
        }
        const uint32_t sb = su + (uint32_t)(st * SSB);

#pragma unroll
        for (int ks = 0; ks < 32; ks += 16) {
            const int kc = (ks >> 3) + lchunk;
            uint32_t Bf[2][2 * NWT];
#pragma unroll
            for (int pr = 0; pr < NWT / 2; pr++) {
                int r = wn + pr * 16 + lr;
                uint32_t oh = sb + BOB + swz(r, kc);
                uint32_t ol = sb + BLB + swz(r, kc);
                ldm4(Bf[0][pr * 4 + 0], Bf[0][pr * 4 + 1], Bf[0][pr * 4 + 2], Bf[0][pr * 4 + 3], oh);
                ldm4(Bf[1][pr * 4 + 0], Bf[1][pr * 4 + 1], Bf[1][pr * 4 + 2], Bf[1][pr * 4 + 3], ol);
            }
#pragma unroll
            for (int mt = 0; mt < 4; mt++) {
                int r = wm + mt * 16 + lr;
                uint32_t ah0, ah1, ah2, ah3, al0, al1, al2, al3;
                ldm4(ah0, ah1, ah2, ah3, sb + AOB + swz(r, kc));
                ldm4(al0, al1, al2, al3, sb + ALB + swz(r, kc));
#pragma unroll
                for (int nt = 0; nt < NWT; nt++) {
                    int i0 = (nt >> 1) * 4 + (nt & 1);
                    uint32_t bh0 = Bf[0][i0], bh1 = Bf[0][i0 + 2];
                    uint32_t bl0 = Bf[1][i0], bl1 = Bf[1][i0 + 2];
                    mma16816(acc[mt][nt], ah0, ah1, ah2, ah3, bh0, bh1);
                    mma16816(acc[mt][nt], ah0, ah1, ah2, ah3, bl0, bl1);
                    mma16816(acc[mt][nt], al0, al1, al2, al3, bh0, bh1);
                }
            }
        }
        if (++st == 3) st = 0;
    }

    // ---- epilogue ----
    const bool planes = (EP == 0) || (EP == 3 && m0 >= 2 * CH);
    if (planes) {
        __nv_bfloat16* Chp = Ch + (size_t)bz * sCp;
        __nv_bfloat16* Clp = Cl + (size_t)bz * sCp;
        const int mb = (EP == 3) ? 2 * CH : 0;
#pragma unroll
        for (int mt = 0; mt < 4; mt++) {
            int m = m0 + wm + mt * 16 + g;
            float bv0 = (EP == 3) ? bias[m] : 0.f;
            float bv1 = (EP == 3) ? bias[m + 8] : 0.f;
#pragma unroll
            for (int nt = 0; nt < NWT; nt++) {
                int n = n0 + wn + nt * 8 + tg * 2;
                float* a = acc[mt][nt];
                __nv_bfloat16 h0, h1, h2, h3, l0, l1, l2, l3;
                split_bf16(a[0] + bv0, h0, l0); split_bf16(a[1] + bv0, h1, l1);
                split_bf16(a[2] + bv1, h2, l2); split_bf16(a[3] + bv1, h3, l3);
                size_t i0 = (size_t)(m - mb) * ldc + n;
                size_t i1 = (size_t)(m - mb + 8) * ldc + n;
                *reinterpret_cast<__nv_bfloat162*>(Chp + i0) = __nv_bfloat162(h0, h1);
                *reinterpret_cast<__nv_bfloat162*>(Chp + i1) = __nv_bfloat162(h2, h3);
                *reinterpret_cast<__nv_bfloat162*>(Clp + i0) = __nv_bfloat162(l0, l1);
                *reinterpret_cast<__nv_bfloat162*>(Clp + i1) = __nv_bfloat162(l2, l3);
            }
        }
    } else {
        float* Cp = C + (size_t)bz * sC;
        const float* R = (EP == 2) ? (resid + (size_t)bz * sC) : nullptr;
#pragma unroll
        for (int mt = 0; mt < 4; mt++) {
            int m = m0 + wm + mt * 16 + g;
            float bv0 = bias[m], bv1 = bias[m + 8];
#pragma unroll
            for (int nt = 0; nt < NWT; nt++) {
                int n = n0 + wn + nt * 8 + tg * 2;
                float* a = acc[mt][nt];
                size_t i0 = (size_t)m * ldc + n;
                size_t i1 = (size_t)(m + 8) * ldc + n;
                float2 o0, o1;
                o0.x = a[0] + bv0; o0.y = a[1] + bv0;
                o1.x = a[2] + bv1; o1.y = a[3] + bv1;
                if (EP == 2) {
                    float2 r0 = *reinterpret_cast<const float2*>(R + i0);
                    float2 r1 = *reinterpret_cast<const float2*>(R + i1);
                    o0.x += r0.x; o0.y += r0.y; o1.x += r1.x; o1.y += r1.y;
                }
                *reinterpret_cast<float2*>(Cp + i0) = o0;
                *reinterpret_cast<float2*>(Cp + i1) = o1;
            }
        }
    }
}

// ---------------------------------------------------------------------------
// GroupNorm: block per (b,g). fp32 residual + transposed bf16 planes.
// ---------------------------------------------------------------------------
__global__ __launch_bounds__(512) void gn_kernel(const float* __restrict__ x,
                                                 const float* __restrict__ gamma,
                                                 const float* __restrict__ beta) {
    int b = blockIdx.x >> 3, g = blockIdx.x & 7;
    size_t off = ((size_t)b * CH + (size_t)g * CPG) * NTOK;
    const float4* xp = reinterpret_cast<const float4*>(x + off);
    float4* gp = reinterpret_cast<float4*>(g_xn + off);
    int t = threadIdx.x;

    __shared__ float rs[512], rq[512];
    float s = 0.f, sq = 0.f;
    for (int i = t; i < GSIZE / 4; i += 512) {
        float4 v = xp[i];
        s  += v.x + v.y + v.z + v.w;
        sq += v.x * v.x + v.y * v.y + v.z * v.z + v.w * v.w;
    }
    rs[t] = s; rq[t] = sq;
    __syncthreads();
    for (int o = 256; o >= 1; o >>= 1) {
        if (t < o) { rs[t] += rs[t + o]; rq[t] += rq[t + o]; }
        __syncthreads();
    }
    float mean = rs[0] * (1.f / GSIZE);
    float var  = rq[0] * (1.f / GSIZE) - mean * mean;
    float rstd = rsqrtf(var + 1e-5f);

    __shared__ __nv_bfloat16 sh[64][72], sl[64][72];
    int c = t >> 3, j0 = (t & 7) * 8;
    float gm = gamma[g * CPG + c] * rstd;
    float bt = beta[g * CPG + c] - mean * gm;
    int nl = t >> 3, chn = t & 7;

    for (int tn = 0; tn < 16; tn++) {
        int base = c * 256 + tn * 16 + (t & 7) * 2;
        float4 v0 = xp[base], v1 = xp[base + 1];
        float y[8] = { v0.x * gm + bt, v0.y * gm + bt, v0.z * gm + bt, v0.w * gm + bt,
                       v1.x * gm + bt, v1.y * gm + bt, v1.z * gm + bt, v1.w * gm + bt };
        float4 w0, w1;
        w0.x = y[0]; w0.y = y[1]; w0.z = y[2]; w0.w = y[3];
        w1.x = y[4]; w1.y = y[5]; w1.z = y[6]; w1.w = y[7];
        gp[base] = w0; gp[base + 1] = w1;
#pragma unroll
        for (int i = 0; i < 8; i++) {
            __nv_bfloat16 h, l;
            split_bf16(y[i], h, l);
            sh[j0 + i][c] = h; sl[j0 + i][c] = l;
        }
        __syncthreads();
        size_t dst = ((size_t)b * NTOK + tn * 64 + nl) * CH + g * CPG + chn * 8;
        *reinterpret_cast<uint4*>(&g_xnTh[dst]) = *reinterpret_cast<uint4*>(&sh[nl][chn * 8]);
        *reinterpret_cast<uint4*>(&g_xnTl[dst]) = *reinterpret_cast<uint4*>(&sl[nl][chn * 8]);
        __syncthreads();
    }
}

// ---------------------------------------------------------------------------
// Weight convert fp32 -> hi/lo planes
// ---------------------------------------------------------------------------
__global__ void conv_kernel(const float* __restrict__ src, __nv_bfloat16* __restrict__ h,
                            __nv_bfloat16* __restrict__ l, int n8) {
    int i = blockIdx.x * 256 + threadIdx.x;
    if (i >= n8) return;
    const float4* s = reinterpret_cast<const float4*>(src) + i * 2;
    float4 v0 = s[0], v1 = s[1];
    __nv_bfloat16 hh[8], ll[8];
    split_bf16(v0.x, hh[0], ll[0]); split_bf16(v0.y, hh[1], ll[1]);
    split_bf16(v0.z, hh[2], ll[2]); split_bf16(v0.w, hh[3], ll[3]);
    split_bf16(v1.x, hh[4], ll[4]); split_bf16(v1.y, hh[5], ll[5]);
    split_bf16(v1.z, hh[6], ll[6]); split_bf16(v1.w, hh[7], ll[7]);
    *reinterpret_cast<uint4*>(h + (size_t)i * 8) = *reinterpret_cast<uint4*>(hh);
    *reinterpret_cast<uint4*>(l + (size_t)i * 8) = *reinterpret_cast<uint4*>(ll);
}

// ---------------------------------------------------------------------------
// k softmax over c per (b,n); writes bf16 planes [C,N].
// ---------------------------------------------------------------------------
__global__ __launch_bounds__(256) void ksoftmax_kernel() {
    int b = blockIdx.x >> 5;
    int n0 = (blockIdx.x & 31) * 32;
    const float* base = g_qkvT + (size_t)b * C3 * NTOK + (size_t)CH * NTOK + n0;
    __nv_bfloat16* kh = g_kh + (size_t)b * CH * NTOK + n0;
    __nv_bfloat16* kl = g_kl + (size_t)b * CH * NTOK + n0;
    int lane = threadIdx.x & 31, j = threadIdx.x >> 5;

    float mx = -1e30f, sum = 0.f;
    for (int i = 0; i < 64; i++) {
        float v = base[(size_t)(j * 64 + i) * NTOK + lane];
        float nm = fmaxf(mx, v);
        sum = sum * __expf(mx - nm) + __expf(v - nm);
        mx = nm;
    }
    __shared__ float sM[8][32], sS[8][32];
    sM[j][lane] = mx; sS[j][lane] = sum;
    __syncthreads();
    if (j == 0) {
        float M = sM[0][lane], S = sS[0][lane];
#pragma unroll
        for (int t = 1; t < 8; t++) {
            float m2 = sM[t][lane], s2 = sS[t][lane];
            float nm = fmaxf(M, m2);
            S = S * __expf(M - nm) + s2 * __expf(m2 - nm);
            M = nm;
        }
        sM[0][lane] = M; sS[0][lane] = 1.f / S;
    }
    __syncthreads();
    float M = sM[0][lane], inv = sS[0][lane];
    for (int i = 0; i < 64; i++) {
        size_t idx = (size_t)(j * 64 + i) * NTOK + lane;
        float e = __expf(base[idx] - M) * inv;
        __nv_bfloat16 h, l;
        split_bf16(e, h, l);
        kh[idx] = h; kl[idx] = l;
    }
}

// ---------------------------------------------------------------------------
// q softmax over n per (b,c); writes TRANSPOSED planes qT [B,N,C].
// ---------------------------------------------------------------------------
__global__ __launch_bounds__(256) void qsoftmax_kernel() {
    int b = blockIdx.x >> 4, c0 = (blockIdx.x & 15) * 32;
    const float* base = g_qkvT + (size_t)b * C3 * NTOK;
    int t = threadIdx.x;
    int cr = t >> 3, sub = t & 7;
    const float4* rp = reinterpret_cast<const float4*>(
        base + (size_t)(c0 + cr) * NTOK + sub * 128);

    float mx = -1e30f, sum = 0.f;
#pragma unroll
    for (int i = 0; i < 32; i++) {
        float4 v = rp[i];
        float m4 = fmaxf(fmaxf(v.x, v.y), fmaxf(v.z, v.w));
        float nm = fmaxf(mx, m4);
        sum = sum * __expf(mx - nm) + __expf(v.x - nm) + __expf(v.y - nm)
            + __expf(v.z - nm) + __expf(v.w - nm);
        mx = nm;
    }
#pragma unroll
    for (int o = 4; o >= 1; o >>= 1) {
        float m2 = __shfl_xor_sync(0xFFFFFFFFu, mx, o);
        float s2 = __shfl_xor_sync(0xFFFFFFFFu, sum, o);
        float nm = fmaxf(mx, m2);
        sum = sum * __expf(mx - nm) + s2 * __expf(m2 - nm);
        mx = nm;
    }
    __shared__ float sM[32], sI[32];
    if (sub == 0) { sM[cr] = mx; sI[cr] = 1.f / sum; }
    __syncthreads();
    float M = sM[cr], inv = sI[cr];

    __shared__ __nv_bfloat16 th[64][40], tl[64][40];
    int nl = t >> 2, chn = t & 3;
    for (int tn = 0; tn < 16; tn++) {
        const float4* sp = reinterpret_cast<const float4*>(
            base + (size_t)(c0 + cr) * NTOK + tn * 64 + sub * 8);
        float4 v0 = sp[0], v1 = sp[1];
        float e[8] = { __expf(v0.x - M) * inv, __expf(v0.y - M) * inv,
                       __expf(v0.z - M) * inv, __expf(v0.w - M) * inv,
                       __expf(v1.x - M) * inv, __expf(v1.y - M) * inv,
                       __expf(v1.z - M) * inv, __expf(v1.w - M) * inv };
#pragma unroll
        for (int i = 0; i < 8; i++) {
            __nv_bfloat16 h, l;
            split_bf16(e[i], h, l);
            th[sub * 8 + i][cr] = h; tl[sub * 8 + i][cr] = l;
        }
        __syncthreads();
        size_t dst = ((size_t)b * NTOK + tn * 64 + nl) * CH + c0 + chn * 8;
        *reinterpret_cast<uint4*>(&g_qTh[dst]) = *reinterpret_cast<uint4*>(&th[nl][chn * 8]);
        *reinterpret_cast<uint4*>(&g_qTl[dst]) = *reinterpret_cast<uint4*>(&tl[nl][chn * 8]);
        __syncthreads();
    }
}

// ---------------------------------------------------------------------------
// Launch
// ---------------------------------------------------------------------------
extern "C" void kernel_launch(void* const* d_in, const int* in_sizes, int n_in,
                              void* d_out, int out_size) {
    const float* x      = (const float*)d_in[0];
    const float* gn_w   = (const float*)d_in[1];
    const float* gn_b   = (const float*)d_in[2];
    const float* qkv_w  = (const float*)d_in[3];
    const float* qkv_b  = (const float*)d_in[4];
    const float* proj_w = (const float*)d_in[5];
    const float* proj_b = (const float*)d_in[6];
    float* out = (float*)d_out;

    void* p;
    cudaGetSymbolAddress(&p, g_xn);   float* xn   = (float*)p;
    cudaGetSymbolAddress(&p, g_qkvT); float* qkvT = (float*)p;
    cudaGetSymbolAddress(&p, g_xnTh); __nv_bfloat16* xnTh = (__nv_bfloat16*)p;
    cudaGetSymbolAddress(&p, g_xnTl); __nv_bfloat16* xnTl = (__nv_bfloat16*)p;
    cudaGetSymbolAddress(&p, g_w1h);  __nv_bfloat16* w1h = (__nv_bfloat16*)p;
    cudaGetSymbolAddress(&p, g_w1l);  __nv_bfloat16* w1l = (__nv_bfloat16*)p;
    cudaGetSymbolAddress(&p, g_w2h);  __nv_bfloat16* w2h = (__nv_bfloat16*)p;
    cudaGetSymbolAddress(&p, g_w2l);  __nv_bfloat16* w2l = (__nv_bfloat16*)p;
    cudaGetSymbolAddress(&p, g_kh);   __nv_bfloat16* kh = (__nv_bfloat16*)p;
    cudaGetSymbolAddress(&p, g_kl);   __nv_bfloat16* kl = (__nv_bfloat16*)p;
    cudaGetSymbolAddress(&p, g_vh);   __nv_bfloat16* vh = (__nv_bfloat16*)p;
    cudaGetSymbolAddress(&p, g_vl);   __nv_bfloat16* vl = (__nv_bfloat16*)p;
    cudaGetSymbolAddress(&p, g_qTh);  __nv_bfloat16* qTh = (__nv_bfloat16*)p;
    cudaGetSymbolAddress(&p, g_qTl);  __nv_bfloat16* qTl = (__nv_bfloat16*)p;
    cudaGetSymbolAddress(&p, g_ch);   __nv_bfloat16* ch = (__nv_bfloat16*)p;
    cudaGetSymbolAddress(&p, g_cl);   __nv_bfloat16* cl = (__nv_bfloat16*)p;
    cudaGetSymbolAddress(&p, g_o1h);  __nv_bfloat16* o1h = (__nv_bfloat16*)p;
    cudaGetSymbolAddress(&p, g_o1l);  __nv_bfloat16* o1l = (__nv_bfloat16*)p;

    constexpr int SM4 = (2 * 128 + 2 * 128) * 64 * 3;  // 98304
    constexpr int SM2 = (2 * 128 + 2 * 64) * 64 * 3;   // 73728
    cudaFuncSetAttribute(gemm3s<4, 3>, cudaFuncAttributeMaxDynamicSharedMemorySize, SM4);
    cudaFuncSetAttribute(gemm3s<2, 0>, cudaFuncAttributeMaxDynamicSharedMemorySize, SM2);
    cudaFuncSetAttribute(gemm3s<4, 2>, cudaFuncAttributeMaxDynamicSharedMemorySize, SM4);

    // 0) weight planes
    conv_kernel<<<(C3 * CH / 8 + 255) / 256, 256>>>(qkv_w, w1h, w1l, C3 * CH / 8);
    conv_kernel<<<(CH * CH / 8 + 255) / 256, 256>>>(proj_w, w2h, w2l, CH * CH / 8);

    // 1) GroupNorm
    gn_kernel<<<BATCH * GRP, 512>>>(x, gn_w, gn_b);

    // 2) GEMM1 (EP3): q,k rows -> fp32 qkvT; v rows -> bf16 planes. M=1536 N=1024 K=512
    gemm3s<4, 3><<<dim3(NTOK / 128, C3 / 128, BATCH), 256, SM4>>>(
        w1h, w1l, xnTh, xnTl, qkvT, vh, vl,
        CH, CH, CH, NTOK,
        0LL, (long long)NTOK * CH, (long long)C3 * NTOK, (long long)CH * NTOK,
        qkv_b, nullptr);

    // 3) softmaxes -> bf16 planes
    ksoftmax_kernel<<<BATCH * 32, 256>>>();
    qsoftmax_kernel<<<BATCH * 16, 256>>>();

    // 4) GEMM2: ctx[d,c] = sum_n v[d,n]*k[c,n]. M=512 N=512 K=1024, BN=64
    gemm3s<2, 0><<<dim3(CH / 64, CH / 128, BATCH), 256, SM2>>>(
        vh, vl, kh, kl, nullptr, ch, cl,
        NTOK, NTOK, NTOK, CH,
        (long long)CH * NTOK, (long long)CH * NTOK, 0LL, (long long)CH * CH,
        nullptr, nullptr);

    // 5) GEMM3: out1[n,d] = sum_c qT[n,c]*ctx[d,c]. M=1024 N=512 K=512, BN=64
    gemm3s<2, 0><<<dim3(CH / 64, NTOK / 128, BATCH), 256, SM2>>>(
        qTh, qTl, ch, cl, nullptr, o1h, o1l,
        CH, CH, CH, CH,
        (long long)NTOK * CH, (long long)CH * CH, 0LL, (long long)NTOK * CH,
        nullptr, nullptr);

    // 6) GEMM4 (EP2): out[d,n] = proj(out1) + b + xn. M=512 N=1024 K=512
    gemm3s<4, 2><<<dim3(NTOK / 128, CH / 128, BATCH), 256, SM4>>>(
        w2h, w2l, o1h, o1l, out, nullptr, nullptr,
        CH, CH, CH, NTOK,
        0LL, (long long)NTOK * CH, (long long)CH * NTOK, 0LL,
        proj_b, xn);
}

// round 6
// speedup vs baseline: 2.1012x; 1.0062x over previous
#include <cuda_runtime.h>
#include <cuda_bf16.h>
#include <cstdint>

#define BATCH 8
#define CH    512
#define NTOK  1024
#define C3    1536
#define GRP   8
#define CPG   64
#define GSIZE 65536

// ---------------- scratch (device globals) ----------------
__device__ float g_xn  [BATCH * CH * NTOK];            // fp32 residual [B,C,N]
__device__ float g_qkvT[BATCH * C3 * NTOK];            // fp32 GEMM1 out (q,k rows used)
__device__ __nv_bfloat16 g_xnTh[BATCH * NTOK * CH];    // xn^T hi [B,N,C]
__device__ __nv_bfloat16 g_xnTl[BATCH * NTOK * CH];
__device__ __nv_bfloat16 g_w1h[C3 * CH], g_w1l[C3 * CH];
__device__ __nv_bfloat16 g_w2h[CH * CH], g_w2l[CH * CH];
__device__ __nv_bfloat16 g_kh[BATCH * CH * NTOK], g_kl[BATCH * CH * NTOK];   // [B,C,N]
__device__ __nv_bfloat16 g_vh[BATCH * CH * NTOK], g_vl[BATCH * CH * NTOK];   // [B,C,N]
__device__ __nv_bfloat16 g_qTh[BATCH * NTOK * CH], g_qTl[BATCH * NTOK * CH]; // [B,N,C]
__device__ __nv_bfloat16 g_ch[BATCH * CH * CH],  g_cl[BATCH * CH * CH];      // ctx [B,d,c]
__device__ __nv_bfloat16 g_o1h[BATCH * NTOK * CH], g_o1l[BATCH * NTOK * CH]; // out1 [B,n,d]

// ---------------- helpers ----------------
__device__ __forceinline__ uint32_t smem_u32(const void* p) {
    uint32_t a;
    asm("{ .reg .u64 t; cvta.to.shared.u64 t, %1; cvt.u32.u64 %0, t; }" : "=r"(a) : "l"(p));
    return a;
}
__device__ __forceinline__ void split_bf16(float x, __nv_bfloat16& h, __nv_bfloat16& l) {
    h = __float2bfloat16_rn(x);
    l = __float2bfloat16_rn(x - __bfloat162float(h));
}
__device__ __forceinline__ void mma16816(float* c, uint32_t a0, uint32_t a1,
                                         uint32_t a2, uint32_t a3,
                                         uint32_t b0, uint32_t b1) {
    asm volatile(
        "mma.sync.aligned.m16n8k16.row.col.f32.bf16.bf16.f32 "
        "{%0,%1,%2,%3},{%4,%5,%6,%7},{%8,%9},{%0,%1,%2,%3};"
        : "+f"(c[0]), "+f"(c[1]), "+f"(c[2]), "+f"(c[3])
        : "r"(a0), "r"(a1), "r"(a2), "r"(a3), "r"(b0), "r"(b1));
}
__device__ __forceinline__ void ldm4(uint32_t& r0, uint32_t& r1, uint32_t& r2,
                                     uint32_t& r3, uint32_t a) {
    asm volatile("ldmatrix.sync.aligned.m8n8.x4.shared.b16 {%0,%1,%2,%3}, [%4];"
                 : "=r"(r0), "=r"(r1), "=r"(r2), "=r"(r3) : "r"(a));
}
#define CPA16(d, s) asm volatile("cp.async.cg.shared.global [%0], [%1], 16;" :: "r"(d), "l"(s))
#define CPCOMMIT()  asm volatile("cp.async.commit_group;")
#define CPWAIT1()   asm volatile("cp.async.wait_group 1;" ::: "memory")
#define CPWAIT0()   asm volatile("cp.async.wait_group 0;" ::: "memory")

// swizzled byte offset within a plane: row r (64B rows), 16B chunk c
__device__ __forceinline__ uint32_t swz(int r, int c) {
    return (uint32_t)(r * 64 + ((c ^ ((r >> 1) & 3)) << 4));
}

// ---------------------------------------------------------------------------
// bf16x3 tensor-core GEMM, 3-stage cp.async pipeline, swizzled smem,
// pass-reordered MMAs (independent accumulator chains).
// D[BM x BN] = sum_k A(m,k)*B(n,k); BM=128, BN=32*NWT.
// EP 0: bf16 hi/lo planes out.   EP 2: fp32 + bias[m] + resid.
// EP 3: m0<1024 -> fp32 + bias; m0>=1024 -> bf16 planes at (m-1024) + bias.
// ---------------------------------------------------------------------------
template <int NWT, int EP, int OCC>
__global__ __launch_bounds__(256, OCC) void gemm3s(
    const __nv_bfloat16* __restrict__ Ah, const __nv_bfloat16* __restrict__ Al,
    const __nv_bfloat16* __restrict__ Bh, const __nv_bfloat16* __restrict__ Bl,
    float* __restrict__ C, __nv_bfloat16* __restrict__ Ch, __nv_bfloat16* __restrict__ Cl,
    int K, int lda, int ldb, int ldc,
    long long sA, long long sB, long long sC, long long sCp,
    const float* __restrict__ bias, const float* __restrict__ resid)
{
    constexpr int BM = 128, BN = 32 * NWT;
    constexpr int AOB = 0;
    constexpr int ALB = BM * 64;
    constexpr int BOB = 2 * BM * 64;
    constexpr int BLB = 2 * BM * 64 + BN * 64;
    constexpr int SSB = (2 * BM + 2 * BN) * 64;
    constexpr int ITA = (2 * BM * 4) / 256;
    constexpr int ITB = (2 * BN * 4) / 256;
    constexpr int LPB = BN * 4;

    extern __shared__ __nv_bfloat16 smbuf[];
    const uint32_t su = smem_u32(smbuf);
    const int tid = threadIdx.x;
    const int bz = blockIdx.z;
    Ah += (size_t)bz * sA; Al += (size_t)bz * sA;
    Bh += (size_t)bz * sB; Bl += (size_t)bz * sB;
    const int m0 = blockIdx.y * BM, n0 = blockIdx.x * BN;

    const int lane = tid & 31, wid = tid >> 5;
    const int g = lane >> 2, tg = lane & 3;
    const int wm = (wid & 1) * 64, wn = (wid >> 1) * (8 * NWT);
    const int lr = lane & 15, lchunk = lane >> 4;

    float acc[4][NWT][4];
#pragma unroll
    for (int i = 0; i < 4; i++)
#pragma unroll
        for (int j = 0; j < NWT; j++)
#pragma unroll
            for (int q = 0; q < 4; q++) acc[i][j][q] = 0.f;

    auto fill = [&](int st, int k0) {
        uint32_t base = su + (uint32_t)(st * SSB);
#pragma unroll
        for (int i = 0; i < ITA; i++) {
            int idx = tid + 256 * i;
            int pl = idx >> 9, rem = idx & 511;
            int row = rem >> 2, ch = rem & 3;
            const __nv_bfloat16* s = (pl ? Al : Ah) + (size_t)(m0 + row) * lda + k0 + ch * 8;
            CPA16(base + (uint32_t)(pl ? ALB : AOB) + swz(row, ch), s);
        }
#pragma unroll
        for (int i = 0; i < ITB; i++) {
            int idx = tid + 256 * i;
            int pl = idx / LPB, rem = idx % LPB;
            int row = rem >> 2, ch = rem & 3;
            const __nv_bfloat16* s = (pl ? Bl : Bh) + (size_t)(n0 + row) * ldb + k0 + ch * 8;
            CPA16(base + (uint32_t)(pl ? BLB : BOB) + swz(row, ch), s);
        }
        CPCOMMIT();
    };

    const int NC = K / 32;
    fill(0, 0);
    fill(1, 32);

    int st = 0;
    for (int c = 0; c < NC; c++) {
        if (c + 1 < NC) { CPWAIT1(); } else { CPWAIT0(); }
        __syncthreads();
        if (c + 2 < NC) {
            int ns = st + 2; if (ns >= 3) ns -= 3;
            fill(ns, (c + 2) * 32);
        }
        const uint32_t sb = su + (uint32_t)(st * SSB);

#pragma unroll
        for (int ks = 0; ks < 32; ks += 16) {
            const int kc = (ks >> 3) + lchunk;
            // ---- load ALL fragments for this k-step ----
            uint32_t Bhf[2 * NWT], Blf[2 * NWT];
#pragma unroll
            for (int pr = 0; pr < NWT / 2; pr++) {
                int r = wn + pr * 16 + lr;
                ldm4(Bhf[pr * 4 + 0], Bhf[pr * 4 + 1], Bhf[pr * 4 + 2], Bhf[pr * 4 + 3],
                     sb + BOB + swz(r, kc));
                ldm4(Blf[pr * 4 + 0], Blf[pr * 4 + 1], Blf[pr * 4 + 2], Blf[pr * 4 + 3],
                     sb + BLB + swz(r, kc));
            }
            uint32_t Ahf[4][4], Alf[4][4];
#pragma unroll
            for (int mt = 0; mt < 4; mt++) {
                int r = wm + mt * 16 + lr;
                ldm4(Ahf[mt][0], Ahf[mt][1], Ahf[mt][2], Ahf[mt][3], sb + AOB + swz(r, kc));
                ldm4(Alf[mt][0], Alf[mt][1], Alf[mt][2], Alf[mt][3], sb + ALB + swz(r, kc));
            }
            // ---- pass 1: hi x hi (independent acc chains) ----
#pragma unroll
            for (int mt = 0; mt < 4; mt++)
#pragma unroll
                for (int nt = 0; nt < NWT; nt++) {
                    int i0 = (nt >> 1) * 4 + (nt & 1);
                    mma16816(acc[mt][nt], Ahf[mt][0], Ahf[mt][1], Ahf[mt][2], Ahf[mt][3],
                             Bhf[i0], Bhf[i0 + 2]);
                }
            // ---- pass 2: hi x lo ----
#pragma unroll
            for (int mt = 0; mt < 4; mt++)
#pragma unroll
                for (int nt = 0; nt < NWT; nt++) {
                    int i0 = (nt >> 1) * 4 + (nt & 1);
                    mma16816(acc[mt][nt], Ahf[mt][0], Ahf[mt][1], Ahf[mt][2], Ahf[mt][3],
                             Blf[i0], Blf[i0 + 2]);
                }
            // ---- pass 3: lo x hi ----
#pragma unroll
            for (int mt = 0; mt < 4; mt++)
#pragma unroll
                for (int nt = 0; nt < NWT; nt++) {
                    int i0 = (nt >> 1) * 4 + (nt & 1);
                    mma16816(acc[mt][nt], Alf[mt][0], Alf[mt][1], Alf[mt][2], Alf[mt][3],
                             Bhf[i0], Bhf[i0 + 2]);
                }
        }
        if (++st == 3) st = 0;
    }

    // ---- epilogue ----
    const bool planes = (EP == 0) || (EP == 3 && m0 >= 2 * CH);
    if (planes) {
        __nv_bfloat16* Chp = Ch + (size_t)bz * sCp;
        __nv_bfloat16* Clp = Cl + (size_t)bz * sCp;
        const int mb = (EP == 3) ? 2 * CH : 0;
#pragma unroll
        for (int mt = 0; mt < 4; mt++) {
            int m = m0 + wm + mt * 16 + g;
            float bv0 = (EP == 3) ? bias[m] : 0.f;
            float bv1 = (EP == 3) ? bias[m + 8] : 0.f;
#pragma unroll
            for (int nt = 0; nt < NWT; nt++) {
                int n = n0 + wn + nt * 8 + tg * 2;
                float* a = acc[mt][nt];
                __nv_bfloat16 h0, h1, h2, h3, l0, l1, l2, l3;
                split_bf16(a[0] + bv0, h0, l0); split_bf16(a[1] + bv0, h1, l1);
                split_bf16(a[2] + bv1, h2, l2); split_bf16(a[3] + bv1, h3, l3);
                size_t i0 = (size_t)(m - mb) * ldc + n;
                size_t i1 = (size_t)(m - mb + 8) * ldc + n;
                *reinterpret_cast<__nv_bfloat162*>(Chp + i0) = __nv_bfloat162(h0, h1);
                *reinterpret_cast<__nv_bfloat162*>(Chp + i1) = __nv_bfloat162(h2, h3);
                *reinterpret_cast<__nv_bfloat162*>(Clp + i0) = __nv_bfloat162(l0, l1);
                *reinterpret_cast<__nv_bfloat162*>(Clp + i1) = __nv_bfloat162(l2, l3);
            }
        }
    } else {
        float* Cp = C + (size_t)bz * sC;
        const float* R = (EP == 2) ? (resid + (size_t)bz * sC) : nullptr;
#pragma unroll
        for (int mt = 0; mt < 4; mt++) {
            int m = m0 + wm + mt * 16 + g;
            float bv0 = bias[m], bv1 = bias[m + 8];
#pragma unroll
            for (int nt = 0; nt < NWT; nt++) {
                int n = n0 + wn + nt * 8 + tg * 2;
                float* a = acc[mt][nt];
                size_t i0 = (size_t)m * ldc + n;
                size_t i1 = (size_t)(m + 8) * ldc + n;
                float2 o0, o1;
                o0.x = a[0] + bv0; o0.y = a[1] + bv0;
                o1.x = a[2] + bv1; o1.y = a[3] + bv1;
                if (EP == 2) {
                    float2 r0 = *reinterpret_cast<const float2*>(R + i0);
                    float2 r1 = *reinterpret_cast<const float2*>(R + i1);
                    o0.x += r0.x; o0.y += r0.y; o1.x += r1.x; o1.y += r1.y;
                }
                *reinterpret_cast<float2*>(Cp + i0) = o0;
                *reinterpret_cast<float2*>(Cp + i1) = o1;
            }
        }
    }
}

// ---------------------------------------------------------------------------
// GroupNorm: block per (b,g). fp32 residual + transposed bf16 planes.
// ---------------------------------------------------------------------------
__global__ __launch_bounds__(512) void gn_kernel(const float* __restrict__ x,
                                                 const float* __restrict__ gamma,
                                                 const float* __restrict__ beta) {
    int b = blockIdx.x >> 3, g = blockIdx.x & 7;
    size_t off = ((size_t)b * CH + (size_t)g * CPG) * NTOK;
    const float4* xp = reinterpret_cast<const float4*>(x + off);
    float4* gp = reinterpret_cast<float4*>(g_xn + off);
    int t = threadIdx.x;

    __shared__ float rs[512], rq[512];
    float s = 0.f, sq = 0.f;
    for (int i = t; i < GSIZE / 4; i += 512) {
        float4 v = xp[i];
        s  += v.x + v.y + v.z + v.w;
        sq += v.x * v.x + v.y * v.y + v.z * v.z + v.w * v.w;
    }
    rs[t] = s; rq[t] = sq;
    __syncthreads();
    for (int o = 256; o >= 1; o >>= 1) {
        if (t < o) { rs[t] += rs[t + o]; rq[t] += rq[t + o]; }
        __syncthreads();
    }
    float mean = rs[0] * (1.f / GSIZE);
    float var  = rq[0] * (1.f / GSIZE) - mean * mean;
    float rstd = rsqrtf(var + 1e-5f);

    __shared__ __nv_bfloat16 sh[64][72], sl[64][72];
    int c = t >> 3, j0 = (t & 7) * 8;
    float gm = gamma[g * CPG + c] * rstd;
    float bt = beta[g * CPG + c] - mean * gm;
    int nl = t >> 3, chn = t & 7;

    for (int tn = 0; tn < 16; tn++) {
        int base = c * 256 + tn * 16 + (t & 7) * 2;
        float4 v0 = xp[base], v1 = xp[base + 1];
        float y[8] = { v0.x * gm + bt, v0.y * gm + bt, v0.z * gm + bt, v0.w * gm + bt,
                       v1.x * gm + bt, v1.y * gm + bt, v1.z * gm + bt, v1.w * gm + bt };
        float4 w0, w1;
        w0.x = y[0]; w0.y = y[1]; w0.z = y[2]; w0.w = y[3];
        w1.x = y[4]; w1.y = y[5]; w1.z = y[6]; w1.w = y[7];
        gp[base] = w0; gp[base + 1] = w1;
#pragma unroll
        for (int i = 0; i < 8; i++) {
            __nv_bfloat16 h, l;
            split_bf16(y[i], h, l);
            sh[j0 + i][c] = h; sl[j0 + i][c] = l;
        }
        __syncthreads();
        size_t dst = ((size_t)b * NTOK + tn * 64 + nl) * CH + g * CPG + chn * 8;
        *reinterpret_cast<uint4*>(&g_xnTh[dst]) = *reinterpret_cast<uint4*>(&sh[nl][chn * 8]);
        *reinterpret_cast<uint4*>(&g_xnTl[dst]) = *reinterpret_cast<uint4*>(&sl[nl][chn * 8]);
        __syncthreads();
    }
}

// ---------------------------------------------------------------------------
// Weight convert fp32 -> hi/lo planes
// ---------------------------------------------------------------------------
__global__ void conv_kernel(const float* __restrict__ src, __nv_bfloat16* __restrict__ h,
                            __nv_bfloat16* __restrict__ l, int n8) {
    int i = blockIdx.x * 256 + threadIdx.x;
    if (i >= n8) return;
    const float4* s = reinterpret_cast<const float4*>(src) + i * 2;
    float4 v0 = s[0], v1 = s[1];
    __nv_bfloat16 hh[8], ll[8];
    split_bf16(v0.x, hh[0], ll[0]); split_bf16(v0.y, hh[1], ll[1]);
    split_bf16(v0.z, hh[2], ll[2]); split_bf16(v0.w, hh[3], ll[3]);
    split_bf16(v1.x, hh[4], ll[4]); split_bf16(v1.y, hh[5], ll[5]);
    split_bf16(v1.z, hh[6], ll[6]); split_bf16(v1.w, hh[7], ll[7]);
    *reinterpret_cast<uint4*>(h + (size_t)i * 8) = *reinterpret_cast<uint4*>(hh);
    *reinterpret_cast<uint4*>(l + (size_t)i * 8) = *reinterpret_cast<uint4*>(ll);
}

// ---------------------------------------------------------------------------
// k softmax over c per (b,n); writes bf16 planes [C,N].
// ---------------------------------------------------------------------------
__global__ __launch_bounds__(256) void ksoftmax_kernel() {
    int b = blockIdx.x >> 5;
    int n0 = (blockIdx.x & 31) * 32;
    const float* base = g_qkvT + (size_t)b * C3 * NTOK + (size_t)CH * NTOK + n0;
    __nv_bfloat16* kh = g_kh + (size_t)b * CH * NTOK + n0;
    __nv_bfloat16* kl = g_kl + (size_t)b * CH * NTOK + n0;
    int lane = threadIdx.x & 31, j = threadIdx.x >> 5;

    float mx = -1e30f, sum = 0.f;
    for (int i = 0; i < 64; i++) {
        float v = base[(size_t)(j * 64 + i) * NTOK + lane];
        float nm = fmaxf(mx, v);
        sum = sum * __expf(mx - nm) + __expf(v - nm);
        mx = nm;
    }
    __shared__ float sM[8][32], sS[8][32];
    sM[j][lane] = mx; sS[j][lane] = sum;
    __syncthreads();
    if (j == 0) {
        float M = sM[0][lane], S = sS[0][lane];
#pragma unroll
        for (int t = 1; t < 8; t++) {
            float m2 = sM[t][lane], s2 = sS[t][lane];
            float nm = fmaxf(M, m2);
            S = S * __expf(M - nm) + s2 * __expf(m2 - nm);
            M = nm;
        }
        sM[0][lane] = M; sS[0][lane] = 1.f / S;
    }
    __syncthreads();
    float M = sM[0][lane], inv = sS[0][lane];
    for (int i = 0; i < 64; i++) {
        size_t idx = (size_t)(j * 64 + i) * NTOK + lane;
        float e = __expf(base[idx] - M) * inv;
        __nv_bfloat16 h, l;
        split_bf16(e, h, l);
        kh[idx] = h; kl[idx] = l;
    }
}

// ---------------------------------------------------------------------------
// q softmax over n per (b,c); writes TRANSPOSED planes qT [B,N,C].
// ---------------------------------------------------------------------------
__global__ __launch_bounds__(256) void qsoftmax_kernel() {
    int b = blockIdx.x >> 4, c0 = (blockIdx.x & 15) * 32;
    const float* base = g_qkvT + (size_t)b * C3 * NTOK;
    int t = threadIdx.x;
    int cr = t >> 3, sub = t & 7;
    const float4* rp = reinterpret_cast<const float4*>(
        base + (size_t)(c0 + cr) * NTOK + sub * 128);

    float mx = -1e30f, sum = 0.f;
#pragma unroll
    for (int i = 0; i < 32; i++) {
        float4 v = rp[i];
        float m4 = fmaxf(fmaxf(v.x, v.y), fmaxf(v.z, v.w));
        float nm = fmaxf(mx, m4);
        sum = sum * __expf(mx - nm) + __expf(v.x - nm) + __expf(v.y - nm)
            + __expf(v.z - nm) + __expf(v.w - nm);
        mx = nm;
    }
#pragma unroll
    for (int o = 4; o >= 1; o >>= 1) {
        float m2 = __shfl_xor_sync(0xFFFFFFFFu, mx, o);
        float s2 = __shfl_xor_sync(0xFFFFFFFFu, sum, o);
        float nm = fmaxf(mx, m2);
        sum = sum * __expf(mx - nm) + s2 * __expf(m2 - nm);
        mx = nm;
    }
    __shared__ float sM[32], sI[32];
    if (sub == 0) { sM[cr] = mx; sI[cr] = 1.f / sum; }
    __syncthreads();
    float M = sM[cr], inv = sI[cr];

    __shared__ __nv_bfloat16 th[64][40], tl[64][40];
    int nl = t >> 2, chn = t & 3;
    for (int tn = 0; tn < 16; tn++) {
        const float4* sp = reinterpret_cast<const float4*>(
            base + (size_t)(c0 + cr) * NTOK + tn * 64 + sub * 8);
        float4 v0 = sp[0], v1 = sp[1];
        float e[8] = { __expf(v0.x - M) * inv, __expf(v0.y - M) * inv,
                       __expf(v0.z - M) * inv, __expf(v0.w - M) * inv,
                       __expf(v1.x - M) * inv, __expf(v1.y - M) * inv,
                       __expf(v1.z - M) * inv, __expf(v1.w - M) * inv };
#pragma unroll
        for (int i = 0; i < 8; i++) {
            __nv_bfloat16 h, l;
            split_bf16(e[i], h, l);
            th[sub * 8 + i][cr] = h; tl[sub * 8 + i][cr] = l;
        }
        __syncthreads();
        size_t dst = ((size_t)b * NTOK + tn * 64 + nl) * CH + c0 + chn * 8;
        *reinterpret_cast<uint4*>(&g_qTh[dst]) = *reinterpret_cast<uint4*>(&th[nl][chn * 8]);
        *reinterpret_cast<uint4*>(&g_qTl[dst]) = *reinterpret_cast<uint4*>(&tl[nl][chn * 8]);
        __syncthreads();
    }
}

// ---------------------------------------------------------------------------
// Launch
// ---------------------------------------------------------------------------
extern "C" void kernel_launch(void* const* d_in, const int* in_sizes, int n_in,
                              void* d_out, int out_size) {
    const float* x      = (const float*)d_in[0];
    const float* gn_w   = (const float*)d_in[1];
    const float* gn_b   = (const float*)d_in[2];
    const float* qkv_w  = (const float*)d_in[3];
    const float* qkv_b  = (const float*)d_in[4];
    const float* proj_w = (const float*)d_in[5];
    const float* proj_b = (const float*)d_in[6];
    float* out = (float*)d_out;

    void* p;
    cudaGetSymbolAddress(&p, g_xn);   float* xn   = (float*)p;
    cudaGetSymbolAddress(&p, g_qkvT); float* qkvT = (float*)p;
    cudaGetSymbolAddress(&p, g_xnTh); __nv_bfloat16* xnTh = (__nv_bfloat16*)p;
    cudaGetSymbolAddress(&p, g_xnTl); __nv_bfloat16* xnTl = (__nv_bfloat16*)p;
    cudaGetSymbolAddress(&p, g_w1h);  __nv_bfloat16* w1h = (__nv_bfloat16*)p;
    cudaGetSymbolAddress(&p, g_w1l);  __nv_bfloat16* w1l = (__nv_bfloat16*)p;
    cudaGetSymbolAddress(&p, g_w2h);  __nv_bfloat16* w2h = (__nv_bfloat16*)p;
    cudaGetSymbolAddress(&p, g_w2l);  __nv_bfloat16* w2l = (__nv_bfloat16*)p;
    cudaGetSymbolAddress(&p, g_kh);   __nv_bfloat16* kh = (__nv_bfloat16*)p;
    cudaGetSymbolAddress(&p, g_kl);   __nv_bfloat16* kl = (__nv_bfloat16*)p;
    cudaGetSymbolAddress(&p, g_vh);   __nv_bfloat16* vh = (__nv_bfloat16*)p;
    cudaGetSymbolAddress(&p, g_vl);   __nv_bfloat16* vl = (__nv_bfloat16*)p;
    cudaGetSymbolAddress(&p, g_qTh);  __nv_bfloat16* qTh = (__nv_bfloat16*)p;
    cudaGetSymbolAddress(&p, g_qTl);  __nv_bfloat16* qTl = (__nv_bfloat16*)p;
    cudaGetSymbolAddress(&p, g_ch);   __nv_bfloat16* ch = (__nv_bfloat16*)p;
    cudaGetSymbolAddress(&p, g_cl);   __nv_bfloat16* cl = (__nv_bfloat16*)p;
    cudaGetSymbolAddress(&p, g_o1h);  __nv_bfloat16* o1h = (__nv_bfloat16*)p;
    cudaGetSymbolAddress(&p, g_o1l);  __nv_bfloat16* o1l = (__nv_bfloat16*)p;

    constexpr int SM4 = (2 * 128 + 2 * 128) * 64 * 3;  // 98304
    constexpr int SM2 = (2 * 128 + 2 * 64) * 64 * 3;   // 73728
    cudaFuncSetAttribute(gemm3s<4, 3, 2>, cudaFuncAttributeMaxDynamicSharedMemorySize, SM4);
    cudaFuncSetAttribute(gemm3s<2, 0, 3>, cudaFuncAttributeMaxDynamicSharedMemorySize, SM2);
    cudaFuncSetAttribute(gemm3s<4, 2, 2>, cudaFuncAttributeMaxDynamicSharedMemorySize, SM4);

    // 0) weight planes
    conv_kernel<<<(C3 * CH / 8 + 255) / 256, 256>>>(qkv_w, w1h, w1l, C3 * CH / 8);
    conv_kernel<<<(CH * CH / 8 + 255) / 256, 256>>>(proj_w, w2h, w2l, CH * CH / 8);

    // 1) GroupNorm
    gn_kernel<<<BATCH * GRP, 512>>>(x, gn_w, gn_b);

    // 2) GEMM1 (EP3): q,k rows -> fp32 qkvT; v rows -> bf16 planes. M=1536 N=1024 K=512
    gemm3s<4, 3, 2><<<dim3(NTOK / 128, C3 / 128, BATCH), 256, SM4>>>(
        w1h, w1l, xnTh, xnTl, qkvT, vh, vl,
        CH, CH, CH, NTOK,
        0LL, (long long)NTOK * CH, (long long)C3 * NTOK, (long long)CH * NTOK,
        qkv_b, nullptr);

    // 3) softmaxes -> bf16 planes
    ksoftmax_kernel<<<BATCH * 32, 256>>>();
    qsoftmax_kernel<<<BATCH * 16, 256>>>();

    // 4) GEMM2: ctx[d,c] = sum_n v[d,n]*k[c,n]. M=512 N=512 K=1024, BN=64
    gemm3s<2, 0, 3><<<dim3(CH / 64, CH / 128, BATCH), 256, SM2>>>(
        vh, vl, kh, kl, nullptr, ch, cl,
        NTOK, NTOK, NTOK, CH,
        (long long)CH * NTOK, (long long)CH * NTOK, 0LL, (long long)CH * CH,
        nullptr, nullptr);

    // 5) GEMM3: out1[n,d] = sum_c qT[n,c]*ctx[d,c]. M=1024 N=512 K=512, BN=64
    gemm3s<2, 0, 3><<<dim3(CH / 64, NTOK / 128, BATCH), 256, SM2>>>(
        qTh, qTl, ch, cl, nullptr, o1h, o1l,
        CH, CH, CH, CH,
        (long long)NTOK * CH, (long long)CH * CH, 0LL, (long long)NTOK * CH,
        nullptr, nullptr);

    // 6) GEMM4 (EP2): out[d,n] = proj(out1) + b + xn. M=512 N=1024 K=512
    gemm3s<4, 2, 2><<<dim3(NTOK / 128, CH / 128, BATCH), 256, SM4>>>(
        w2h, w2l, o1h, o1l, out, nullptr, nullptr,
        CH, CH, CH, NTOK,
        0LL, (long long)NTOK * CH, (long long)CH * NTOK, 0LL,
        proj_b, xn);
}

// round 7
// speedup vs baseline: 2.4051x; 1.1446x over previous
#include <cuda_runtime.h>
#include <cuda_bf16.h>
#include <cuda_fp16.h>
#include <cstdint>

#define BATCH 8
#define CH    512
#define NTOK  1024
#define C3    1536
#define GRP   8
#define CPG   64
#define GSIZE 65536

// ---------------- scratch (device globals) ----------------
__device__ float g_xn  [BATCH * CH * NTOK];            // fp32 residual [B,C,N]
__device__ float g_qkvT[BATCH * C3 * NTOK];            // fp32 GEMM1 out (q,k rows used)
__device__ __half g_xnTh[BATCH * NTOK * CH];           // xn^T hi fp16 [B,N,C]
__device__ __half g_xnTl[BATCH * NTOK * CH];           // xn^T lo fp16
__device__ __half g_w1f[C3 * CH];                      // w1 hi fp16 (lo dropped)
__device__ __nv_bfloat16 g_w2h[CH * CH], g_w2l[CH * CH];
__device__ __nv_bfloat16 g_kh[BATCH * CH * NTOK], g_kl[BATCH * CH * NTOK];   // [B,C,N]
__device__ __nv_bfloat16 g_vh[BATCH * CH * NTOK], g_vl[BATCH * CH * NTOK];   // [B,C,N]
__device__ __nv_bfloat16 g_qTh[BATCH * NTOK * CH], g_qTl[BATCH * NTOK * CH]; // [B,N,C]
__device__ __nv_bfloat16 g_ch[BATCH * CH * CH],  g_cl[BATCH * CH * CH];      // ctx [B,d,c]
__device__ __nv_bfloat16 g_o1h[BATCH * NTOK * CH], g_o1l[BATCH * NTOK * CH]; // out1 [B,n,d]

// ---------------- helpers ----------------
__device__ __forceinline__ uint32_t smem_u32(const void* p) {
    uint32_t a;
    asm("{ .reg .u64 t; cvta.to.shared.u64 t, %1; cvt.u32.u64 %0, t; }" : "=r"(a) : "l"(p));
    return a;
}
__device__ __forceinline__ void split_bf16(float x, __nv_bfloat16& h, __nv_bfloat16& l) {
    h = __float2bfloat16_rn(x);
    l = __float2bfloat16_rn(x - __bfloat162float(h));
}
__device__ __forceinline__ void split_f16(float x, __half& h, __half& l) {
    h = __float2half_rn(x);
    l = __float2half_rn(x - __half2float(h));
}
template <bool F16>
__device__ __forceinline__ void mma16816(float* c, uint32_t a0, uint32_t a1,
                                         uint32_t a2, uint32_t a3,
                                         uint32_t b0, uint32_t b1) {
    if (F16) {
        asm volatile(
            "mma.sync.aligned.m16n8k16.row.col.f32.f16.f16.f32 "
            "{%0,%1,%2,%3},{%4,%5,%6,%7},{%8,%9},{%0,%1,%2,%3};"
            : "+f"(c[0]), "+f"(c[1]), "+f"(c[2]), "+f"(c[3])
            : "r"(a0), "r"(a1), "r"(a2), "r"(a3), "r"(b0), "r"(b1));
    } else {
        asm volatile(
            "mma.sync.aligned.m16n8k16.row.col.f32.bf16.bf16.f32 "
            "{%0,%1,%2,%3},{%4,%5,%6,%7},{%8,%9},{%0,%1,%2,%3};"
            : "+f"(c[0]), "+f"(c[1]), "+f"(c[2]), "+f"(c[3])
            : "r"(a0), "r"(a1), "r"(a2), "r"(a3), "r"(b0), "r"(b1));
    }
}
__device__ __forceinline__ void ldm4(uint32_t& r0, uint32_t& r1, uint32_t& r2,
                                     uint32_t& r3, uint32_t a) {
    asm volatile("ldmatrix.sync.aligned.m8n8.x4.shared.b16 {%0,%1,%2,%3}, [%4];"
                 : "=r"(r0), "=r"(r1), "=r"(r2), "=r"(r3) : "r"(a));
}
#define CPA16(d, s) asm volatile("cp.async.cg.shared.global [%0], [%1], 16;" :: "r"(d), "l"(s))
#define CPCOMMIT()  asm volatile("cp.async.commit_group;")
#define CPWAIT1()   asm volatile("cp.async.wait_group 1;" ::: "memory")
#define CPWAIT0()   asm volatile("cp.async.wait_group 0;" ::: "memory")

// swizzled byte offset within a plane: row r (64B rows), 16B chunk c
__device__ __forceinline__ uint32_t swz(int r, int c) {
    return (uint32_t)(r * 64 + ((c ^ ((r >> 1) & 3)) << 4));
}

// ---------------------------------------------------------------------------
// tensor-core GEMM, 3-stage cp.async pipeline, swizzled smem.
// F16=false: bf16 3-pass (A hi/lo + B hi/lo).
// F16=true : fp16 2-pass (A hi only + B hi/lo) -- drops l_A x h_B term.
// D[BM x BN] = sum_k A(m,k)*B(n,k); BM=128, BN=32*NWT.
// EP 0: bf16 hi/lo planes out.   EP 2: fp32 + bias[m] + resid.
// EP 3: m0<1024 -> fp32 + bias; m0>=1024 -> bf16 planes at (m-1024) + bias.
// ---------------------------------------------------------------------------
template <int NWT, int EP, int OCC, bool F16>
__global__ __launch_bounds__(256, OCC) void gemm3s(
    const uint16_t* __restrict__ Ah, const uint16_t* __restrict__ Al,
    const uint16_t* __restrict__ Bh, const uint16_t* __restrict__ Bl,
    float* __restrict__ C, __nv_bfloat16* __restrict__ Ch, __nv_bfloat16* __restrict__ Cl,
    int K, int lda, int ldb, int ldc,
    long long sA, long long sB, long long sC, long long sCp,
    const float* __restrict__ bias, const float* __restrict__ resid)
{
    constexpr int BM = 128, BN = 32 * NWT;
    constexpr int PA = F16 ? 1 : 2;              // A planes
    constexpr int AOB = 0;
    constexpr int ALB = BM * 64;                 // A-lo (bf16 only)
    constexpr int BOB = PA * BM * 64;
    constexpr int BLB = PA * BM * 64 + BN * 64;
    constexpr int SSB = (PA * BM + 2 * BN) * 64;
    constexpr int ITA = (PA * BM * 4) / 256;
    constexpr int ITB = (2 * BN * 4) / 256;
    constexpr int LPB = BN * 4;

    extern __shared__ __align__(128) uint16_t smbuf[];
    const uint32_t su = smem_u32(smbuf);
    const int tid = threadIdx.x;
    const int bz = blockIdx.z;
    Ah += (size_t)bz * sA;
    if (!F16) Al += (size_t)bz * sA;
    Bh += (size_t)bz * sB; Bl += (size_t)bz * sB;
    const int m0 = blockIdx.y * BM, n0 = blockIdx.x * BN;

    const int lane = tid & 31, wid = tid >> 5;
    const int g = lane >> 2, tg = lane & 3;
    const int wm = (wid & 1) * 64, wn = (wid >> 1) * (8 * NWT);
    const int lr = lane & 15, lchunk = lane >> 4;

    float acc[4][NWT][4];
#pragma unroll
    for (int i = 0; i < 4; i++)
#pragma unroll
        for (int j = 0; j < NWT; j++)
#pragma unroll
            for (int q = 0; q < 4; q++) acc[i][j][q] = 0.f;

    auto fill = [&](int st, int k0) {
        uint32_t base = su + (uint32_t)(st * SSB);
#pragma unroll
        for (int i = 0; i < ITA; i++) {
            int idx = tid + 256 * i;
            int pl = idx >> 9, rem = idx & 511;
            int row = rem >> 2, ch = rem & 3;
            const uint16_t* s = (pl ? Al : Ah) + (size_t)(m0 + row) * lda + k0 + ch * 8;
            CPA16(base + (uint32_t)(pl ? ALB : AOB) + swz(row, ch), s);
        }
#pragma unroll
        for (int i = 0; i < ITB; i++) {
            int idx = tid + 256 * i;
            int pl = idx / LPB, rem = idx % LPB;
            int row = rem >> 2, ch = rem & 3;
            const uint16_t* s = (pl ? Bl : Bh) + (size_t)(n0 + row) * ldb + k0 + ch * 8;
            CPA16(base + (uint32_t)(pl ? BLB : BOB) + swz(row, ch), s);
        }
        CPCOMMIT();
    };

    const int NC = K / 32;
    fill(0, 0);
    fill(1, 32);

    int st = 0;
    for (int c = 0; c < NC; c++) {
        if (c + 1 < NC) { CPWAIT1(); } else { CPWAIT0(); }
        __syncthreads();
        if (c + 2 < NC) {
            int ns = st + 2; if (ns >= 3) ns -= 3;
            fill(ns, (c + 2) * 32);
        }
        const uint32_t sb = su + (uint32_t)(st * SSB);

#pragma unroll
        for (int ks = 0; ks < 32; ks += 16) {
            const int kc = (ks >> 3) + lchunk;
            uint32_t Bhf[2 * NWT], Blf[2 * NWT];
#pragma unroll
            for (int pr = 0; pr < NWT / 2; pr++) {
                int r = wn + pr * 16 + lr;
                ldm4(Bhf[pr * 4 + 0], Bhf[pr * 4 + 1], Bhf[pr * 4 + 2], Bhf[pr * 4 + 3],
                     sb + BOB + swz(r, kc));
                ldm4(Blf[pr * 4 + 0], Blf[pr * 4 + 1], Blf[pr * 4 + 2], Blf[pr * 4 + 3],
                     sb + BLB + swz(r, kc));
            }
            uint32_t Ahf[4][4], Alf[4][4];
#pragma unroll
            for (int mt = 0; mt < 4; mt++) {
                int r = wm + mt * 16 + lr;
                ldm4(Ahf[mt][0], Ahf[mt][1], Ahf[mt][2], Ahf[mt][3], sb + AOB + swz(r, kc));
                if (!F16)
                    ldm4(Alf[mt][0], Alf[mt][1], Alf[mt][2], Alf[mt][3], sb + ALB + swz(r, kc));
            }
            // pass 1: hiA x hiB
#pragma unroll
            for (int mt = 0; mt < 4; mt++)
#pragma unroll
                for (int nt = 0; nt < NWT; nt++) {
                    int i0 = (nt >> 1) * 4 + (nt & 1);
                    mma16816<F16>(acc[mt][nt], Ahf[mt][0], Ahf[mt][1], Ahf[mt][2], Ahf[mt][3],
                                  Bhf[i0], Bhf[i0 + 2]);
                }
            // pass 2: hiA x loB
#pragma unroll
            for (int mt = 0; mt < 4; mt++)
#pragma unroll
                for (int nt = 0; nt < NWT; nt++) {
                    int i0 = (nt >> 1) * 4 + (nt & 1);
                    mma16816<F16>(acc[mt][nt], Ahf[mt][0], Ahf[mt][1], Ahf[mt][2], Ahf[mt][3],
                                  Blf[i0], Blf[i0 + 2]);
                }
            // pass 3 (bf16 only): loA x hiB
            if (!F16) {
#pragma unroll
                for (int mt = 0; mt < 4; mt++)
#pragma unroll
                    for (int nt = 0; nt < NWT; nt++) {
                        int i0 = (nt >> 1) * 4 + (nt & 1);
                        mma16816<F16>(acc[mt][nt], Alf[mt][0], Alf[mt][1], Alf[mt][2], Alf[mt][3],
                                      Bhf[i0], Bhf[i0 + 2]);
                    }
            }
        }
        if (++st == 3) st = 0;
    }

    // ---- epilogue ----
    const bool planes = (EP == 0) || (EP == 3 && m0 >= 2 * CH);
    if (planes) {
        __nv_bfloat16* Chp = Ch + (size_t)bz * sCp;
        __nv_bfloat16* Clp = Cl + (size_t)bz * sCp;
        const int mb = (EP == 3) ? 2 * CH : 0;
#pragma unroll
        for (int mt = 0; mt < 4; mt++) {
            int m = m0 + wm + mt * 16 + g;
            float bv0 = (EP == 3) ? bias[m] : 0.f;
            float bv1 = (EP == 3) ? bias[m + 8] : 0.f;
#pragma unroll
            for (int nt = 0; nt < NWT; nt++) {
                int n = n0 + wn + nt * 8 + tg * 2;
                float* a = acc[mt][nt];
                __nv_bfloat16 h0, h1, h2, h3, l0, l1, l2, l3;
                split_bf16(a[0] + bv0, h0, l0); split_bf16(a[1] + bv0, h1, l1);
                split_bf16(a[2] + bv1, h2, l2); split_bf16(a[3] + bv1, h3, l3);
                size_t i0 = (size_t)(m - mb) * ldc + n;
                size_t i1 = (size_t)(m - mb + 8) * ldc + n;
                *reinterpret_cast<__nv_bfloat162*>(Chp + i0) = __nv_bfloat162(h0, h1);
                *reinterpret_cast<__nv_bfloat162*>(Chp + i1) = __nv_bfloat162(h2, h3);
                *reinterpret_cast<__nv_bfloat162*>(Clp + i0) = __nv_bfloat162(l0, l1);
                *reinterpret_cast<__nv_bfloat162*>(Clp + i1) = __nv_bfloat162(l2, l3);
            }
        }
    } else {
        float* Cp = C + (size_t)bz * sC;
        const float* R = (EP == 2) ? (resid + (size_t)bz * sC) : nullptr;
#pragma unroll
        for (int mt = 0; mt < 4; mt++) {
            int m = m0 + wm + mt * 16 + g;
            float bv0 = bias[m], bv1 = bias[m + 8];
#pragma unroll
            for (int nt = 0; nt < NWT; nt++) {
                int n = n0 + wn + nt * 8 + tg * 2;
                float* a = acc[mt][nt];
                size_t i0 = (size_t)m * ldc + n;
                size_t i1 = (size_t)(m + 8) * ldc + n;
                float2 o0, o1;
                o0.x = a[0] + bv0; o0.y = a[1] + bv0;
                o1.x = a[2] + bv1; o1.y = a[3] + bv1;
                if (EP == 2) {
                    float2 r0 = *reinterpret_cast<const float2*>(R + i0);
                    float2 r1 = *reinterpret_cast<const float2*>(R + i1);
                    o0.x += r0.x; o0.y += r0.y; o1.x += r1.x; o1.y += r1.y;
                }
                *reinterpret_cast<float2*>(Cp + i0) = o0;
                *reinterpret_cast<float2*>(Cp + i1) = o1;
            }
        }
    }
}

// ---------------------------------------------------------------------------
// GroupNorm: block per (b,g). fp32 residual + transposed fp16 planes.
// ---------------------------------------------------------------------------
__global__ __launch_bounds__(512) void gn_kernel(const float* __restrict__ x,
                                                 const float* __restrict__ gamma,
                                                 const float* __restrict__ beta) {
    int b = blockIdx.x >> 3, g = blockIdx.x & 7;
    size_t off = ((size_t)b * CH + (size_t)g * CPG) * NTOK;
    const float4* xp = reinterpret_cast<const float4*>(x + off);
    float4* gp = reinterpret_cast<float4*>(g_xn + off);
    int t = threadIdx.x;

    __shared__ float rs[512], rq[512];
    float s = 0.f, sq = 0.f;
    for (int i = t; i < GSIZE / 4; i += 512) {
        float4 v = xp[i];
        s  += v.x + v.y + v.z + v.w;
        sq += v.x * v.x + v.y * v.y + v.z * v.z + v.w * v.w;
    }
    rs[t] = s; rq[t] = sq;
    __syncthreads();
    for (int o = 256; o >= 1; o >>= 1) {
        if (t < o) { rs[t] += rs[t + o]; rq[t] += rq[t + o]; }
        __syncthreads();
    }
    float mean = rs[0] * (1.f / GSIZE);
    float var  = rq[0] * (1.f / GSIZE) - mean * mean;
    float rstd = rsqrtf(var + 1e-5f);

    __shared__ __half sh[64][72], sl[64][72];
    int c = t >> 3, j0 = (t & 7) * 8;
    float gm = gamma[g * CPG + c] * rstd;
    float bt = beta[g * CPG + c] - mean * gm;
    int nl = t >> 3, chn = t & 7;

    for (int tn = 0; tn < 16; tn++) {
        int base = c * 256 + tn * 16 + (t & 7) * 2;
        float4 v0 = xp[base], v1 = xp[base + 1];
        float y[8] = { v0.x * gm + bt, v0.y * gm + bt, v0.z * gm + bt, v0.w * gm + bt,
                       v1.x * gm + bt, v1.y * gm + bt, v1.z * gm + bt, v1.w * gm + bt };
        float4 w0, w1;
        w0.x = y[0]; w0.y = y[1]; w0.z = y[2]; w0.w = y[3];
        w1.x = y[4]; w1.y = y[5]; w1.z = y[6]; w1.w = y[7];
        gp[base] = w0; gp[base + 1] = w1;
#pragma unroll
        for (int i = 0; i < 8; i++) {
            __half h, l;
            split_f16(y[i], h, l);
            sh[j0 + i][c] = h; sl[j0 + i][c] = l;
        }
        __syncthreads();
        size_t dst = ((size_t)b * NTOK + tn * 64 + nl) * CH + g * CPG + chn * 8;
        *reinterpret_cast<uint4*>(&g_xnTh[dst]) = *reinterpret_cast<uint4*>(&sh[nl][chn * 8]);
        *reinterpret_cast<uint4*>(&g_xnTl[dst]) = *reinterpret_cast<uint4*>(&sl[nl][chn * 8]);
        __syncthreads();
    }
}

// ---------------------------------------------------------------------------
// Weight converts
// ---------------------------------------------------------------------------
__global__ void conv_bf16_kernel(const float* __restrict__ src, __nv_bfloat16* __restrict__ h,
                                 __nv_bfloat16* __restrict__ l, int n8) {
    int i = blockIdx.x * 256 + threadIdx.x;
    if (i >= n8) return;
    const float4* s = reinterpret_cast<const float4*>(src) + i * 2;
    float4 v0 = s[0], v1 = s[1];
    __nv_bfloat16 hh[8], ll[8];
    split_bf16(v0.x, hh[0], ll[0]); split_bf16(v0.y, hh[1], ll[1]);
    split_bf16(v0.z, hh[2], ll[2]); split_bf16(v0.w, hh[3], ll[3]);
    split_bf16(v1.x, hh[4], ll[4]); split_bf16(v1.y, hh[5], ll[5]);
    split_bf16(v1.z, hh[6], ll[6]); split_bf16(v1.w, hh[7], ll[7]);
    *reinterpret_cast<uint4*>(h + (size_t)i * 8) = *reinterpret_cast<uint4*>(hh);
    *reinterpret_cast<uint4*>(l + (size_t)i * 8) = *reinterpret_cast<uint4*>(ll);
}
__global__ void conv_f16h_kernel(const float* __restrict__ src, __half* __restrict__ h, int n8) {
    int i = blockIdx.x * 256 + threadIdx.x;
    if (i >= n8) return;
    const float4* s = reinterpret_cast<const float4*>(src) + i * 2;
    float4 v0 = s[0], v1 = s[1];
    __half hh[8];
    hh[0] = __float2half_rn(v0.x); hh[1] = __float2half_rn(v0.y);
    hh[2] = __float2half_rn(v0.z); hh[3] = __float2half_rn(v0.w);
    hh[4] = __float2half_rn(v1.x); hh[5] = __float2half_rn(v1.y);
    hh[6] = __float2half_rn(v1.z); hh[7] = __float2half_rn(v1.w);
    *reinterpret_cast<uint4*>(h + (size_t)i * 8) = *reinterpret_cast<uint4*>(hh);
}

// ---------------------------------------------------------------------------
// k softmax over c per (b,n); writes bf16 planes [C,N].
// ---------------------------------------------------------------------------
__global__ __launch_bounds__(256) void ksoftmax_kernel() {
    int b = blockIdx.x >> 5;
    int n0 = (blockIdx.x & 31) * 32;
    const float* base = g_qkvT + (size_t)b * C3 * NTOK + (size_t)CH * NTOK + n0;
    __nv_bfloat16* kh = g_kh + (size_t)b * CH * NTOK + n0;
    __nv_bfloat16* kl = g_kl + (size_t)b * CH * NTOK + n0;
    int lane = threadIdx.x & 31, j = threadIdx.x >> 5;

    float mx = -1e30f, sum = 0.f;
    for (int i = 0; i < 64; i++) {
        float v = base[(size_t)(j * 64 + i) * NTOK + lane];
        float nm = fmaxf(mx, v);
        sum = sum * __expf(mx - nm) + __expf(v - nm);
        mx = nm;
    }
    __shared__ float sM[8][32], sS[8][32];
    sM[j][lane] = mx; sS[j][lane] = sum;
    __syncthreads();
    if (j == 0) {
        float M = sM[0][lane], S = sS[0][lane];
#pragma unroll
        for (int t = 1; t < 8; t++) {
            float m2 = sM[t][lane], s2 = sS[t][lane];
            float nm = fmaxf(M, m2);
            S = S * __expf(M - nm) + s2 * __expf(m2 - nm);
            M = nm;
        }
        sM[0][lane] = M; sS[0][lane] = 1.f / S;
    }
    __syncthreads();
    float M = sM[0][lane], inv = sS[0][lane];
    for (int i = 0; i < 64; i++) {
        size_t idx = (size_t)(j * 64 + i) * NTOK + lane;
        float e = __expf(base[idx] - M) * inv;
        __nv_bfloat16 h, l;
        split_bf16(e, h, l);
        kh[idx] = h; kl[idx] = l;
    }
}

// ---------------------------------------------------------------------------
// q softmax over n per (b,c); writes TRANSPOSED bf16 planes qT [B,N,C].
// ---------------------------------------------------------------------------
__global__ __launch_bounds__(256) void qsoftmax_kernel() {
    int b = blockIdx.x >> 4, c0 = (blockIdx.x & 15) * 32;
    const float* base = g_qkvT + (size_t)b * C3 * NTOK;
    int t = threadIdx.x;
    int cr = t >> 3, sub = t & 7;
    const float4* rp = reinterpret_cast<const float4*>(
        base + (size_t)(c0 + cr) * NTOK + sub * 128);

    float mx = -1e30f, sum = 0.f;
#pragma unroll
    for (int i = 0; i < 32; i++) {
        float4 v = rp[i];
        float m4 = fmaxf(fmaxf(v.x, v.y), fmaxf(v.z, v.w));
        float nm = fmaxf(mx, m4);
        sum = sum * __expf(mx - nm) + __expf(v.x - nm) + __expf(v.y - nm)
            + __expf(v.z - nm) + __expf(v.w - nm);
        mx = nm;
    }
#pragma unroll
    for (int o = 4; o >= 1; o >>= 1) {
        float m2 = __shfl_xor_sync(0xFFFFFFFFu, mx, o);
        float s2 = __shfl_xor_sync(0xFFFFFFFFu, sum, o);
        float nm = fmaxf(mx, m2);
        sum = sum * __expf(mx - nm) + s2 * __expf(m2 - nm);
        mx = nm;
    }
    __shared__ float sM[32], sI[32];
    if (sub == 0) { sM[cr] = mx; sI[cr] = 1.f / sum; }
    __syncthreads();
    float M = sM[cr], inv = sI[cr];

    __shared__ __nv_bfloat16 th[64][40], tl[64][40];
    int nl = t >> 2, chn = t & 3;
    for (int tn = 0; tn < 16; tn++) {
        const float4* sp = reinterpret_cast<const float4*>(
            base + (size_t)(c0 + cr) * NTOK + tn * 64 + sub * 8);
        float4 v0 = sp[0], v1 = sp[1];
        float e[8] = { __expf(v0.x - M) * inv, __expf(v0.y - M) * inv,
                       __expf(v0.z - M) * inv, __expf(v0.w - M) * inv,
                       __expf(v1.x - M) * inv, __expf(v1.y - M) * inv,
                       __expf(v1.z - M) * inv, __expf(v1.w - M) * inv };
#pragma unroll
        for (int i = 0; i < 8; i++) {
            __nv_bfloat16 h, l;
            split_bf16(e[i], h, l);
            th[sub * 8 + i][cr] = h; tl[sub * 8 + i][cr] = l;
        }
        __syncthreads();
        size_t dst = ((size_t)b * NTOK + tn * 64 + nl) * CH + c0 + chn * 8;
        *reinterpret_cast<uint4*>(&g_qTh[dst]) = *reinterpret_cast<uint4*>(&th[nl][chn * 8]);
        *reinterpret_cast<uint4*>(&g_qTl[dst]) = *reinterpret_cast<uint4*>(&tl[nl][chn * 8]);
        __syncthreads();
    }
}

// ---------------------------------------------------------------------------
// Launch
// ---------------------------------------------------------------------------
extern "C" void kernel_launch(void* const* d_in, const int* in_sizes, int n_in,
                              void* d_out, int out_size) {
    const float* x      = (const float*)d_in[0];
    const float* gn_w   = (const float*)d_in[1];
    const float* gn_b   = (const float*)d_in[2];
    const float* qkv_w  = (const float*)d_in[3];
    const float* qkv_b  = (const float*)d_in[4];
    const float* proj_w = (const float*)d_in[5];
    const float* proj_b = (const float*)d_in[6];
    float* out = (float*)d_out;

    void* p;
    cudaGetSymbolAddress(&p, g_xn);   float* xn   = (float*)p;
    cudaGetSymbolAddress(&p, g_qkvT); float* qkvT = (float*)p;
    cudaGetSymbolAddress(&p, g_xnTh); __half* xnTh = (__half*)p;
    cudaGetSymbolAddress(&p, g_xnTl); __half* xnTl = (__half*)p;
    cudaGetSymbolAddress(&p, g_w1f);  __half* w1f = (__half*)p;
    cudaGetSymbolAddress(&p, g_w2h);  __nv_bfloat16* w2h = (__nv_bfloat16*)p;
    cudaGetSymbolAddress(&p, g_w2l);  __nv_bfloat16* w2l = (__nv_bfloat16*)p;
    cudaGetSymbolAddress(&p, g_kh);   __nv_bfloat16* kh = (__nv_bfloat16*)p;
    cudaGetSymbolAddress(&p, g_kl);   __nv_bfloat16* kl = (__nv_bfloat16*)p;
    cudaGetSymbolAddress(&p, g_vh);   __nv_bfloat16* vh = (__nv_bfloat16*)p;
    cudaGetSymbolAddress(&p, g_vl);   __nv_bfloat16* vl = (__nv_bfloat16*)p;
    cudaGetSymbolAddress(&p, g_qTh);  __nv_bfloat16* qTh = (__nv_bfloat16*)p;
    cudaGetSymbolAddress(&p, g_qTl);  __nv_bfloat16* qTl = (__nv_bfloat16*)p;
    cudaGetSymbolAddress(&p, g_ch);   __nv_bfloat16* ch = (__nv_bfloat16*)p;
    cudaGetSymbolAddress(&p, g_cl);   __nv_bfloat16* cl = (__nv_bfloat16*)p;
    cudaGetSymbolAddress(&p, g_o1h);  __nv_bfloat16* o1h = (__nv_bfloat16*)p;
    cudaGetSymbolAddress(&p, g_o1l);  __nv_bfloat16* o1l = (__nv_bfloat16*)p;

    constexpr int SM4F = (1 * 128 + 2 * 128) * 64 * 3;  // 73728 (fp16 GEMM1)
    constexpr int SM4  = (2 * 128 + 2 * 128) * 64 * 3;  // 98304 (bf16 NWT4)
    constexpr int SM2  = (2 * 128 + 2 * 64) * 64 * 3;   // 73728 (bf16 NWT2)
    cudaFuncSetAttribute(gemm3s<4, 3, 2, true>,  cudaFuncAttributeMaxDynamicSharedMemorySize, SM4F);
    cudaFuncSetAttribute(gemm3s<2, 0, 3, false>, cudaFuncAttributeMaxDynamicSharedMemorySize, SM2);
    cudaFuncSetAttribute(gemm3s<4, 2, 2, false>, cudaFuncAttributeMaxDynamicSharedMemorySize, SM4);

    // 0) weight planes
    conv_f16h_kernel<<<(C3 * CH / 8 + 255) / 256, 256>>>(qkv_w, w1f, C3 * CH / 8);
    conv_bf16_kernel<<<(CH * CH / 8 + 255) / 256, 256>>>(proj_w, w2h, w2l, CH * CH / 8);

    // 1) GroupNorm
    gn_kernel<<<BATCH * GRP, 512>>>(x, gn_w, gn_b);

    // 2) GEMM1 fp16 2-pass (EP3): q,k -> fp32 qkvT; v -> bf16 planes. M=1536 N=1024 K=512
    gemm3s<4, 3, 2, true><<<dim3(NTOK / 128, C3 / 128, BATCH), 256, SM4F>>>(
        (const uint16_t*)w1f, nullptr, (const uint16_t*)xnTh, (const uint16_t*)xnTl,
        qkvT, vh, vl,
        CH, CH, CH, NTOK,
        0LL, (long long)NTOK * CH, (long long)C3 * NTOK, (long long)CH * NTOK,
        qkv_b, nullptr);

    // 3) softmaxes -> bf16 planes
    ksoftmax_kernel<<<BATCH * 32, 256>>>();
    qsoftmax_kernel<<<BATCH * 16, 256>>>();

    // 4) GEMM2 bf16 3-pass: ctx[d,c] = sum_n v[d,n]*k[c,n]. M=512 N=512 K=1024
    gemm3s<2, 0, 3, false><<<dim3(CH / 64, CH / 128, BATCH), 256, SM2>>>(
        (const uint16_t*)vh, (const uint16_t*)vl, (const uint16_t*)kh, (const uint16_t*)kl,
        nullptr, ch, cl,
        NTOK, NTOK, NTOK, CH,
        (long long)CH * NTOK, (long long)CH * NTOK, 0LL, (long long)CH * CH,
        nullptr, nullptr);

    // 5) GEMM3 bf16 3-pass: out1[n,d] = sum_c qT[n,c]*ctx[d,c]. M=1024 N=512 K=512
    gemm3s<2, 0, 3, false><<<dim3(CH / 64, NTOK / 128, BATCH), 256, SM2>>>(
        (const uint16_t*)qTh, (const uint16_t*)qTl, (const uint16_t*)ch, (const uint16_t*)cl,
        nullptr, o1h, o1l,
        CH, CH, CH, CH,
        (long long)NTOK * CH, (long long)CH * CH, 0LL, (long long)NTOK * CH,
        nullptr, nullptr);

    // 6) GEMM4 bf16 3-pass (EP2): out[d,n] = proj(out1) + b + xn. M=512 N=1024 K=512
    gemm3s<4, 2, 2, false><<<dim3(NTOK / 128, CH / 128, BATCH), 256, SM4>>>(
        (const uint16_t*)w2h, (const uint16_t*)w2l, (const uint16_t*)o1h, (const uint16_t*)o1l,
        out, nullptr, nullptr,
        CH, CH, CH, NTOK,
        0LL, (long long)NTOK * CH, (long long)CH * NTOK, 0LL,
        proj_b, xn);
}

// round 8
// speedup vs baseline: 2.8897x; 1.2015x over previous
#include <cuda_runtime.h>
#include <cuda_fp16.h>
#include <cstdint>

#define BATCH 8
#define CH    512
#define NTOK  1024
#define C3    1536
#define GRP   8
#define CPG   64
#define GSIZE 65536

// ---------------- scratch (device globals) ----------------
__device__ float g_xn  [BATCH * CH * NTOK];            // fp32 residual [B,C,N]
__device__ float g_qkvT[BATCH * C3 * NTOK];            // fp32 GEMM1 out (q,k rows)
__device__ __half g_xnTh[BATCH * NTOK * CH];           // xn^T hi [B,N,C]
__device__ __half g_xnTl[BATCH * NTOK * CH];           // xn^T lo
__device__ __half g_w1f[C3 * CH];                      // w1 hi
__device__ __half g_w2f[CH * CH];                      // w2 hi
__device__ __half g_kh[BATCH * CH * NTOK], g_kl[BATCH * CH * NTOK];   // k planes [C,N]
__device__ __half g_vh[BATCH * CH * NTOK];                            // v hi [C,N]
__device__ __half g_qTh[BATCH * NTOK * CH];                           // qT hi [N,C]
__device__ __half g_ch[BATCH * CH * CH],  g_cl[BATCH * CH * CH];      // ctx [d,c]
__device__ __half g_o1h[BATCH * NTOK * CH], g_o1l[BATCH * NTOK * CH]; // out1 [n,d]

// ---------------- helpers ----------------
__device__ __forceinline__ uint32_t smem_u32(const void* p) {
    uint32_t a;
    asm("{ .reg .u64 t; cvta.to.shared.u64 t, %1; cvt.u32.u64 %0, t; }" : "=r"(a) : "l"(p));
    return a;
}
__device__ __forceinline__ void split_f16(float x, __half& h, __half& l) {
    h = __float2half_rn(x);
    l = __float2half_rn(x - __half2float(h));
}
__device__ __forceinline__ void mmaf16(float* c, uint32_t a0, uint32_t a1,
                                       uint32_t a2, uint32_t a3,
                                       uint32_t b0, uint32_t b1) {
    asm volatile(
        "mma.sync.aligned.m16n8k16.row.col.f32.f16.f16.f32 "
        "{%0,%1,%2,%3},{%4,%5,%6,%7},{%8,%9},{%0,%1,%2,%3};"
        : "+f"(c[0]), "+f"(c[1]), "+f"(c[2]), "+f"(c[3])
        : "r"(a0), "r"(a1), "r"(a2), "r"(a3), "r"(b0), "r"(b1));
}
__device__ __forceinline__ void ldm4(uint32_t& r0, uint32_t& r1, uint32_t& r2,
                                     uint32_t& r3, uint32_t a) {
    asm volatile("ldmatrix.sync.aligned.m8n8.x4.shared.b16 {%0,%1,%2,%3}, [%4];"
                 : "=r"(r0), "=r"(r1), "=r"(r2), "=r"(r3) : "r"(a));
}
#define CPA16(d, s) asm volatile("cp.async.cg.shared.global [%0], [%1], 16;" :: "r"(d), "l"(s))
#define CPCOMMIT()  asm volatile("cp.async.commit_group;")
#define CPWAIT1()   asm volatile("cp.async.wait_group 1;" ::: "memory")
#define CPWAIT0()   asm volatile("cp.async.wait_group 0;" ::: "memory")

// swizzled byte offset within a plane: row r (64B rows), 16B chunk c
__device__ __forceinline__ uint32_t swz(int r, int c) {
    return (uint32_t)(r * 64 + ((c ^ ((r >> 1) & 3)) << 4));
}

// ---------------------------------------------------------------------------
// fp16 2-pass tensor-core GEMM (A hi only; B hi+lo), 3-stage cp.async pipeline.
// D[64 x BN] = sum_k A(m,k)*B(n,k); BN = 32*NWT.
// EP 0: fp16 hi/lo planes, no bias (ctx, out1).
// EP 2: fp32 + bias[m] + resid[m*ldc+n] (final).
// EP 3: m0 < 1024 -> fp32 + bias (q,k); m0 >= 1024 -> fp16 hi plane + bias (v).
// 256 threads, 8 warps (2 x 4), warp tile 32 x (8*NWT), 3 CTAs/SM.
// ---------------------------------------------------------------------------
template <int NWT, int EP>
__global__ __launch_bounds__(256, 3) void gemmf16(
    const __half* __restrict__ Ah,
    const __half* __restrict__ Bh, const __half* __restrict__ Bl,
    float* __restrict__ C, __half* __restrict__ Ch, __half* __restrict__ Cl,
    int K, int lda, int ldb, int ldc,
    long long sA, long long sB, long long sC, long long sCp,
    const float* __restrict__ bias, const float* __restrict__ resid)
{
    constexpr int BM = 64, BN = 32 * NWT;
    constexpr int BOB = BM * 64;
    constexpr int BLB = BM * 64 + BN * 64;
    constexpr int SSB = (BM + 2 * BN) * 64;
    constexpr int ITB = (2 * BN * 4) / 256;
    constexpr int LPB = BN * 4;

    extern __shared__ __align__(128) __half smbuf[];
    const uint32_t su = smem_u32(smbuf);
    const int tid = threadIdx.x;
    const int bz = blockIdx.z;
    Ah += (size_t)bz * sA;
    Bh += (size_t)bz * sB; Bl += (size_t)bz * sB;
    const int m0 = blockIdx.y * BM, n0 = blockIdx.x * BN;

    const int lane = tid & 31, wid = tid >> 5;
    const int g = lane >> 2, tg = lane & 3;
    const int wm = (wid & 1) * 32, wn = (wid >> 1) * (8 * NWT);
    const int lr = lane & 15, lchunk = lane >> 4;

    float acc[2][NWT][4];
#pragma unroll
    for (int i = 0; i < 2; i++)
#pragma unroll
        for (int j = 0; j < NWT; j++)
#pragma unroll
            for (int q = 0; q < 4; q++) acc[i][j][q] = 0.f;

    auto fill = [&](int st, int k0) {
        uint32_t base = su + (uint32_t)(st * SSB);
        {   // A: 64 rows x 4 chunks = 256 loads
            int row = tid >> 2, ch = tid & 3;
            const __half* s = Ah + (size_t)(m0 + row) * lda + k0 + ch * 8;
            CPA16(base + swz(row, ch), s);
        }
#pragma unroll
        for (int i = 0; i < ITB; i++) {
            int idx = tid + 256 * i;
            int pl = idx / LPB, rem = idx % LPB;
            int row = rem >> 2, ch = rem & 3;
            const __half* s = (pl ? Bl : Bh) + (size_t)(n0 + row) * ldb + k0 + ch * 8;
            CPA16(base + (uint32_t)(pl ? BLB : BOB) + swz(row, ch), s);
        }
        CPCOMMIT();
    };

    const int NC = K / 32;
    fill(0, 0);
    fill(1, 32);

    int st = 0;
    for (int c = 0; c < NC; c++) {
        if (c + 1 < NC) { CPWAIT1(); } else { CPWAIT0(); }
        __syncthreads();
        if (c + 2 < NC) {
            int ns = st + 2; if (ns >= 3) ns -= 3;
            fill(ns, (c + 2) * 32);
        }
        const uint32_t sb = su + (uint32_t)(st * SSB);

#pragma unroll
        for (int ks = 0; ks < 32; ks += 16) {
            const int kc = (ks >> 3) + lchunk;
            uint32_t Bhf[2 * NWT], Blf[2 * NWT];
#pragma unroll
            for (int pr = 0; pr < NWT / 2; pr++) {
                int r = wn + pr * 16 + lr;
                ldm4(Bhf[pr * 4 + 0], Bhf[pr * 4 + 1], Bhf[pr * 4 + 2], Bhf[pr * 4 + 3],
                     sb + BOB + swz(r, kc));
                ldm4(Blf[pr * 4 + 0], Blf[pr * 4 + 1], Blf[pr * 4 + 2], Blf[pr * 4 + 3],
                     sb + BLB + swz(r, kc));
            }
            uint32_t Af[2][4];
#pragma unroll
            for (int mt = 0; mt < 2; mt++) {
                int r = wm + mt * 16 + lr;
                ldm4(Af[mt][0], Af[mt][1], Af[mt][2], Af[mt][3], sb + swz(r, kc));
            }
            // pass 1: A x hiB
#pragma unroll
            for (int mt = 0; mt < 2; mt++)
#pragma unroll
                for (int nt = 0; nt < NWT; nt++) {
                    int i0 = (nt >> 1) * 4 + (nt & 1);
                    mmaf16(acc[mt][nt], Af[mt][0], Af[mt][1], Af[mt][2], Af[mt][3],
                           Bhf[i0], Bhf[i0 + 2]);
                }
            // pass 2: A x loB
#pragma unroll
            for (int mt = 0; mt < 2; mt++)
#pragma unroll
                for (int nt = 0; nt < NWT; nt++) {
                    int i0 = (nt >> 1) * 4 + (nt & 1);
                    mmaf16(acc[mt][nt], Af[mt][0], Af[mt][1], Af[mt][2], Af[mt][3],
                           Blf[i0], Blf[i0 + 2]);
                }
        }
        if (++st == 3) st = 0;
    }

    // ---- epilogue ----
    const bool planes = (EP == 0) || (EP == 3 && m0 >= 2 * CH);
    if (planes) {
        __half* Chp = Ch + (size_t)bz * sCp;
        __half* Clp = (EP == 0) ? (Cl + (size_t)bz * sCp) : nullptr;
        const int mb = (EP == 3) ? 2 * CH : 0;
#pragma unroll
        for (int mt = 0; mt < 2; mt++) {
            int m = m0 + wm + mt * 16 + g;
            float bv0 = (EP == 3) ? bias[m] : 0.f;
            float bv1 = (EP == 3) ? bias[m + 8] : 0.f;
#pragma unroll
            for (int nt = 0; nt < NWT; nt++) {
                int n = n0 + wn + nt * 8 + tg * 2;
                float* a = acc[mt][nt];
                __half h0, h1, h2, h3, l0, l1, l2, l3;
                split_f16(a[0] + bv0, h0, l0); split_f16(a[1] + bv0, h1, l1);
                split_f16(a[2] + bv1, h2, l2); split_f16(a[3] + bv1, h3, l3);
                size_t i0 = (size_t)(m - mb) * ldc + n;
                size_t i1 = (size_t)(m - mb + 8) * ldc + n;
                *reinterpret_cast<__half2*>(Chp + i0) = __half2(h0, h1);
                *reinterpret_cast<__half2*>(Chp + i1) = __half2(h2, h3);
                if (EP == 0) {
                    *reinterpret_cast<__half2*>(Clp + i0) = __half2(l0, l1);
                    *reinterpret_cast<__half2*>(Clp + i1) = __half2(l2, l3);
                }
            }
        }
    } else {
        float* Cp = C + (size_t)bz * sC;
        const float* R = (EP == 2) ? (resid + (size_t)bz * sC) : nullptr;
#pragma unroll
        for (int mt = 0; mt < 2; mt++) {
            int m = m0 + wm + mt * 16 + g;
            float bv0 = bias[m], bv1 = bias[m + 8];
#pragma unroll
            for (int nt = 0; nt < NWT; nt++) {
                int n = n0 + wn + nt * 8 + tg * 2;
                float* a = acc[mt][nt];
                size_t i0 = (size_t)m * ldc + n;
                size_t i1 = (size_t)(m + 8) * ldc + n;
                float2 o0, o1;
                o0.x = a[0] + bv0; o0.y = a[1] + bv0;
                o1.x = a[2] + bv1; o1.y = a[3] + bv1;
                if (EP == 2) {
                    float2 r0 = *reinterpret_cast<const float2*>(R + i0);
                    float2 r1 = *reinterpret_cast<const float2*>(R + i1);
                    o0.x += r0.x; o0.y += r0.y; o1.x += r1.x; o1.y += r1.y;
                }
                *reinterpret_cast<float2*>(Cp + i0) = o0;
                *reinterpret_cast<float2*>(Cp + i1) = o1;
            }
        }
    }
}

// ---------------------------------------------------------------------------
// GroupNorm: block per (b,g). fp32 residual + transposed fp16 hi/lo planes.
// ---------------------------------------------------------------------------
__global__ __launch_bounds__(512) void gn_kernel(const float* __restrict__ x,
                                                 const float* __restrict__ gamma,
                                                 const float* __restrict__ beta) {
    int b = blockIdx.x >> 3, g = blockIdx.x & 7;
    size_t off = ((size_t)b * CH + (size_t)g * CPG) * NTOK;
    const float4* xp = reinterpret_cast<const float4*>(x + off);
    float4* gp = reinterpret_cast<float4*>(g_xn + off);
    int t = threadIdx.x;

    __shared__ float rs[512], rq[512];
    float s = 0.f, sq = 0.f;
    for (int i = t; i < GSIZE / 4; i += 512) {
        float4 v = xp[i];
        s  += v.x + v.y + v.z + v.w;
        sq += v.x * v.x + v.y * v.y + v.z * v.z + v.w * v.w;
    }
    rs[t] = s; rq[t] = sq;
    __syncthreads();
    for (int o = 256; o >= 1; o >>= 1) {
        if (t < o) { rs[t] += rs[t + o]; rq[t] += rq[t + o]; }
        __syncthreads();
    }
    float mean = rs[0] * (1.f / GSIZE);
    float var  = rq[0] * (1.f / GSIZE) - mean * mean;
    float rstd = rsqrtf(var + 1e-5f);

    __shared__ __half sh[64][72], sl[64][72];
    int c = t >> 3, j0 = (t & 7) * 8;
    float gm = gamma[g * CPG + c] * rstd;
    float bt = beta[g * CPG + c] - mean * gm;
    int nl = t >> 3, chn = t & 7;

    for (int tn = 0; tn < 16; tn++) {
        int base = c * 256 + tn * 16 + (t & 7) * 2;
        float4 v0 = xp[base], v1 = xp[base + 1];
        float y[8] = { v0.x * gm + bt, v0.y * gm + bt, v0.z * gm + bt, v0.w * gm + bt,
                       v1.x * gm + bt, v1.y * gm + bt, v1.z * gm + bt, v1.w * gm + bt };
        float4 w0, w1;
        w0.x = y[0]; w0.y = y[1]; w0.z = y[2]; w0.w = y[3];
        w1.x = y[4]; w1.y = y[5]; w1.z = y[6]; w1.w = y[7];
        gp[base] = w0; gp[base + 1] = w1;
#pragma unroll
        for (int i = 0; i < 8; i++) {
            __half h, l;
            split_f16(y[i], h, l);
            sh[j0 + i][c] = h; sl[j0 + i][c] = l;
        }
        __syncthreads();
        size_t dst = ((size_t)b * NTOK + tn * 64 + nl) * CH + g * CPG + chn * 8;
        *reinterpret_cast<uint4*>(&g_xnTh[dst]) = *reinterpret_cast<uint4*>(&sh[nl][chn * 8]);
        *reinterpret_cast<uint4*>(&g_xnTl[dst]) = *reinterpret_cast<uint4*>(&sl[nl][chn * 8]);
        __syncthreads();
    }
}

// ---------------------------------------------------------------------------
// Weight convert fp32 -> fp16 hi
// ---------------------------------------------------------------------------
__global__ void conv_f16h_kernel(const float* __restrict__ src, __half* __restrict__ h, int n8) {
    int i = blockIdx.x * 256 + threadIdx.x;
    if (i >= n8) return;
    const float4* s = reinterpret_cast<const float4*>(src) + i * 2;
    float4 v0 = s[0], v1 = s[1];
    __half hh[8];
    hh[0] = __float2half_rn(v0.x); hh[1] = __float2half_rn(v0.y);
    hh[2] = __float2half_rn(v0.z); hh[3] = __float2half_rn(v0.w);
    hh[4] = __float2half_rn(v1.x); hh[5] = __float2half_rn(v1.y);
    hh[6] = __float2half_rn(v1.z); hh[7] = __float2half_rn(v1.w);
    *reinterpret_cast<uint4*>(h + (size_t)i * 8) = *reinterpret_cast<uint4*>(hh);
}

// ---------------------------------------------------------------------------
// k softmax over c per (b,n); writes fp16 hi/lo planes [C,N].
// ---------------------------------------------------------------------------
__global__ __launch_bounds__(256) void ksoftmax_kernel() {
    int b = blockIdx.x >> 5;
    int n0 = (blockIdx.x & 31) * 32;
    const float* base = g_qkvT + (size_t)b * C3 * NTOK + (size_t)CH * NTOK + n0;
    __half* kh = g_kh + (size_t)b * CH * NTOK + n0;
    __half* kl = g_kl + (size_t)b * CH * NTOK + n0;
    int lane = threadIdx.x & 31, j = threadIdx.x >> 5;

    float mx = -1e30f, sum = 0.f;
    for (int i = 0; i < 64; i++) {
        float v = base[(size_t)(j * 64 + i) * NTOK + lane];
        float nm = fmaxf(mx, v);
        sum = sum * __expf(mx - nm) + __expf(v - nm);
        mx = nm;
    }
    __shared__ float sM[8][32], sS[8][32];
    sM[j][lane] = mx; sS[j][lane] = sum;
    __syncthreads();
    if (j == 0) {
        float M = sM[0][lane], S = sS[0][lane];
#pragma unroll
        for (int t = 1; t < 8; t++) {
            float m2 = sM[t][lane], s2 = sS[t][lane];
            float nm = fmaxf(M, m2);
            S = S * __expf(M - nm) + s2 * __expf(m2 - nm);
            M = nm;
        }
        sM[0][lane] = M; sS[0][lane] = 1.f / S;
    }
    __syncthreads();
    float M = sM[0][lane], inv = sS[0][lane];
    for (int i = 0; i < 64; i++) {
        size_t idx = (size_t)(j * 64 + i) * NTOK + lane;
        float e = __expf(base[idx] - M) * inv;
        __half h, l;
        split_f16(e, h, l);
        kh[idx] = h; kl[idx] = l;
    }
}

// ---------------------------------------------------------------------------
// q softmax over n per (b,c); writes TRANSPOSED fp16 hi plane qT [N,C].
// ---------------------------------------------------------------------------
__global__ __launch_bounds__(256) void qsoftmax_kernel() {
    int b = blockIdx.x >> 4, c0 = (blockIdx.x & 15) * 32;
    const float* base = g_qkvT + (size_t)b * C3 * NTOK;
    int t = threadIdx.x;
    int cr = t >> 3, sub = t & 7;
    const float4* rp = reinterpret_cast<const float4*>(
        base + (size_t)(c0 + cr) * NTOK + sub * 128);

    float mx = -1e30f, sum = 0.f;
#pragma unroll
    for (int i = 0; i < 32; i++) {
        float4 v = rp[i];
        float m4 = fmaxf(fmaxf(v.x, v.y), fmaxf(v.z, v.w));
        float nm = fmaxf(mx, m4);
        sum = sum * __expf(mx - nm) + __expf(v.x - nm) + __expf(v.y - nm)
            + __expf(v.z - nm) + __expf(v.w - nm);
        mx = nm;
    }
#pragma unroll
    for (int o = 4; o >= 1; o >>= 1) {
        float m2 = __shfl_xor_sync(0xFFFFFFFFu, mx, o);
        float s2 = __shfl_xor_sync(0xFFFFFFFFu, sum, o);
        float nm = fmaxf(mx, m2);
        sum = sum * __expf(mx - nm) + s2 * __expf(m2 - nm);
        mx = nm;
    }
    __shared__ float sM[32], sI[32];
    if (sub == 0) { sM[cr] = mx; sI[cr] = 1.f / sum; }
    __syncthreads();
    float M = sM[cr], inv = sI[cr];

    __shared__ __half th[64][40];
    int nl = t >> 2, chn = t & 3;
    for (int tn = 0; tn < 16; tn++) {
        const float4* sp = reinterpret_cast<const float4*>(
            base + (size_t)(c0 + cr) * NTOK + tn * 64 + sub * 8);
        float4 v0 = sp[0], v1 = sp[1];
        float e[8] = { __expf(v0.x - M) * inv, __expf(v0.y - M) * inv,
                       __expf(v0.z - M) * inv, __expf(v0.w - M) * inv,
                       __expf(v1.x - M) * inv, __expf(v1.y - M) * inv,
                       __expf(v1.z - M) * inv, __expf(v1.w - M) * inv };
#pragma unroll
        for (int i = 0; i < 8; i++)
            th[sub * 8 + i][cr] = __float2half_rn(e[i]);
        __syncthreads();
        size_t dst = ((size_t)b * NTOK + tn * 64 + nl) * CH + c0 + chn * 8;
        *reinterpret_cast<uint4*>(&g_qTh[dst]) = *reinterpret_cast<uint4*>(&th[nl][chn * 8]);
        __syncthreads();
    }
}

// ---------------------------------------------------------------------------
// Launch
// ---------------------------------------------------------------------------
extern "C" void kernel_launch(void* const* d_in, const int* in_sizes, int n_in,
                              void* d_out, int out_size) {
    const float* x      = (const float*)d_in[0];
    const float* gn_w   = (const float*)d_in[1];
    const float* gn_b   = (const float*)d_in[2];
    const float* qkv_w  = (const float*)d_in[3];
    const float* qkv_b  = (const float*)d_in[4];
    const float* proj_w = (const float*)d_in[5];
    const float* proj_b = (const float*)d_in[6];
    float* out = (float*)d_out;

    void* p;
    cudaGetSymbolAddress(&p, g_xn);   float* xn   = (float*)p;
    cudaGetSymbolAddress(&p, g_qkvT); float* qkvT = (float*)p;
    cudaGetSymbolAddress(&p, g_xnTh); __half* xnTh = (__half*)p;
    cudaGetSymbolAddress(&p, g_xnTl); __half* xnTl = (__half*)p;
    cudaGetSymbolAddress(&p, g_w1f);  __half* w1f = (__half*)p;
    cudaGetSymbolAddress(&p, g_w2f);  __half* w2f = (__half*)p;
    cudaGetSymbolAddress(&p, g_kh);   __half* kh = (__half*)p;
    cudaGetSymbolAddress(&p, g_kl);   __half* kl = (__half*)p;
    cudaGetSymbolAddress(&p, g_vh);   __half* vh = (__half*)p;
    cudaGetSymbolAddress(&p, g_qTh);  __half* qTh = (__half*)p;
    cudaGetSymbolAddress(&p, g_ch);   __half* ch = (__half*)p;
    cudaGetSymbolAddress(&p, g_cl);   __half* cl = (__half*)p;
    cudaGetSymbolAddress(&p, g_o1h);  __half* o1h = (__half*)p;
    cudaGetSymbolAddress(&p, g_o1l);  __half* o1l = (__half*)p;

    constexpr int SM4 = (64 + 2 * 128) * 64 * 3;  // 61440 (NWT4)
    constexpr int SM2 = (64 + 2 * 64) * 64 * 3;   // 36864 (NWT2)
    cudaFuncSetAttribute(gemmf16<4, 3>, cudaFuncAttributeMaxDynamicSharedMemorySize, SM4);
    cudaFuncSetAttribute(gemmf16<2, 0>, cudaFuncAttributeMaxDynamicSharedMemorySize, SM2);
    cudaFuncSetAttribute(gemmf16<4, 2>, cudaFuncAttributeMaxDynamicSharedMemorySize, SM4);

    // 0) weight planes (hi only)
    conv_f16h_kernel<<<(C3 * CH / 8 + 255) / 256, 256>>>(qkv_w, w1f, C3 * CH / 8);
    conv_f16h_kernel<<<(CH * CH / 8 + 255) / 256, 256>>>(proj_w, w2f, CH * CH / 8);

    // 1) GroupNorm
    gn_kernel<<<BATCH * GRP, 512>>>(x, gn_w, gn_b);

    // 2) GEMM1 (EP3): q,k -> fp32 qkvT; v -> fp16 hi plane. M=1536 N=1024 K=512
    gemmf16<4, 3><<<dim3(NTOK / 128, C3 / 64, BATCH), 256, SM4>>>(
        w1f, xnTh, xnTl, qkvT, vh, nullptr,
        CH, CH, CH, NTOK,
        0LL, (long long)NTOK * CH, (long long)C3 * NTOK, (long long)CH * NTOK,
        qkv_b, nullptr);

    // 3) softmaxes
    ksoftmax_kernel<<<BATCH * 32, 256>>>();
    qsoftmax_kernel<<<BATCH * 16, 256>>>();

    // 4) GEMM2 (EP0): ctx[d,c] = sum_n v[d,n]*k[c,n]. M=512 N=512 K=1024
    gemmf16<2, 0><<<dim3(CH / 64, CH / 64, BATCH), 256, SM2>>>(
        vh, kh, kl, nullptr, ch, cl,
        NTOK, NTOK, NTOK, CH,
        (long long)CH * NTOK, (long long)CH * NTOK, 0LL, (long long)CH * CH,
        nullptr, nullptr);

    // 5) GEMM3 (EP0): out1[n,d] = sum_c qT[n,c]*ctx[d,c]. M=1024 N=512 K=512
    gemmf16<2, 0><<<dim3(CH / 64, NTOK / 64, BATCH), 256, SM2>>>(
        qTh, ch, cl, nullptr, o1h, o1l,
        CH, CH, CH, CH,
        (long long)NTOK * CH, (long long)CH * CH, 0LL, (long long)NTOK * CH,
        nullptr, nullptr);

    // 6) GEMM4 (EP2): out[d,n] = proj(out1) + b + xn. M=512 N=1024 K=512
    gemmf16<4, 2><<<dim3(NTOK / 128, CH / 64, BATCH), 256, SM4>>>(
        w2f, o1h, o1l, out, nullptr, nullptr,
        CH, CH, CH, NTOK,
        0LL, (long long)NTOK * CH, (long long)CH * NTOK, 0LL,
        proj_b, xn);
}

// round 9
// speedup vs baseline: 4.2803x; 1.4812x over previous
#include <cuda_runtime.h>
#include <cuda_fp16.h>
#include <cstdint>

#define BATCH 8
#define CH    512
#define NTOK  1024
#define C3    1536
#define GRP   8
#define CPG   64
#define GSIZE 65536

// ---------------- scratch (device globals) ----------------
__device__ float g_xn  [BATCH * CH * NTOK];            // fp32 residual [B,C,N]
__device__ float g_qkvT[BATCH * C3 * NTOK];            // fp32 GEMM1 out (q,k rows)
__device__ __half g_xnTh[BATCH * NTOK * CH];           // xn^T fp16 [B,N,C]
__device__ __half g_w1f[C3 * CH];                      // w1 fp16
__device__ __half g_w2f[CH * CH];                      // w2 fp16
__device__ __half g_kh[BATCH * CH * NTOK];             // k fp16 [C,N]
__device__ __half g_vh[BATCH * CH * NTOK];             // v fp16 [C,N]
__device__ __half g_qTh[BATCH * NTOK * CH];            // qT fp16 [N,C]
__device__ __half g_ch[BATCH * CH * CH];               // ctx fp16 [d,c]
__device__ __half g_o1h[BATCH * NTOK * CH];            // out1 fp16 [n,d]

// ---------------- helpers ----------------
__device__ __forceinline__ uint32_t smem_u32(const void* p) {
    uint32_t a;
    asm("{ .reg .u64 t; cvta.to.shared.u64 t, %1; cvt.u32.u64 %0, t; }" : "=r"(a) : "l"(p));
    return a;
}
__device__ __forceinline__ void mmaf16(float* c, uint32_t a0, uint32_t a1,
                                       uint32_t a2, uint32_t a3,
                                       uint32_t b0, uint32_t b1) {
    asm volatile(
        "mma.sync.aligned.m16n8k16.row.col.f32.f16.f16.f32 "
        "{%0,%1,%2,%3},{%4,%5,%6,%7},{%8,%9},{%0,%1,%2,%3};"
        : "+f"(c[0]), "+f"(c[1]), "+f"(c[2]), "+f"(c[3])
        : "r"(a0), "r"(a1), "r"(a2), "r"(a3), "r"(b0), "r"(b1));
}
__device__ __forceinline__ void ldm4(uint32_t& r0, uint32_t& r1, uint32_t& r2,
                                     uint32_t& r3, uint32_t a) {
    asm volatile("ldmatrix.sync.aligned.m8n8.x4.shared.b16 {%0,%1,%2,%3}, [%4];"
                 : "=r"(r0), "=r"(r1), "=r"(r2), "=r"(r3) : "r"(a));
}
#define CPA16(d, s) asm volatile("cp.async.cg.shared.global [%0], [%1], 16;" :: "r"(d), "l"(s))
#define CPCOMMIT()  asm volatile("cp.async.commit_group;")
#define CPWAIT1()   asm volatile("cp.async.wait_group 1;" ::: "memory")
#define CPWAIT0()   asm volatile("cp.async.wait_group 0;" ::: "memory")

// swizzled byte offset within a plane: row r (64B rows), 16B chunk c
__device__ __forceinline__ uint32_t swz(int r, int c) {
    return (uint32_t)(r * 64 + ((c ^ ((r >> 1) & 3)) << 4));
}

// ---------------------------------------------------------------------------
// fp16 single-pass tensor-core GEMM, 3-stage cp.async pipeline, swizzled smem.
// D[64 x 128] = sum_k A(m,k)*B(n,k).
// EP 0: fp16 plane out, no bias (ctx, out1).
// EP 2: fp32 + bias[m] + resid[m*ldc+n] (final).
// EP 3: m0 < 1024 -> fp32 + bias (q,k); m0 >= 1024 -> fp16 plane + bias (v).
// 256 threads, 8 warps (2 x 4), warp tile 32 x 32, 4 CTAs/SM.
// ---------------------------------------------------------------------------
template <int EP>
__global__ __launch_bounds__(256, 4) void gemmf16(
    const __half* __restrict__ Ah, const __half* __restrict__ Bh,
    float* __restrict__ C, __half* __restrict__ Ch,
    int K, int lda, int ldb, int ldc,
    long long sA, long long sB, long long sC, long long sCp,
    const float* __restrict__ bias, const float* __restrict__ resid)
{
    constexpr int BM = 64, BN = 128, NWT = 4;
    constexpr int BOB = BM * 64;               // B plane byte offset in stage
    constexpr int SSB = (BM + BN) * 64;        // stage bytes = 12288

    extern __shared__ __align__(128) __half smbuf[];
    const uint32_t su = smem_u32(smbuf);
    const int tid = threadIdx.x;
    const int bz = blockIdx.z;
    Ah += (size_t)bz * sA;
    Bh += (size_t)bz * sB;
    const int m0 = blockIdx.y * BM, n0 = blockIdx.x * BN;

    const int lane = tid & 31, wid = tid >> 5;
    const int g = lane >> 2, tg = lane & 3;
    const int wm = (wid & 1) * 32, wn = (wid >> 1) * 32;
    const int lr = lane & 15, lchunk = lane >> 4;

    float acc[2][NWT][4];
#pragma unroll
    for (int i = 0; i < 2; i++)
#pragma unroll
        for (int j = 0; j < NWT; j++)
#pragma unroll
            for (int q = 0; q < 4; q++) acc[i][j][q] = 0.f;

    auto fill = [&](int st, int k0) {
        uint32_t base = su + (uint32_t)(st * SSB);
        {   // A: 64 rows x 4 chunks = 256 loads
            int row = tid >> 2, ch = tid & 3;
            CPA16(base + swz(row, ch), Ah + (size_t)(m0 + row) * lda + k0 + ch * 8);
        }
#pragma unroll
        for (int i = 0; i < 2; i++) {   // B: 128 rows x 4 chunks = 512 loads
            int idx = tid + 256 * i;
            int row = idx >> 2, ch = idx & 3;
            CPA16(base + BOB + swz(row, ch), Bh + (size_t)(n0 + row) * ldb + k0 + ch * 8);
        }
        CPCOMMIT();
    };

    const int NC = K / 32;
    fill(0, 0);
    fill(1, 32);

    int st = 0;
    for (int c = 0; c < NC; c++) {
        if (c + 1 < NC) { CPWAIT1(); } else { CPWAIT0(); }
        __syncthreads();
        if (c + 2 < NC) {
            int ns = st + 2; if (ns >= 3) ns -= 3;
            fill(ns, (c + 2) * 32);
        }
        const uint32_t sb = su + (uint32_t)(st * SSB);

#pragma unroll
        for (int ks = 0; ks < 32; ks += 16) {
            const int kc = (ks >> 3) + lchunk;
            uint32_t Bf[2 * NWT];
#pragma unroll
            for (int pr = 0; pr < 2; pr++) {
                int r = wn + pr * 16 + lr;
                ldm4(Bf[pr * 4 + 0], Bf[pr * 4 + 1], Bf[pr * 4 + 2], Bf[pr * 4 + 3],
                     sb + BOB + swz(r, kc));
            }
            uint32_t Af[2][4];
#pragma unroll
            for (int mt = 0; mt < 2; mt++) {
                int r = wm + mt * 16 + lr;
                ldm4(Af[mt][0], Af[mt][1], Af[mt][2], Af[mt][3], sb + swz(r, kc));
            }
#pragma unroll
            for (int mt = 0; mt < 2; mt++)
#pragma unroll
                for (int nt = 0; nt < NWT; nt++) {
                    int i0 = (nt >> 1) * 4 + (nt & 1);
                    mmaf16(acc[mt][nt], Af[mt][0], Af[mt][1], Af[mt][2], Af[mt][3],
                           Bf[i0], Bf[i0 + 2]);
                }
        }
        if (++st == 3) st = 0;
    }

    // ---- epilogue ----
    const bool planes = (EP == 0) || (EP == 3 && m0 >= 2 * CH);
    if (planes) {
        __half* Chp = Ch + (size_t)bz * sCp;
        const int mb = (EP == 3) ? 2 * CH : 0;
#pragma unroll
        for (int mt = 0; mt < 2; mt++) {
            int m = m0 + wm + mt * 16 + g;
            float bv0 = (EP == 3) ? bias[m] : 0.f;
            float bv1 = (EP == 3) ? bias[m + 8] : 0.f;
#pragma unroll
            for (int nt = 0; nt < NWT; nt++) {
                int n = n0 + wn + nt * 8 + tg * 2;
                float* a = acc[mt][nt];
                size_t i0 = (size_t)(m - mb) * ldc + n;
                size_t i1 = (size_t)(m - mb + 8) * ldc + n;
                *reinterpret_cast<__half2*>(Chp + i0) =
                    __half2(__float2half_rn(a[0] + bv0), __float2half_rn(a[1] + bv0));
                *reinterpret_cast<__half2*>(Chp + i1) =
                    __half2(__float2half_rn(a[2] + bv1), __float2half_rn(a[3] + bv1));
            }
        }
    } else {
        float* Cp = C + (size_t)bz * sC;
        const float* R = (EP == 2) ? (resid + (size_t)bz * sC) : nullptr;
#pragma unroll
        for (int mt = 0; mt < 2; mt++) {
            int m = m0 + wm + mt * 16 + g;
            float bv0 = bias[m], bv1 = bias[m + 8];
#pragma unroll
            for (int nt = 0; nt < NWT; nt++) {
                int n = n0 + wn + nt * 8 + tg * 2;
                float* a = acc[mt][nt];
                size_t i0 = (size_t)m * ldc + n;
                size_t i1 = (size_t)(m + 8) * ldc + n;
                float2 o0, o1;
                o0.x = a[0] + bv0; o0.y = a[1] + bv0;
                o1.x = a[2] + bv1; o1.y = a[3] + bv1;
                if (EP == 2) {
                    float2 r0 = *reinterpret_cast<const float2*>(R + i0);
                    float2 r1 = *reinterpret_cast<const float2*>(R + i1);
                    o0.x += r0.x; o0.y += r0.y; o1.x += r1.x; o1.y += r1.y;
                }
                *reinterpret_cast<float2*>(Cp + i0) = o0;
                *reinterpret_cast<float2*>(Cp + i1) = o1;
            }
        }
    }
}

// ---------------------------------------------------------------------------
// GroupNorm: block per (b,g). fp32 residual + transposed fp16 plane.
// ---------------------------------------------------------------------------
__global__ __launch_bounds__(512) void gn_kernel(const float* __restrict__ x,
                                                 const float* __restrict__ gamma,
                                                 const float* __restrict__ beta) {
    int b = blockIdx.x >> 3, g = blockIdx.x & 7;
    size_t off = ((size_t)b * CH + (size_t)g * CPG) * NTOK;
    const float4* xp = reinterpret_cast<const float4*>(x + off);
    float4* gp = reinterpret_cast<float4*>(g_xn + off);
    int t = threadIdx.x;

    __shared__ float rs[512], rq[512];
    float s = 0.f, sq = 0.f;
    for (int i = t; i < GSIZE / 4; i += 512) {
        float4 v = xp[i];
        s  += v.x + v.y + v.z + v.w;
        sq += v.x * v.x + v.y * v.y + v.z * v.z + v.w * v.w;
    }
    rs[t] = s; rq[t] = sq;
    __syncthreads();
    for (int o = 256; o >= 1; o >>= 1) {
        if (t < o) { rs[t] += rs[t + o]; rq[t] += rq[t + o]; }
        __syncthreads();
    }
    float mean = rs[0] * (1.f / GSIZE);
    float var  = rq[0] * (1.f / GSIZE) - mean * mean;
    float rstd = rsqrtf(var + 1e-5f);

    __shared__ __half sh[64][72];
    int c = t >> 3, j0 = (t & 7) * 8;
    float gm = gamma[g * CPG + c] * rstd;
    float bt = beta[g * CPG + c] - mean * gm;
    int nl = t >> 3, chn = t & 7;

    for (int tn = 0; tn < 16; tn++) {
        int base = c * 256 + tn * 16 + (t & 7) * 2;
        float4 v0 = xp[base], v1 = xp[base + 1];
        float y[8] = { v0.x * gm + bt, v0.y * gm + bt, v0.z * gm + bt, v0.w * gm + bt,
                       v1.x * gm + bt, v1.y * gm + bt, v1.z * gm + bt, v1.w * gm + bt };
        float4 w0, w1;
        w0.x = y[0]; w0.y = y[1]; w0.z = y[2]; w0.w = y[3];
        w1.x = y[4]; w1.y = y[5]; w1.z = y[6]; w1.w = y[7];
        gp[base] = w0; gp[base + 1] = w1;
#pragma unroll
        for (int i = 0; i < 8; i++)
            sh[j0 + i][c] = __float2half_rn(y[i]);
        __syncthreads();
        size_t dst = ((size_t)b * NTOK + tn * 64 + nl) * CH + g * CPG + chn * 8;
        *reinterpret_cast<uint4*>(&g_xnTh[dst]) = *reinterpret_cast<uint4*>(&sh[nl][chn * 8]);
        __syncthreads();
    }
}

// ---------------------------------------------------------------------------
// Weight convert fp32 -> fp16
// ---------------------------------------------------------------------------
__global__ void conv_f16h_kernel(const float* __restrict__ src, __half* __restrict__ h, int n8) {
    int i = blockIdx.x * 256 + threadIdx.x;
    if (i >= n8) return;
    const float4* s = reinterpret_cast<const float4*>(src) + i * 2;
    float4 v0 = s[0], v1 = s[1];
    __half hh[8];
    hh[0] = __float2half_rn(v0.x); hh[1] = __float2half_rn(v0.y);
    hh[2] = __float2half_rn(v0.z); hh[3] = __float2half_rn(v0.w);
    hh[4] = __float2half_rn(v1.x); hh[5] = __float2half_rn(v1.y);
    hh[6] = __float2half_rn(v1.z); hh[7] = __float2half_rn(v1.w);
    *reinterpret_cast<uint4*>(h + (size_t)i * 8) = *reinterpret_cast<uint4*>(hh);
}

// ---------------------------------------------------------------------------
// k softmax over c per (b,n); writes fp16 plane [C,N].
// ---------------------------------------------------------------------------
__global__ __launch_bounds__(256) void ksoftmax_kernel() {
    int b = blockIdx.x >> 5;
    int n0 = (blockIdx.x & 31) * 32;
    const float* base = g_qkvT + (size_t)b * C3 * NTOK + (size_t)CH * NTOK + n0;
    __half* kh = g_kh + (size_t)b * CH * NTOK + n0;
    int lane = threadIdx.x & 31, j = threadIdx.x >> 5;

    float mx = -1e30f, sum = 0.f;
    for (int i = 0; i < 64; i++) {
        float v = base[(size_t)(j * 64 + i) * NTOK + lane];
        float nm = fmaxf(mx, v);
        sum = sum * __expf(mx - nm) + __expf(v - nm);
        mx = nm;
    }
    __shared__ float sM[8][32], sS[8][32];
    sM[j][lane] = mx; sS[j][lane] = sum;
    __syncthreads();
    if (j == 0) {
        float M = sM[0][lane], S = sS[0][lane];
#pragma unroll
        for (int t = 1; t < 8; t++) {
            float m2 = sM[t][lane], s2 = sS[t][lane];
            float nm = fmaxf(M, m2);
            S = S * __expf(M - nm) + s2 * __expf(m2 - nm);
            M = nm;
        }
        sM[0][lane] = M; sS[0][lane] = 1.f / S;
    }
    __syncthreads();
    float M = sM[0][lane], inv = sS[0][lane];
    for (int i = 0; i < 64; i++) {
        size_t idx = (size_t)(j * 64 + i) * NTOK + lane;
        kh[idx] = __float2half_rn(__expf(base[idx] - M) * inv);
    }
}

// ---------------------------------------------------------------------------
// q softmax over n per (b,c); writes TRANSPOSED fp16 plane qT [N,C].
// ---------------------------------------------------------------------------
__global__ __launch_bounds__(256) void qsoftmax_kernel() {
    int b = blockIdx.x >> 4, c0 = (blockIdx.x & 15) * 32;
    const float* base = g_qkvT + (size_t)b * C3 * NTOK;
    int t = threadIdx.x;
    int cr = t >> 3, sub = t & 7;
    const float4* rp = reinterpret_cast<const float4*>(
        base + (size_t)(c0 + cr) * NTOK + sub * 128);

    float mx = -1e30f, sum = 0.f;
#pragma unroll
    for (int i = 0; i < 32; i++) {
        float4 v = rp[i];
        float m4 = fmaxf(fmaxf(v.x, v.y), fmaxf(v.z, v.w));
        float nm = fmaxf(mx, m4);
        sum = sum * __expf(mx - nm) + __expf(v.x - nm) + __expf(v.y - nm)
            + __expf(v.z - nm) + __expf(v.w - nm);
        mx = nm;
    }
#pragma unroll
    for (int o = 4; o >= 1; o >>= 1) {
        float m2 = __shfl_xor_sync(0xFFFFFFFFu, mx, o);
        float s2 = __shfl_xor_sync(0xFFFFFFFFu, sum, o);
        float nm = fmaxf(mx, m2);
        sum = sum * __expf(mx - nm) + s2 * __expf(m2 - nm);
        mx = nm;
    }
    __shared__ float sM[32], sI[32];
    if (sub == 0) { sM[cr] = mx; sI[cr] = 1.f / sum; }
    __syncthreads();
    float M = sM[cr], inv = sI[cr];

    __shared__ __half th[64][40];
    int nl = t >> 2, chn = t & 3;
    for (int tn = 0; tn < 16; tn++) {
        const float4* sp = reinterpret_cast<const float4*>(
            base + (size_t)(c0 + cr) * NTOK + tn * 64 + sub * 8);
        float4 v0 = sp[0], v1 = sp[1];
        float e[8] = { __expf(v0.x - M) * inv, __expf(v0.y - M) * inv,
                       __expf(v0.z - M) * inv, __expf(v0.w - M) * inv,
                       __expf(v1.x - M) * inv, __expf(v1.y - M) * inv,
                       __expf(v1.z - M) * inv, __expf(v1.w - M) * inv };
#pragma unroll
        for (int i = 0; i < 8; i++)
            th[sub * 8 + i][cr] = __float2half_rn(e[i]);
        __syncthreads();
        size_t dst = ((size_t)b * NTOK + tn * 64 + nl) * CH + c0 + chn * 8;
        *reinterpret_cast<uint4*>(&g_qTh[dst]) = *reinterpret_cast<uint4*>(&th[nl][chn * 8]);
        __syncthreads();
    }
}

// ---------------------------------------------------------------------------
// Launch
// ---------------------------------------------------------------------------
extern "C" void kernel_launch(void* const* d_in, const int* in_sizes, int n_in,
                              void* d_out, int out_size) {
    const float* x      = (const float*)d_in[0];
    const float* gn_w   = (const float*)d_in[1];
    const float* gn_b   = (const float*)d_in[2];
    const float* qkv_w  = (const float*)d_in[3];
    const float* qkv_b  = (const float*)d_in[4];
    const float* proj_w = (const float*)d_in[5];
    const float* proj_b = (const float*)d_in[6];
    float* out = (float*)d_out;

    void* p;
    cudaGetSymbolAddress(&p, g_xn);   float* xn   = (float*)p;
    cudaGetSymbolAddress(&p, g_qkvT); float* qkvT = (float*)p;
    cudaGetSymbolAddress(&p, g_xnTh); __half* xnTh = (__half*)p;
    cudaGetSymbolAddress(&p, g_w1f);  __half* w1f = (__half*)p;
    cudaGetSymbolAddress(&p, g_w2f);  __half* w2f = (__half*)p;
    cudaGetSymbolAddress(&p, g_kh);   __half* kh = (__half*)p;
    cudaGetSymbolAddress(&p, g_vh);   __half* vh = (__half*)p;
    cudaGetSymbolAddress(&p, g_qTh);  __half* qTh = (__half*)p;
    cudaGetSymbolAddress(&p, g_ch);   __half* ch = (__half*)p;
    cudaGetSymbolAddress(&p, g_o1h);  __half* o1h = (__half*)p;

    constexpr int SMB = (64 + 128) * 64 * 3;   // 36864
    cudaFuncSetAttribute(gemmf16<3>, cudaFuncAttributeMaxDynamicSharedMemorySize, SMB);
    cudaFuncSetAttribute(gemmf16<0>, cudaFuncAttributeMaxDynamicSharedMemorySize, SMB);
    cudaFuncSetAttribute(gemmf16<2>, cudaFuncAttributeMaxDynamicSharedMemorySize, SMB);

    // 0) weight fp16
    conv_f16h_kernel<<<(C3 * CH / 8 + 255) / 256, 256>>>(qkv_w, w1f, C3 * CH / 8);
    conv_f16h_kernel<<<(CH * CH / 8 + 255) / 256, 256>>>(proj_w, w2f, CH * CH / 8);

    // 1) GroupNorm
    gn_kernel<<<BATCH * GRP, 512>>>(x, gn_w, gn_b);

    // 2) GEMM1 (EP3): q,k -> fp32 qkvT; v -> fp16 plane. M=1536 N=1024 K=512
    gemmf16<3><<<dim3(NTOK / 128, C3 / 64, BATCH), 256, SMB>>>(
        w1f, xnTh, qkvT, vh,
        CH, CH, CH, NTOK,
        0LL, (long long)NTOK * CH, (long long)C3 * NTOK, (long long)CH * NTOK,
        qkv_b, nullptr);

    // 3) softmaxes
    ksoftmax_kernel<<<BATCH * 32, 256>>>();
    qsoftmax_kernel<<<BATCH * 16, 256>>>();

    // 4) GEMM2 (EP0): ctx[d,c] = sum_n v[d,n]*k[c,n]. M=512 N=512 K=1024
    gemmf16<0><<<dim3(CH / 128, CH / 64, BATCH), 256, SMB>>>(
        vh, kh, nullptr, ch,
        NTOK, NTOK, NTOK, CH,
        (long long)CH * NTOK, (long long)CH * NTOK, 0LL, (long long)CH * CH,
        nullptr, nullptr);

    // 5) GEMM3 (EP0): out1[n,d] = sum_c qT[n,c]*ctx[d,c]. M=1024 N=512 K=512
    gemmf16<0><<<dim3(CH / 128, NTOK / 64, BATCH), 256, SMB>>>(
        qTh, ch, nullptr, o1h,
        CH, CH, CH, CH,
        (long long)NTOK * CH, (long long)CH * CH, 0LL, (long long)NTOK * CH,
        nullptr, nullptr);

    // 6) GEMM4 (EP2): out[d,n] = proj(out1) + b + xn. M=512 N=1024 K=512
    gemmf16<2><<<dim3(NTOK / 128, CH / 64, BATCH), 256, SMB>>>(
        w2f, o1h, out, nullptr,
        CH, CH, CH, NTOK,
        0LL, (long long)NTOK * CH, (long long)CH * NTOK, 0LL,
        proj_b, xn);
}

// round 10
// speedup vs baseline: 4.3635x; 1.0194x over previous
#include <cuda_runtime.h>
#include <cuda_fp16.h>
#include <cstdint>

#define BATCH 8
#define CH    512
#define NTOK  1024
#define C3    1536
#define GRP   8
#define CPG   64
#define GSIZE 65536

// ---------------- scratch (device globals) ----------------
__device__ float g_xn  [BATCH * CH * NTOK];            // fp32 residual [B,C,N]
__device__ float g_qkvT[BATCH * C3 * NTOK];            // fp32 GEMM1 out (q,k rows)
__device__ __half g_xnTh[BATCH * NTOK * CH];           // xn^T fp16 [B,N,C]
__device__ __half g_w1f[C3 * CH];                      // w1 fp16
__device__ __half g_w2f[CH * CH];                      // w2 fp16
__device__ __half g_kh[BATCH * CH * NTOK];             // k fp16 [C,N]
__device__ __half g_vh[BATCH * CH * NTOK];             // v fp16 [C,N]
__device__ __half g_qTh[BATCH * NTOK * CH];            // qT fp16 [N,C]
__device__ __half g_ch[BATCH * CH * CH];               // ctx fp16 [d,c]
__device__ __half g_o1h[BATCH * NTOK * CH];            // out1 fp16 [n,d]

// ---------------- helpers ----------------
__device__ __forceinline__ uint32_t smem_u32(const void* p) {
    uint32_t a;
    asm("{ .reg .u64 t; cvta.to.shared.u64 t, %1; cvt.u32.u64 %0, t; }" : "=r"(a) : "l"(p));
    return a;
}
__device__ __forceinline__ void mmaf16(float* c, uint32_t a0, uint32_t a1,
                                       uint32_t a2, uint32_t a3,
                                       uint32_t b0, uint32_t b1) {
    asm volatile(
        "mma.sync.aligned.m16n8k16.row.col.f32.f16.f16.f32 "
        "{%0,%1,%2,%3},{%4,%5,%6,%7},{%8,%9},{%0,%1,%2,%3};"
        : "+f"(c[0]), "+f"(c[1]), "+f"(c[2]), "+f"(c[3])
        : "r"(a0), "r"(a1), "r"(a2), "r"(a3), "r"(b0), "r"(b1));
}
__device__ __forceinline__ void ldm4(uint32_t& r0, uint32_t& r1, uint32_t& r2,
                                     uint32_t& r3, uint32_t a) {
    asm volatile("ldmatrix.sync.aligned.m8n8.x4.shared.b16 {%0,%1,%2,%3}, [%4];"
                 : "=r"(r0), "=r"(r1), "=r"(r2), "=r"(r3) : "r"(a));
}
#define CPA16(d, s) asm volatile("cp.async.cg.shared.global [%0], [%1], 16;" :: "r"(d), "l"(s))
#define CPCOMMIT()  asm volatile("cp.async.commit_group;")
#define CPWAIT1()   asm volatile("cp.async.wait_group 1;" ::: "memory")
#define CPWAIT0()   asm volatile("cp.async.wait_group 0;" ::: "memory")

// swizzled byte offset within a plane: row r (64B rows), 16B chunk c
__device__ __forceinline__ uint32_t swz(int r, int c) {
    return (uint32_t)(r * 64 + ((c ^ ((r >> 1) & 3)) << 4));
}

// ---------------------------------------------------------------------------
// fp16 single-pass tensor-core GEMM, 3-stage cp.async pipeline, swizzled smem.
// D[BM x 128] = sum_k A(m,k)*B(n,k), BM = 64*MWT.
// 8 warps (2 x 4): warp tile (32*MWT) x 32.  MWT=1: 4 CTAs/SM; MWT=2: 2 CTAs/SM.
// EP 0: fp16 plane out, no bias.  EP 2: fp32 + bias[m] + resid.
// EP 3: m0 < 1024 -> fp32 + bias; m0 >= 1024 -> fp16 plane + bias (v).
// ---------------------------------------------------------------------------
template <int MWT, int EP>
__global__ __launch_bounds__(256, (MWT == 1 ? 4 : 2)) void gemmf16(
    const __half* __restrict__ Ah, const __half* __restrict__ Bh,
    float* __restrict__ C, __half* __restrict__ Ch,
    int K, int lda, int ldb, int ldc,
    long long sA, long long sB, long long sC, long long sCp,
    const float* __restrict__ bias, const float* __restrict__ resid)
{
    constexpr int BM = 64 * MWT, BN = 128;
    constexpr int NMT = 2 * MWT;               // 16-row A tiles per warp
    constexpr int BOB = BM * 64;                // B plane byte offset in stage
    constexpr int SSB = (BM + BN) * 64;         // stage bytes

    extern __shared__ __align__(128) __half smbuf[];
    const uint32_t su = smem_u32(smbuf);
    const int tid = threadIdx.x;
    const int bz = blockIdx.z;
    Ah += (size_t)bz * sA;
    Bh += (size_t)bz * sB;
    const int m0 = blockIdx.y * BM, n0 = blockIdx.x * BN;

    const int lane = tid & 31, wid = tid >> 5;
    const int g = lane >> 2, tg = lane & 3;
    const int wm = (wid & 1) * 32 * MWT, wn = (wid >> 1) * 32;
    const int lr = lane & 15, lchunk = lane >> 4;

    float acc[NMT][4][4];
#pragma unroll
    for (int i = 0; i < NMT; i++)
#pragma unroll
        for (int j = 0; j < 4; j++)
#pragma unroll
            for (int q = 0; q < 4; q++) acc[i][j][q] = 0.f;

    auto fill = [&](int st, int k0) {
        uint32_t base = su + (uint32_t)(st * SSB);
#pragma unroll
        for (int i = 0; i < MWT; i++) {   // A: BM rows x 4 chunks
            int idx = tid + 256 * i;
            int row = idx >> 2, ch = idx & 3;
            CPA16(base + swz(row, ch), Ah + (size_t)(m0 + row) * lda + k0 + ch * 8);
        }
#pragma unroll
        for (int i = 0; i < 2; i++) {     // B: 128 rows x 4 chunks = 512 loads
            int idx = tid + 256 * i;
            int row = idx >> 2, ch = idx & 3;
            CPA16(base + BOB + swz(row, ch), Bh + (size_t)(n0 + row) * ldb + k0 + ch * 8);
        }
        CPCOMMIT();
    };

    const int NC = K / 32;
    fill(0, 0);
    fill(1, 32);

    int st = 0;
    for (int c = 0; c < NC; c++) {
        if (c + 1 < NC) { CPWAIT1(); } else { CPWAIT0(); }
        __syncthreads();
        if (c + 2 < NC) {
            int ns = st + 2; if (ns >= 3) ns -= 3;
            fill(ns, (c + 2) * 32);
        }
        const uint32_t sb = su + (uint32_t)(st * SSB);

#pragma unroll
        for (int ks = 0; ks < 32; ks += 16) {
            const int kc = (ks >> 3) + lchunk;
            uint32_t Bf[8];
#pragma unroll
            for (int pr = 0; pr < 2; pr++) {
                int r = wn + pr * 16 + lr;
                ldm4(Bf[pr * 4 + 0], Bf[pr * 4 + 1], Bf[pr * 4 + 2], Bf[pr * 4 + 3],
                     sb + BOB + swz(r, kc));
            }
            uint32_t Af[NMT][4];
#pragma unroll
            for (int mt = 0; mt < NMT; mt++) {
                int r = wm + mt * 16 + lr;
                ldm4(Af[mt][0], Af[mt][1], Af[mt][2], Af[mt][3], sb + swz(r, kc));
            }
#pragma unroll
            for (int mt = 0; mt < NMT; mt++)
#pragma unroll
                for (int nt = 0; nt < 4; nt++) {
                    int i0 = (nt >> 1) * 4 + (nt & 1);
                    mmaf16(acc[mt][nt], Af[mt][0], Af[mt][1], Af[mt][2], Af[mt][3],
                           Bf[i0], Bf[i0 + 2]);
                }
        }
        if (++st == 3) st = 0;
    }

    // ---- epilogue ----
    const bool planes = (EP == 0) || (EP == 3 && m0 >= 2 * CH);
    if (planes) {
        __half* Chp = Ch + (size_t)bz * sCp;
        const int mb = (EP == 3) ? 2 * CH : 0;
#pragma unroll
        for (int mt = 0; mt < NMT; mt++) {
            int m = m0 + wm + mt * 16 + g;
            float bv0 = (EP == 3) ? bias[m] : 0.f;
            float bv1 = (EP == 3) ? bias[m + 8] : 0.f;
#pragma unroll
            for (int nt = 0; nt < 4; nt++) {
                int n = n0 + wn + nt * 8 + tg * 2;
                float* a = acc[mt][nt];
                size_t i0 = (size_t)(m - mb) * ldc + n;
                size_t i1 = (size_t)(m - mb + 8) * ldc + n;
                *reinterpret_cast<__half2*>(Chp + i0) =
                    __half2(__float2half_rn(a[0] + bv0), __float2half_rn(a[1] + bv0));
                *reinterpret_cast<__half2*>(Chp + i1) =
                    __half2(__float2half_rn(a[2] + bv1), __float2half_rn(a[3] + bv1));
            }
        }
    } else {
        float* Cp = C + (size_t)bz * sC;
        const float* R = (EP == 2) ? (resid + (size_t)bz * sC) : nullptr;
#pragma unroll
        for (int mt = 0; mt < NMT; mt++) {
            int m = m0 + wm + mt * 16 + g;
            float bv0 = bias[m], bv1 = bias[m + 8];
#pragma unroll
            for (int nt = 0; nt < 4; nt++) {
                int n = n0 + wn + nt * 8 + tg * 2;
                float* a = acc[mt][nt];
                size_t i0 = (size_t)m * ldc + n;
                size_t i1 = (size_t)(m + 8) * ldc + n;
                float2 o0, o1;
                o0.x = a[0] + bv0; o0.y = a[1] + bv0;
                o1.x = a[2] + bv1; o1.y = a[3] + bv1;
                if (EP == 2) {
                    float2 r0 = *reinterpret_cast<const float2*>(R + i0);
                    float2 r1 = *reinterpret_cast<const float2*>(R + i1);
                    o0.x += r0.x; o0.y += r0.y; o1.x += r1.x; o1.y += r1.y;
                }
                *reinterpret_cast<float2*>(Cp + i0) = o0;
                *reinterpret_cast<float2*>(Cp + i1) = o1;
            }
        }
    }
}

// ---------------------------------------------------------------------------
// GroupNorm: block per (b,g). fp32 residual + transposed fp16 plane.
// ---------------------------------------------------------------------------
__global__ __launch_bounds__(512) void gn_kernel(const float* __restrict__ x,
                                                 const float* __restrict__ gamma,
                                                 const float* __restrict__ beta) {
    int b = blockIdx.x >> 3, g = blockIdx.x & 7;
    size_t off = ((size_t)b * CH + (size_t)g * CPG) * NTOK;
    const float4* xp = reinterpret_cast<const float4*>(x + off);
    float4* gp = reinterpret_cast<float4*>(g_xn + off);
    int t = threadIdx.x;

    __shared__ float rs[512], rq[512];
    float s = 0.f, sq = 0.f;
    for (int i = t; i < GSIZE / 4; i += 512) {
        float4 v = xp[i];
        s  += v.x + v.y + v.z + v.w;
        sq += v.x * v.x + v.y * v.y + v.z * v.z + v.w * v.w;
    }
    rs[t] = s; rq[t] = sq;
    __syncthreads();
    for (int o = 256; o >= 1; o >>= 1) {
        if (t < o) { rs[t] += rs[t + o]; rq[t] += rq[t + o]; }
        __syncthreads();
    }
    float mean = rs[0] * (1.f / GSIZE);
    float var  = rq[0] * (1.f / GSIZE) - mean * mean;
    float rstd = rsqrtf(var + 1e-5f);

    __shared__ __half sh[64][72];
    int c = t >> 3, j0 = (t & 7) * 8;
    float gm = gamma[g * CPG + c] * rstd;
    float bt = beta[g * CPG + c] - mean * gm;
    int nl = t >> 3, chn = t & 7;

    for (int tn = 0; tn < 16; tn++) {
        int base = c * 256 + tn * 16 + (t & 7) * 2;
        float4 v0 = xp[base], v1 = xp[base + 1];
        float y[8] = { v0.x * gm + bt, v0.y * gm + bt, v0.z * gm + bt, v0.w * gm + bt,
                       v1.x * gm + bt, v1.y * gm + bt, v1.z * gm + bt, v1.w * gm + bt };
        float4 w0, w1;
        w0.x = y[0]; w0.y = y[1]; w0.z = y[2]; w0.w = y[3];
        w1.x = y[4]; w1.y = y[5]; w1.z = y[6]; w1.w = y[7];
        gp[base] = w0; gp[base + 1] = w1;
#pragma unroll
        for (int i = 0; i < 8; i++)
            sh[j0 + i][c] = __float2half_rn(y[i]);
        __syncthreads();
        size_t dst = ((size_t)b * NTOK + tn * 64 + nl) * CH + g * CPG + chn * 8;
        *reinterpret_cast<uint4*>(&g_xnTh[dst]) = *reinterpret_cast<uint4*>(&sh[nl][chn * 8]);
        __syncthreads();
    }
}

// ---------------------------------------------------------------------------
// Weight convert: both weights in one launch. n8 = total float4-pairs.
// ---------------------------------------------------------------------------
__global__ void conv_all_kernel(const float* __restrict__ w1, const float* __restrict__ w2) {
    int i = blockIdx.x * 256 + threadIdx.x;
    const int n1 = C3 * CH / 8, n2 = CH * CH / 8;
    if (i >= n1 + n2) return;
    const float* src = (i < n1) ? w1 : w2;
    __half* dst = (i < n1) ? g_w1f : g_w2f;
    int j = (i < n1) ? i : i - n1;
    const float4* s = reinterpret_cast<const float4*>(src) + j * 2;
    float4 v0 = s[0], v1 = s[1];
    __half hh[8];
    hh[0] = __float2half_rn(v0.x); hh[1] = __float2half_rn(v0.y);
    hh[2] = __float2half_rn(v0.z); hh[3] = __float2half_rn(v0.w);
    hh[4] = __float2half_rn(v1.x); hh[5] = __float2half_rn(v1.y);
    hh[6] = __float2half_rn(v1.z); hh[7] = __float2half_rn(v1.w);
    *reinterpret_cast<uint4*>(dst + (size_t)j * 8) = *reinterpret_cast<uint4*>(hh);
}

// ---------------------------------------------------------------------------
// k softmax over c per (b,n); writes fp16 plane [C,N].
// ---------------------------------------------------------------------------
__global__ __launch_bounds__(256) void ksoftmax_kernel() {
    int b = blockIdx.x >> 5;
    int n0 = (blockIdx.x & 31) * 32;
    const float* base = g_qkvT + (size_t)b * C3 * NTOK + (size_t)CH * NTOK + n0;
    __half* kh = g_kh + (size_t)b * CH * NTOK + n0;
    int lane = threadIdx.x & 31, j = threadIdx.x >> 5;

    float mx = -1e30f, sum = 0.f;
    for (int i = 0; i < 64; i++) {
        float v = base[(size_t)(j * 64 + i) * NTOK + lane];
        float nm = fmaxf(mx, v);
        sum = sum * __expf(mx - nm) + __expf(v - nm);
        mx = nm;
    }
    __shared__ float sM[8][32], sS[8][32];
    sM[j][lane] = mx; sS[j][lane] = sum;
    __syncthreads();
    if (j == 0) {
        float M = sM[0][lane], S = sS[0][lane];
#pragma unroll
        for (int t = 1; t < 8; t++) {
            float m2 = sM[t][lane], s2 = sS[t][lane];
            float nm = fmaxf(M, m2);
            S = S * __expf(M - nm) + s2 * __expf(m2 - nm);
            M = nm;
        }
        sM[0][lane] = M; sS[0][lane] = 1.f / S;
    }
    __syncthreads();
    float M = sM[0][lane], inv = sS[0][lane];
    for (int i = 0; i < 64; i++) {
        size_t idx = (size_t)(j * 64 + i) * NTOK + lane;
        kh[idx] = __float2half_rn(__expf(base[idx] - M) * inv);
    }
}

// ---------------------------------------------------------------------------
// q softmax over n per (b,c); writes TRANSPOSED fp16 plane qT [N,C].
// ---------------------------------------------------------------------------
__global__ __launch_bounds__(256) void qsoftmax_kernel() {
    int b = blockIdx.x >> 4, c0 = (blockIdx.x & 15) * 32;
    const float* base = g_qkvT + (size_t)b * C3 * NTOK;
    int t = threadIdx.x;
    int cr = t >> 3, sub = t & 7;
    const float4* rp = reinterpret_cast<const float4*>(
        base + (size_t)(c0 + cr) * NTOK + sub * 128);

    float mx = -1e30f, sum = 0.f;
#pragma unroll
    for (int i = 0; i < 32; i++) {
        float4 v = rp[i];
        float m4 = fmaxf(fmaxf(v.x, v.y), fmaxf(v.z, v.w));
        float nm = fmaxf(mx, m4);
        sum = sum * __expf(mx - nm) + __expf(v.x - nm) + __expf(v.y - nm)
            + __expf(v.z - nm) + __expf(v.w - nm);
        mx = nm;
    }
#pragma unroll
    for (int o = 4; o >= 1; o >>= 1) {
        float m2 = __shfl_xor_sync(0xFFFFFFFFu, mx, o);
        float s2 = __shfl_xor_sync(0xFFFFFFFFu, sum, o);
        float nm = fmaxf(mx, m2);
        sum = sum * __expf(mx - nm) + s2 * __expf(m2 - nm);
        mx = nm;
    }
    __shared__ float sM[32], sI[32];
    if (sub == 0) { sM[cr] = mx; sI[cr] = 1.f / sum; }
    __syncthreads();
    float M = sM[cr], inv = sI[cr];

    __shared__ __half th[64][40];
    int nl = t >> 2, chn = t & 3;
    for (int tn = 0; tn < 16; tn++) {
        const float4* sp = reinterpret_cast<const float4*>(
            base + (size_t)(c0 + cr) * NTOK + tn * 64 + sub * 8);
        float4 v0 = sp[0], v1 = sp[1];
        float e[8] = { __expf(v0.x - M) * inv, __expf(v0.y - M) * inv,
                       __expf(v0.z - M) * inv, __expf(v0.w - M) * inv,
                       __expf(v1.x - M) * inv, __expf(v1.y - M) * inv,
                       __expf(v1.z - M) * inv, __expf(v1.w - M) * inv };
#pragma unroll
        for (int i = 0; i < 8; i++)
            th[sub * 8 + i][cr] = __float2half_rn(e[i]);
        __syncthreads();
        size_t dst = ((size_t)b * NTOK + tn * 64 + nl) * CH + c0 + chn * 8;
        *reinterpret_cast<uint4*>(&g_qTh[dst]) = *reinterpret_cast<uint4*>(&th[nl][chn * 8]);
        __syncthreads();
    }
}

// ---------------------------------------------------------------------------
// Launch
// ---------------------------------------------------------------------------
extern "C" void kernel_launch(void* const* d_in, const int* in_sizes, int n_in,
                              void* d_out, int out_size) {
    const float* x      = (const float*)d_in[0];
    const float* gn_w   = (const float*)d_in[1];
    const float* gn_b   = (const float*)d_in[2];
    const float* qkv_w  = (const float*)d_in[3];
    const float* qkv_b  = (const float*)d_in[4];
    const float* proj_w = (const float*)d_in[5];
    const float* proj_b = (const float*)d_in[6];
    float* out = (float*)d_out;

    void* p;
    cudaGetSymbolAddress(&p, g_xn);   float* xn   = (float*)p;
    cudaGetSymbolAddress(&p, g_qkvT); float* qkvT = (float*)p;
    cudaGetSymbolAddress(&p, g_xnTh); __half* xnTh = (__half*)p;
    cudaGetSymbolAddress(&p, g_w1f);  __half* w1f = (__half*)p;
    cudaGetSymbolAddress(&p, g_w2f);  __half* w2f = (__half*)p;
    cudaGetSymbolAddress(&p, g_kh);   __half* kh = (__half*)p;
    cudaGetSymbolAddress(&p, g_vh);   __half* vh = (__half*)p;
    cudaGetSymbolAddress(&p, g_qTh);  __half* qTh = (__half*)p;
    cudaGetSymbolAddress(&p, g_ch);   __half* ch = (__half*)p;
    cudaGetSymbolAddress(&p, g_o1h);  __half* o1h = (__half*)p;

    constexpr int SMB1 = (64 + 128) * 64 * 3;    // 36864 (MWT=1)
    constexpr int SMB2 = (128 + 128) * 64 * 3;   // 49152 (MWT=2)
    cudaFuncSetAttribute(gemmf16<2, 3>, cudaFuncAttributeMaxDynamicSharedMemorySize, SMB2);
    cudaFuncSetAttribute(gemmf16<1, 0>, cudaFuncAttributeMaxDynamicSharedMemorySize, SMB1);
    cudaFuncSetAttribute(gemmf16<2, 0>, cudaFuncAttributeMaxDynamicSharedMemorySize, SMB2);
    cudaFuncSetAttribute(gemmf16<2, 2>, cudaFuncAttributeMaxDynamicSharedMemorySize, SMB2);

    // 0) weight fp16 (single launch)
    conv_all_kernel<<<((C3 * CH + CH * CH) / 8 + 255) / 256, 256>>>(qkv_w, proj_w);

    // 1) GroupNorm
    gn_kernel<<<BATCH * GRP, 512>>>(x, gn_w, gn_b);

    // 2) GEMM1 (MWT=2, EP3): q,k -> fp32 qkvT; v -> fp16 plane. M=1536 N=1024 K=512
    gemmf16<2, 3><<<dim3(NTOK / 128, C3 / 128, BATCH), 256, SMB2>>>(
        w1f, xnTh, qkvT, vh,
        CH, CH, CH, NTOK,
        0LL, (long long)NTOK * CH, (long long)C3 * NTOK, (long long)CH * NTOK,
        qkv_b, nullptr);

    // 3) softmaxes
    ksoftmax_kernel<<<BATCH * 32, 256>>>();
    qsoftmax_kernel<<<BATCH * 16, 256>>>();

    // 4) GEMM2 (MWT=1, EP0): ctx[d,c] = sum_n v[d,n]*k[c,n]. M=512 N=512 K=1024
    gemmf16<1, 0><<<dim3(CH / 128, CH / 64, BATCH), 256, SMB1>>>(
        vh, kh, nullptr, ch,
        NTOK, NTOK, NTOK, CH,
        (long long)CH * NTOK, (long long)CH * NTOK, 0LL, (long long)CH * CH,
        nullptr, nullptr);

    // 5) GEMM3 (MWT=2, EP0): out1[n,d] = sum_c qT[n,c]*ctx[d,c]. M=1024 N=512 K=512
    gemmf16<2, 0><<<dim3(CH / 128, NTOK / 128, BATCH), 256, SMB2>>>(
        qTh, ch, nullptr, o1h,
        CH, CH, CH, CH,
        (long long)NTOK * CH, (long long)CH * CH, 0LL, (long long)NTOK * CH,
        nullptr, nullptr);

    // 6) GEMM4 (MWT=2, EP2): out[d,n] = proj(out1) + b + xn. M=512 N=1024 K=512
    gemmf16<2, 2><<<dim3(NTOK / 128, CH / 128, BATCH), 256, SMB2>>>(
        w2f, o1h, out, nullptr,
        CH, CH, CH, NTOK,
        0LL, (long long)NTOK * CH, (long long)CH * NTOK, 0LL,
        proj_b, xn);
}

// round 11
// speedup vs baseline: 4.5148x; 1.0347x over previous
#include <cuda_runtime.h>
#include <cuda_fp16.h>
#include <cstdint>

#define BATCH 8
#define CH    512
#define NTOK  1024
#define C3    1536
#define GRP   8
#define CPG   64
#define GSIZE 65536

// ---------------- scratch (device globals) ----------------
__device__ float g_xn  [BATCH * CH * NTOK];            // fp32 residual [B,C,N]
__device__ float g_qkvT[BATCH * C3 * NTOK];            // fp32 GEMM1 out (q,k rows)
__device__ __half g_xnTh[BATCH * NTOK * CH];           // xn^T fp16 [B,N,C]
__device__ __half g_w1f[C3 * CH];                      // w1 fp16
__device__ __half g_w2f[CH * CH];                      // w2 fp16
__device__ __half g_kh[BATCH * CH * NTOK];             // k fp16 [C,N]
__device__ __half g_vh[BATCH * CH * NTOK];             // v fp16 [C,N]
__device__ __half g_qTh[BATCH * NTOK * CH];            // qT fp16 [N,C]
__device__ __half g_ch[BATCH * CH * CH];               // ctx fp16 [d,c]
__device__ __half g_o1h[BATCH * NTOK * CH];            // out1 fp16 [n,d]

// ---------------- helpers ----------------
__device__ __forceinline__ uint32_t smem_u32(const void* p) {
    uint32_t a;
    asm("{ .reg .u64 t; cvta.to.shared.u64 t, %1; cvt.u32.u64 %0, t; }" : "=r"(a) : "l"(p));
    return a;
}
__device__ __forceinline__ void mmaf16(float* c, uint32_t a0, uint32_t a1,
                                       uint32_t a2, uint32_t a3,
                                       uint32_t b0, uint32_t b1) {
    asm volatile(
        "mma.sync.aligned.m16n8k16.row.col.f32.f16.f16.f32 "
        "{%0,%1,%2,%3},{%4,%5,%6,%7},{%8,%9},{%0,%1,%2,%3};"
        : "+f"(c[0]), "+f"(c[1]), "+f"(c[2]), "+f"(c[3])
        : "r"(a0), "r"(a1), "r"(a2), "r"(a3), "r"(b0), "r"(b1));
}
__device__ __forceinline__ void ldm4(uint32_t& r0, uint32_t& r1, uint32_t& r2,
                                     uint32_t& r3, uint32_t a) {
    asm volatile("ldmatrix.sync.aligned.m8n8.x4.shared.b16 {%0,%1,%2,%3}, [%4];"
                 : "=r"(r0), "=r"(r1), "=r"(r2), "=r"(r3) : "r"(a));
}
#define CPA16(d, s) asm volatile("cp.async.cg.shared.global [%0], [%1], 16;" :: "r"(d), "l"(s))
#define CPCOMMIT()  asm volatile("cp.async.commit_group;")
#define CPWAIT1()   asm volatile("cp.async.wait_group 1;" ::: "memory")
#define CPWAIT0()   asm volatile("cp.async.wait_group 0;" ::: "memory")

// swizzled byte offset within a plane: row r (64B rows), 16B chunk c
__device__ __forceinline__ uint32_t swz(int r, int c) {
    return (uint32_t)(r * 64 + ((c ^ ((r >> 1) & 3)) << 4));
}

// ---------------------------------------------------------------------------
// fp16 single-pass tensor-core GEMM, 3-stage cp.async pipeline, swizzled smem.
// D[BM x 128] = sum_k A(m,k)*B(n,k), BM = 64*MWT.
// 8 warps (2 x 4): warp tile (32*MWT) x 32.  MWT=1: 4 CTAs/SM; MWT=2: 2 CTAs/SM.
// EP 0: fp16 plane out, no bias.  EP 2: fp32 + bias[m] + resid.
// EP 3: m0 < 1024 -> fp32 + bias; m0 >= 1024 -> fp16 plane + bias (v).
// ---------------------------------------------------------------------------
template <int MWT, int EP>
__global__ __launch_bounds__(256, (MWT == 1 ? 4 : 2)) void gemmf16(
    const __half* __restrict__ Ah, const __half* __restrict__ Bh,
    float* __restrict__ C, __half* __restrict__ Ch,
    int K, int lda, int ldb, int ldc,
    long long sA, long long sB, long long sC, long long sCp,
    const float* __restrict__ bias, const float* __restrict__ resid)
{
    constexpr int BM = 64 * MWT, BN = 128;
    constexpr int NMT = 2 * MWT;
    constexpr int BOB = BM * 64;
    constexpr int SSB = (BM + BN) * 64;

    extern __shared__ __align__(128) __half smbuf[];
    const uint32_t su = smem_u32(smbuf);
    const int tid = threadIdx.x;
    const int bz = blockIdx.z;
    Ah += (size_t)bz * sA;
    Bh += (size_t)bz * sB;
    const int m0 = blockIdx.y * BM, n0 = blockIdx.x * BN;

    const int lane = tid & 31, wid = tid >> 5;
    const int g = lane >> 2, tg = lane & 3;
    const int wm = (wid & 1) * 32 * MWT, wn = (wid >> 1) * 32;
    const int lr = lane & 15, lchunk = lane >> 4;

    float acc[NMT][4][4];
#pragma unroll
    for (int i = 0; i < NMT; i++)
#pragma unroll
        for (int j = 0; j < 4; j++)
#pragma unroll
            for (int q = 0; q < 4; q++) acc[i][j][q] = 0.f;

    auto fill = [&](int st, int k0) {
        uint32_t base = su + (uint32_t)(st * SSB);
#pragma unroll
        for (int i = 0; i < MWT; i++) {
            int idx = tid + 256 * i;
            int row = idx >> 2, ch = idx & 3;
            CPA16(base + swz(row, ch), Ah + (size_t)(m0 + row) * lda + k0 + ch * 8);
        }
#pragma unroll
        for (int i = 0; i < 2; i++) {
            int idx = tid + 256 * i;
            int row = idx >> 2, ch = idx & 3;
            CPA16(base + BOB + swz(row, ch), Bh + (size_t)(n0 + row) * ldb + k0 + ch * 8);
        }
        CPCOMMIT();
    };

    const int NC = K / 32;
    fill(0, 0);
    fill(1, 32);

    int st = 0;
    for (int c = 0; c < NC; c++) {
        if (c + 1 < NC) { CPWAIT1(); } else { CPWAIT0(); }
        __syncthreads();
        if (c + 2 < NC) {
            int ns = st + 2; if (ns >= 3) ns -= 3;
            fill(ns, (c + 2) * 32);
        }
        const uint32_t sb = su + (uint32_t)(st * SSB);

#pragma unroll
        for (int ks = 0; ks < 32; ks += 16) {
            const int kc = (ks >> 3) + lchunk;
            uint32_t Bf[8];
#pragma unroll
            for (int pr = 0; pr < 2; pr++) {
                int r = wn + pr * 16 + lr;
                ldm4(Bf[pr * 4 + 0], Bf[pr * 4 + 1], Bf[pr * 4 + 2], Bf[pr * 4 + 3],
                     sb + BOB + swz(r, kc));
            }
            uint32_t Af[NMT][4];
#pragma unroll
            for (int mt = 0; mt < NMT; mt++) {
                int r = wm + mt * 16 + lr;
                ldm4(Af[mt][0], Af[mt][1], Af[mt][2], Af[mt][3], sb + swz(r, kc));
            }
#pragma unroll
            for (int mt = 0; mt < NMT; mt++)
#pragma unroll
                for (int nt = 0; nt < 4; nt++) {
                    int i0 = (nt >> 1) * 4 + (nt & 1);
                    mmaf16(acc[mt][nt], Af[mt][0], Af[mt][1], Af[mt][2], Af[mt][3],
                           Bf[i0], Bf[i0 + 2]);
                }
        }
        if (++st == 3) st = 0;
    }

    // ---- epilogue ----
    const bool planes = (EP == 0) || (EP == 3 && m0 >= 2 * CH);
    if (planes) {
        __half* Chp = Ch + (size_t)bz * sCp;
        const int mb = (EP == 3) ? 2 * CH : 0;
#pragma unroll
        for (int mt = 0; mt < NMT; mt++) {
            int m = m0 + wm + mt * 16 + g;
            float bv0 = (EP == 3) ? bias[m] : 0.f;
            float bv1 = (EP == 3) ? bias[m + 8] : 0.f;
#pragma unroll
            for (int nt = 0; nt < 4; nt++) {
                int n = n0 + wn + nt * 8 + tg * 2;
                float* a = acc[mt][nt];
                size_t i0 = (size_t)(m - mb) * ldc + n;
                size_t i1 = (size_t)(m - mb + 8) * ldc + n;
                *reinterpret_cast<__half2*>(Chp + i0) =
                    __half2(__float2half_rn(a[0] + bv0), __float2half_rn(a[1] + bv0));
                *reinterpret_cast<__half2*>(Chp + i1) =
                    __half2(__float2half_rn(a[2] + bv1), __float2half_rn(a[3] + bv1));
            }
        }
    } else {
        float* Cp = C + (size_t)bz * sC;
        const float* R = (EP == 2) ? (resid + (size_t)bz * sC) : nullptr;
#pragma unroll
        for (int mt = 0; mt < NMT; mt++) {
            int m = m0 + wm + mt * 16 + g;
            float bv0 = bias[m], bv1 = bias[m + 8];
#pragma unroll
            for (int nt = 0; nt < 4; nt++) {
                int n = n0 + wn + nt * 8 + tg * 2;
                float* a = acc[mt][nt];
                size_t i0 = (size_t)m * ldc + n;
                size_t i1 = (size_t)(m + 8) * ldc + n;
                float2 o0, o1;
                o0.x = a[0] + bv0; o0.y = a[1] + bv0;
                o1.x = a[2] + bv1; o1.y = a[3] + bv1;
                if (EP == 2) {
                    float2 r0 = *reinterpret_cast<const float2*>(R + i0);
                    float2 r1 = *reinterpret_cast<const float2*>(R + i1);
                    o0.x += r0.x; o0.y += r0.y; o1.x += r1.x; o1.y += r1.y;
                }
                *reinterpret_cast<float2*>(Cp + i0) = o0;
                *reinterpret_cast<float2*>(Cp + i1) = o1;
            }
        }
    }
}

// ---------------------------------------------------------------------------
// GroupNorm: block per (b,g). fp32 residual + transposed fp16 plane.
// ---------------------------------------------------------------------------
__global__ __launch_bounds__(512) void gn_kernel(const float* __restrict__ x,
                                                 const float* __restrict__ gamma,
                                                 const float* __restrict__ beta) {
    int b = blockIdx.x >> 3, g = blockIdx.x & 7;
    size_t off = ((size_t)b * CH + (size_t)g * CPG) * NTOK;
    const float4* xp = reinterpret_cast<const float4*>(x + off);
    float4* gp = reinterpret_cast<float4*>(g_xn + off);
    int t = threadIdx.x;

    __shared__ float rs[512], rq[512];
    float s = 0.f, sq = 0.f;
    for (int i = t; i < GSIZE / 4; i += 512) {
        float4 v = xp[i];
        s  += v.x + v.y + v.z + v.w;
        sq += v.x * v.x + v.y * v.y + v.z * v.z + v.w * v.w;
    }
    rs[t] = s; rq[t] = sq;
    __syncthreads();
    for (int o = 256; o >= 1; o >>= 1) {
        if (t < o) { rs[t] += rs[t + o]; rq[t] += rq[t + o]; }
        __syncthreads();
    }
    float mean = rs[0] * (1.f / GSIZE);
    float var  = rq[0] * (1.f / GSIZE) - mean * mean;
    float rstd = rsqrtf(var + 1e-5f);

    __shared__ __half sh[64][72];
    int c = t >> 3, j0 = (t & 7) * 8;
    float gm = gamma[g * CPG + c] * rstd;
    float bt = beta[g * CPG + c] - mean * gm;
    int nl = t >> 3, chn = t & 7;

    for (int tn = 0; tn < 16; tn++) {
        int base = c * 256 + tn * 16 + (t & 7) * 2;
        float4 v0 = xp[base], v1 = xp[base + 1];
        float y[8] = { v0.x * gm + bt, v0.y * gm + bt, v0.z * gm + bt, v0.w * gm + bt,
                       v1.x * gm + bt, v1.y * gm + bt, v1.z * gm + bt, v1.w * gm + bt };
        float4 w0, w1;
        w0.x = y[0]; w0.y = y[1]; w0.z = y[2]; w0.w = y[3];
        w1.x = y[4]; w1.y = y[5]; w1.z = y[6]; w1.w = y[7];
        gp[base] = w0; gp[base + 1] = w1;
#pragma unroll
        for (int i = 0; i < 8; i++)
            sh[j0 + i][c] = __float2half_rn(y[i]);
        __syncthreads();
        size_t dst = ((size_t)b * NTOK + tn * 64 + nl) * CH + g * CPG + chn * 8;
        *reinterpret_cast<uint4*>(&g_xnTh[dst]) = *reinterpret_cast<uint4*>(&sh[nl][chn * 8]);
        __syncthreads();
    }
}

// ---------------------------------------------------------------------------
// Weight convert: both weights in one launch.
// ---------------------------------------------------------------------------
__global__ void conv_all_kernel(const float* __restrict__ w1, const float* __restrict__ w2) {
    int i = blockIdx.x * 256 + threadIdx.x;
    const int n1 = C3 * CH / 8, n2 = CH * CH / 8;
    if (i >= n1 + n2) return;
    const float* src = (i < n1) ? w1 : w2;
    __half* dst = (i < n1) ? g_w1f : g_w2f;
    int j = (i < n1) ? i : i - n1;
    const float4* s = reinterpret_cast<const float4*>(src) + j * 2;
    float4 v0 = s[0], v1 = s[1];
    __half hh[8];
    hh[0] = __float2half_rn(v0.x); hh[1] = __float2half_rn(v0.y);
    hh[2] = __float2half_rn(v0.z); hh[3] = __float2half_rn(v0.w);
    hh[4] = __float2half_rn(v1.x); hh[5] = __float2half_rn(v1.y);
    hh[6] = __float2half_rn(v1.z); hh[7] = __float2half_rn(v1.w);
    *reinterpret_cast<uint4*>(dst + (size_t)j * 8) = *reinterpret_cast<uint4*>(hh);
}

// ---------------------------------------------------------------------------
// k softmax over c per (b,n): 512 threads, 16 warps x 32 rows. Grid BATCH*32.
// ---------------------------------------------------------------------------
__global__ __launch_bounds__(512) void ksoftmax_kernel() {
    int b = blockIdx.x >> 5;
    int n0 = (blockIdx.x & 31) * 32;
    const float* base = g_qkvT + (size_t)b * C3 * NTOK + (size_t)CH * NTOK + n0;
    __half* kh = g_kh + (size_t)b * CH * NTOK + n0;
    int lane = threadIdx.x & 31, j = threadIdx.x >> 5;   // j in [0,16)

    float mx = -1e30f, sum = 0.f;
    for (int i = 0; i < 32; i++) {
        float v = base[(size_t)(j * 32 + i) * NTOK + lane];
        float nm = fmaxf(mx, v);
        sum = sum * __expf(mx - nm) + __expf(v - nm);
        mx = nm;
    }
    __shared__ float sM[16][32], sS[16][32];
    sM[j][lane] = mx; sS[j][lane] = sum;
    __syncthreads();
    if (j == 0) {
        float M = sM[0][lane], S = sS[0][lane];
#pragma unroll
        for (int t = 1; t < 16; t++) {
            float m2 = sM[t][lane], s2 = sS[t][lane];
            float nm = fmaxf(M, m2);
            S = S * __expf(M - nm) + s2 * __expf(m2 - nm);
            M = nm;
        }
        sM[0][lane] = M; sS[0][lane] = 1.f / S;
    }
    __syncthreads();
    float M = sM[0][lane], inv = sS[0][lane];
    for (int i = 0; i < 32; i++) {
        size_t idx = (size_t)(j * 32 + i) * NTOK + lane;
        kh[idx] = __float2half_rn(__expf(base[idx] - M) * inv);
    }
}

// ---------------------------------------------------------------------------
// q softmax over n per (b,c): grid BATCH*32 blocks, 16 c-rows per block,
// 256 threads (cr = t>>4, sub = t&15 over 16 x 64-token segments).
// Writes TRANSPOSED fp16 plane qT [N,C].
// ---------------------------------------------------------------------------
__global__ __launch_bounds__(256) void qsoftmax_kernel() {
    int b = blockIdx.x >> 5, c0 = (blockIdx.x & 31) * 16;
    const float* base = g_qkvT + (size_t)b * C3 * NTOK;
    int t = threadIdx.x;
    int cr = t >> 4, sub = t & 15;
    const float4* rp = reinterpret_cast<const float4*>(
        base + (size_t)(c0 + cr) * NTOK + sub * 64);

    float mx = -1e30f, sum = 0.f;
#pragma unroll
    for (int i = 0; i < 16; i++) {
        float4 v = rp[i];
        float m4 = fmaxf(fmaxf(v.x, v.y), fmaxf(v.z, v.w));
        float nm = fmaxf(mx, m4);
        sum = sum * __expf(mx - nm) + __expf(v.x - nm) + __expf(v.y - nm)
            + __expf(v.z - nm) + __expf(v.w - nm);
        mx = nm;
    }
#pragma unroll
    for (int o = 8; o >= 1; o >>= 1) {
        float m2 = __shfl_xor_sync(0xFFFFFFFFu, mx, o);
        float s2 = __shfl_xor_sync(0xFFFFFFFFu, sum, o);
        float nm = fmaxf(mx, m2);
        sum = sum * __expf(mx - nm) + s2 * __expf(m2 - nm);
        mx = nm;
    }
    __shared__ float sM[16], sI[16];
    if (sub == 0) { sM[cr] = mx; sI[cr] = 1.f / sum; }
    __syncthreads();
    float M = sM[cr], inv = sI[cr];

    __shared__ __half th[64][24];    // [token_local][c], padded
    for (int tn = 0; tn < 16; tn++) {
        float4 v = *reinterpret_cast<const float4*>(
            base + (size_t)(c0 + cr) * NTOK + tn * 64 + sub * 4);
        th[sub * 4 + 0][cr] = __float2half_rn(__expf(v.x - M) * inv);
        th[sub * 4 + 1][cr] = __float2half_rn(__expf(v.y - M) * inv);
        th[sub * 4 + 2][cr] = __float2half_rn(__expf(v.z - M) * inv);
        th[sub * 4 + 3][cr] = __float2half_rn(__expf(v.w - M) * inv);
        __syncthreads();
        if (t < 128) {
            int nl = t >> 1, chn = t & 1;
            size_t dst = ((size_t)b * NTOK + tn * 64 + nl) * CH + c0 + chn * 8;
            *reinterpret_cast<uint4*>(&g_qTh[dst]) = *reinterpret_cast<uint4*>(&th[nl][chn * 8]);
        }
        __syncthreads();
    }
}

// ---------------------------------------------------------------------------
// Launch
// ---------------------------------------------------------------------------
extern "C" void kernel_launch(void* const* d_in, const int* in_sizes, int n_in,
                              void* d_out, int out_size) {
    const float* x      = (const float*)d_in[0];
    const float* gn_w   = (const float*)d_in[1];
    const float* gn_b   = (const float*)d_in[2];
    const float* qkv_w  = (const float*)d_in[3];
    const float* qkv_b  = (const float*)d_in[4];
    const float* proj_w = (const float*)d_in[5];
    const float* proj_b = (const float*)d_in[6];
    float* out = (float*)d_out;

    void* p;
    cudaGetSymbolAddress(&p, g_xn);   float* xn   = (float*)p;
    cudaGetSymbolAddress(&p, g_qkvT); float* qkvT = (float*)p;
    cudaGetSymbolAddress(&p, g_xnTh); __half* xnTh = (__half*)p;
    cudaGetSymbolAddress(&p, g_w1f);  __half* w1f = (__half*)p;
    cudaGetSymbolAddress(&p, g_w2f);  __half* w2f = (__half*)p;
    cudaGetSymbolAddress(&p, g_kh);   __half* kh = (__half*)p;
    cudaGetSymbolAddress(&p, g_vh);   __half* vh = (__half*)p;
    cudaGetSymbolAddress(&p, g_qTh);  __half* qTh = (__half*)p;
    cudaGetSymbolAddress(&p, g_ch);   __half* ch = (__half*)p;
    cudaGetSymbolAddress(&p, g_o1h);  __half* o1h = (__half*)p;

    constexpr int SMB1 = (64 + 128) * 64 * 3;    // 36864 (MWT=1)
    constexpr int SMB2 = (128 + 128) * 64 * 3;   // 49152 (MWT=2)
    cudaFuncSetAttribute(gemmf16<2, 3>, cudaFuncAttributeMaxDynamicSharedMemorySize, SMB2);
    cudaFuncSetAttribute(gemmf16<1, 0>, cudaFuncAttributeMaxDynamicSharedMemorySize, SMB1);
    cudaFuncSetAttribute(gemmf16<2, 0>, cudaFuncAttributeMaxDynamicSharedMemorySize, SMB2);
    cudaFuncSetAttribute(gemmf16<2, 2>, cudaFuncAttributeMaxDynamicSharedMemorySize, SMB2);

    // 0) weight fp16 (single launch)
    conv_all_kernel<<<((C3 * CH + CH * CH) / 8 + 255) / 256, 256>>>(qkv_w, proj_w);

    // 1) GroupNorm
    gn_kernel<<<BATCH * GRP, 512>>>(x, gn_w, gn_b);

    // 2) GEMM1 (MWT=2, EP3): q,k -> fp32 qkvT; v -> fp16 plane. M=1536 N=1024 K=512
    gemmf16<2, 3><<<dim3(NTOK / 128, C3 / 128, BATCH), 256, SMB2>>>(
        w1f, xnTh, qkvT, vh,
        CH, CH, CH, NTOK,
        0LL, (long long)NTOK * CH, (long long)C3 * NTOK, (long long)CH * NTOK,
        qkv_b, nullptr);

    // 3) softmaxes (parallelized)
    ksoftmax_kernel<<<BATCH * 32, 512>>>();
    qsoftmax_kernel<<<BATCH * 32, 256>>>();

    // 4) GEMM2 (MWT=1, EP0): ctx[d,c] = sum_n v[d,n]*k[c,n]. M=512 N=512 K=1024
    gemmf16<1, 0><<<dim3(CH / 128, CH / 64, BATCH), 256, SMB1>>>(
        vh, kh, nullptr, ch,
        NTOK, NTOK, NTOK, CH,
        (long long)CH * NTOK, (long long)CH * NTOK, 0LL, (long long)CH * CH,
        nullptr, nullptr);

    // 5) GEMM3 (MWT=2, EP0): out1[n,d] = sum_c qT[n,c]*ctx[d,c]. M=1024 N=512 K=512
    gemmf16<2, 0><<<dim3(CH / 128, NTOK / 128, BATCH), 256, SMB2>>>(
        qTh, ch, nullptr, o1h,
        CH, CH, CH, CH,
        (long long)NTOK * CH, (long long)CH * CH, 0LL, (long long)NTOK * CH,
        nullptr, nullptr);

    // 6) GEMM4 (MWT=2, EP2): out[d,n] = proj(out1) + b + xn. M=512 N=1024 K=512
    gemmf16<2, 2><<<dim3(NTOK / 128, CH / 128, BATCH), 256, SMB2>>>(
        w2f, o1h, out, nullptr,
        CH, CH, CH, NTOK,
        0LL, (long long)NTOK * CH, (long long)CH * NTOK, 0LL,
        proj_b, xn);
}

// round 12
// speedup vs baseline: 4.8295x; 1.0697x over previous
#include <cuda_runtime.h>
#include <cuda_fp16.h>
#include <cstdint>

#define BATCH 8
#define CH    512
#define NTOK  1024
#define C3    1536
#define GRP   8
#define CPG   64
#define GSIZE 65536

// ---------------- scratch (device globals) ----------------
__device__ float g_xn  [BATCH * CH * NTOK];            // fp32 residual [B,C,N]
__device__ float g_gnp [BATCH * GRP * 8 * 2];          // gn partial sums
__device__ __half g_qkvf[BATCH * C3 * NTOK];           // qkv fp16 [B,3C,N]; k softmaxed in place
__device__ __half g_xnTh[BATCH * NTOK * CH];           // xn^T fp16 [B,N,C]
__device__ __half g_w1f[C3 * CH];                      // w1 fp16
__device__ __half g_w2f[CH * CH];                      // w2 fp16
__device__ __half g_qTh[BATCH * NTOK * CH];            // qT fp16 [N,C]
__device__ __half g_ch[BATCH * CH * CH];               // ctx fp16 [d,c]
__device__ __half g_o1h[BATCH * NTOK * CH];            // out1 fp16 [n,d]

// ---------------- helpers ----------------
__device__ __forceinline__ uint32_t smem_u32(const void* p) {
    uint32_t a;
    asm("{ .reg .u64 t; cvta.to.shared.u64 t, %1; cvt.u32.u64 %0, t; }" : "=r"(a) : "l"(p));
    return a;
}
__device__ __forceinline__ void mmaf16(float* c, uint32_t a0, uint32_t a1,
                                       uint32_t a2, uint32_t a3,
                                       uint32_t b0, uint32_t b1) {
    asm volatile(
        "mma.sync.aligned.m16n8k16.row.col.f32.f16.f16.f32 "
        "{%0,%1,%2,%3},{%4,%5,%6,%7},{%8,%9},{%0,%1,%2,%3};"
        : "+f"(c[0]), "+f"(c[1]), "+f"(c[2]), "+f"(c[3])
        : "r"(a0), "r"(a1), "r"(a2), "r"(a3), "r"(b0), "r"(b1));
}
__device__ __forceinline__ void ldm4(uint32_t& r0, uint32_t& r1, uint32_t& r2,
                                     uint32_t& r3, uint32_t a) {
    asm volatile("ldmatrix.sync.aligned.m8n8.x4.shared.b16 {%0,%1,%2,%3}, [%4];"
                 : "=r"(r0), "=r"(r1), "=r"(r2), "=r"(r3) : "r"(a));
}
#define CPA16(d, s) asm volatile("cp.async.cg.shared.global [%0], [%1], 16;" :: "r"(d), "l"(s))
#define CPCOMMIT()  asm volatile("cp.async.commit_group;")
#define CPWAIT1()   asm volatile("cp.async.wait_group 1;" ::: "memory")
#define CPWAIT0()   asm volatile("cp.async.wait_group 0;" ::: "memory")

// swizzled byte offset within a plane: row r (64B rows), 16B chunk c
__device__ __forceinline__ uint32_t swz(int r, int c) {
    return (uint32_t)(r * 64 + ((c ^ ((r >> 1) & 3)) << 4));
}

// ---------------------------------------------------------------------------
// fp16 single-pass tensor-core GEMM, 3-stage cp.async pipeline, swizzled smem.
// D[BM x 128] = sum_k A(m,k)*B(n,k), BM = 64*MWT.
// EP 0: fp16 plane, no bias.  EP 1: fp16 plane + bias[m].
// EP 2: fp32 + bias[m] + resid[m*ldc+n].
// ---------------------------------------------------------------------------
template <int MWT, int EP>
__global__ __launch_bounds__(256, (MWT == 1 ? 4 : 2)) void gemmf16(
    const __half* __restrict__ Ah, const __half* __restrict__ Bh,
    float* __restrict__ C, __half* __restrict__ Ch,
    int K, int lda, int ldb, int ldc,
    long long sA, long long sB, long long sC, long long sCp,
    const float* __restrict__ bias, const float* __restrict__ resid)
{
    constexpr int BM = 64 * MWT, BN = 128;
    constexpr int NMT = 2 * MWT;
    constexpr int BOB = BM * 64;
    constexpr int SSB = (BM + BN) * 64;

    extern __shared__ __align__(128) __half smbuf[];
    const uint32_t su = smem_u32(smbuf);
    const int tid = threadIdx.x;
    const int bz = blockIdx.z;
    Ah += (size_t)bz * sA;
    Bh += (size_t)bz * sB;
    const int m0 = blockIdx.y * BM, n0 = blockIdx.x * BN;

    const int lane = tid & 31, wid = tid >> 5;
    const int g = lane >> 2, tg = lane & 3;
    const int wm = (wid & 1) * 32 * MWT, wn = (wid >> 1) * 32;
    const int lr = lane & 15, lchunk = lane >> 4;

    float acc[NMT][4][4];
#pragma unroll
    for (int i = 0; i < NMT; i++)
#pragma unroll
        for (int j = 0; j < 4; j++)
#pragma unroll
            for (int q = 0; q < 4; q++) acc[i][j][q] = 0.f;

    auto fill = [&](int st, int k0) {
        uint32_t base = su + (uint32_t)(st * SSB);
#pragma unroll
        for (int i = 0; i < MWT; i++) {
            int idx = tid + 256 * i;
            int row = idx >> 2, ch = idx & 3;
            CPA16(base + swz(row, ch), Ah + (size_t)(m0 + row) * lda + k0 + ch * 8);
        }
#pragma unroll
        for (int i = 0; i < 2; i++) {
            int idx = tid + 256 * i;
            int row = idx >> 2, ch = idx & 3;
            CPA16(base + BOB + swz(row, ch), Bh + (size_t)(n0 + row) * ldb + k0 + ch * 8);
        }
        CPCOMMIT();
    };

    const int NC = K / 32;
    fill(0, 0);
    fill(1, 32);

    int st = 0;
    for (int c = 0; c < NC; c++) {
        if (c + 1 < NC) { CPWAIT1(); } else { CPWAIT0(); }
        __syncthreads();
        if (c + 2 < NC) {
            int ns = st + 2; if (ns >= 3) ns -= 3;
            fill(ns, (c + 2) * 32);
        }
        const uint32_t sb = su + (uint32_t)(st * SSB);

#pragma unroll
        for (int ks = 0; ks < 32; ks += 16) {
            const int kc = (ks >> 3) + lchunk;
            uint32_t Bf[8];
#pragma unroll
            for (int pr = 0; pr < 2; pr++) {
                int r = wn + pr * 16 + lr;
                ldm4(Bf[pr * 4 + 0], Bf[pr * 4 + 1], Bf[pr * 4 + 2], Bf[pr * 4 + 3],
                     sb + BOB + swz(r, kc));
            }
            uint32_t Af[NMT][4];
#pragma unroll
            for (int mt = 0; mt < NMT; mt++) {
                int r = wm + mt * 16 + lr;
                ldm4(Af[mt][0], Af[mt][1], Af[mt][2], Af[mt][3], sb + swz(r, kc));
            }
#pragma unroll
            for (int mt = 0; mt < NMT; mt++)
#pragma unroll
                for (int nt = 0; nt < 4; nt++) {
                    int i0 = (nt >> 1) * 4 + (nt & 1);
                    mmaf16(acc[mt][nt], Af[mt][0], Af[mt][1], Af[mt][2], Af[mt][3],
                           Bf[i0], Bf[i0 + 2]);
                }
        }
        if (++st == 3) st = 0;
    }

    // ---- epilogue ----
    if (EP <= 1) {
        __half* Chp = Ch + (size_t)bz * sCp;
#pragma unroll
        for (int mt = 0; mt < NMT; mt++) {
            int m = m0 + wm + mt * 16 + g;
            float bv0 = (EP == 1) ? bias[m] : 0.f;
            float bv1 = (EP == 1) ? bias[m + 8] : 0.f;
#pragma unroll
            for (int nt = 0; nt < 4; nt++) {
                int n = n0 + wn + nt * 8 + tg * 2;
                float* a = acc[mt][nt];
                size_t i0 = (size_t)m * ldc + n;
                size_t i1 = (size_t)(m + 8) * ldc + n;
                *reinterpret_cast<__half2*>(Chp + i0) =
                    __half2(__float2half_rn(a[0] + bv0), __float2half_rn(a[1] + bv0));
                *reinterpret_cast<__half2*>(Chp + i1) =
                    __half2(__float2half_rn(a[2] + bv1), __float2half_rn(a[3] + bv1));
            }
        }
    } else {
        float* Cp = C + (size_t)bz * sC;
        const float* R = resid + (size_t)bz * sC;
#pragma unroll
        for (int mt = 0; mt < NMT; mt++) {
            int m = m0 + wm + mt * 16 + g;
            float bv0 = bias[m], bv1 = bias[m + 8];
#pragma unroll
            for (int nt = 0; nt < 4; nt++) {
                int n = n0 + wn + nt * 8 + tg * 2;
                float* a = acc[mt][nt];
                size_t i0 = (size_t)m * ldc + n;
                size_t i1 = (size_t)(m + 8) * ldc + n;
                float2 r0 = *reinterpret_cast<const float2*>(R + i0);
                float2 r1 = *reinterpret_cast<const float2*>(R + i1);
                float2 o0, o1;
                o0.x = a[0] + bv0 + r0.x; o0.y = a[1] + bv0 + r0.y;
                o1.x = a[2] + bv1 + r1.x; o1.y = a[3] + bv1 + r1.y;
                *reinterpret_cast<float2*>(Cp + i0) = o0;
                *reinterpret_cast<float2*>(Cp + i1) = o1;
            }
        }
    }
}

// ---------------------------------------------------------------------------
// GroupNorm pass 1: partial sums. Grid 64*8 blocks (bg, slice), 256 thr.
// ---------------------------------------------------------------------------
__global__ __launch_bounds__(256) void gn_sum_kernel(const float* __restrict__ x) {
    int bg = blockIdx.x >> 3, slice = blockIdx.x & 7;
    const float4* xp = reinterpret_cast<const float4*>(
        x + (size_t)bg * GSIZE + slice * 8192);
    int t = threadIdx.x;
    float s = 0.f, sq = 0.f;
#pragma unroll
    for (int i = 0; i < 8; i++) {
        float4 v = xp[t + 256 * i];
        s  += v.x + v.y + v.z + v.w;
        sq += v.x * v.x + v.y * v.y + v.z * v.z + v.w * v.w;
    }
#pragma unroll
    for (int o = 16; o >= 1; o >>= 1) {
        s  += __shfl_xor_sync(0xFFFFFFFFu, s, o);
        sq += __shfl_xor_sync(0xFFFFFFFFu, sq, o);
    }
    __shared__ float rs[8], rq[8];
    if ((t & 31) == 0) { rs[t >> 5] = s; rq[t >> 5] = sq; }
    __syncthreads();
    if (t == 0) {
        float S = 0.f, Q = 0.f;
#pragma unroll
        for (int i = 0; i < 8; i++) { S += rs[i]; Q += rq[i]; }
        g_gnp[(bg * 8 + slice) * 2 + 0] = S;
        g_gnp[(bg * 8 + slice) * 2 + 1] = Q;
    }
}

// ---------------------------------------------------------------------------
// GroupNorm pass 2: normalize + fp32 residual + transposed fp16 plane.
// Grid 64*8 blocks (bg, n-slice of 128 tokens), 256 thr.
// ---------------------------------------------------------------------------
__global__ __launch_bounds__(256) void gn_norm_kernel(const float* __restrict__ x,
                                                      const float* __restrict__ gamma,
                                                      const float* __restrict__ beta) {
    int bg = blockIdx.x >> 3, slice = blockIdx.x & 7;
    int b = bg >> 3, g = bg & 7;
    int n0 = slice * 128;
    int t = threadIdx.x;

    float S = 0.f, Q = 0.f;
#pragma unroll
    for (int i = 0; i < 8; i++) {
        S += g_gnp[(bg * 8 + i) * 2 + 0];
        Q += g_gnp[(bg * 8 + i) * 2 + 1];
    }
    float mean = S * (1.f / GSIZE);
    float var  = Q * (1.f / GSIZE) - mean * mean;
    float rstd = rsqrtf(var + 1e-5f);

    int c = t >> 2, sub = t & 3;
    float gm = gamma[g * CPG + c] * rstd;
    float bt = beta[g * CPG + c] - mean * gm;

    size_t rowoff = ((size_t)b * CH + g * CPG + c) * NTOK + n0;
    const float4* xp = reinterpret_cast<const float4*>(x + rowoff);
    float4* gp = reinterpret_cast<float4*>(g_xn + rowoff);

    __shared__ __half th[128][72];
#pragma unroll
    for (int i = 0; i < 8; i++) {
        int nq = sub * 8 + i;             // float4 index within 128 tokens
        float4 v = xp[nq];
        v.x = v.x * gm + bt; v.y = v.y * gm + bt;
        v.z = v.z * gm + bt; v.w = v.w * gm + bt;
        gp[nq] = v;
        th[nq * 4 + 0][c] = __float2half_rn(v.x);
        th[nq * 4 + 1][c] = __float2half_rn(v.y);
        th[nq * 4 + 2][c] = __float2half_rn(v.z);
        th[nq * 4 + 3][c] = __float2half_rn(v.w);
    }
    __syncthreads();
#pragma unroll
    for (int it = 0; it < 4; it++) {
        int idx = t + 256 * it;           // 1024 uint4 writes
        int nl = idx >> 3, c8 = idx & 7;
        size_t dst = ((size_t)b * NTOK + n0 + nl) * CH + g * CPG + c8 * 8;
        *reinterpret_cast<uint4*>(&g_xnTh[dst]) = *reinterpret_cast<uint4*>(&th[nl][c8 * 8]);
    }
}

// ---------------------------------------------------------------------------
// Weight convert: both weights in one launch.
// ---------------------------------------------------------------------------
__global__ void conv_all_kernel(const float* __restrict__ w1, const float* __restrict__ w2) {
    int i = blockIdx.x * 256 + threadIdx.x;
    const int n1 = C3 * CH / 8, n2 = CH * CH / 8;
    if (i >= n1 + n2) return;
    const float* src = (i < n1) ? w1 : w2;
    __half* dst = (i < n1) ? g_w1f : g_w2f;
    int j = (i < n1) ? i : i - n1;
    const float4* s = reinterpret_cast<const float4*>(src) + j * 2;
    float4 v0 = s[0], v1 = s[1];
    __half hh[8];
    hh[0] = __float2half_rn(v0.x); hh[1] = __float2half_rn(v0.y);
    hh[2] = __float2half_rn(v0.z); hh[3] = __float2half_rn(v0.w);
    hh[4] = __float2half_rn(v1.x); hh[5] = __float2half_rn(v1.y);
    hh[6] = __float2half_rn(v1.z); hh[7] = __float2half_rn(v1.w);
    *reinterpret_cast<uint4*>(dst + (size_t)j * 8) = *reinterpret_cast<uint4*>(hh);
}

// ---------------------------------------------------------------------------
// k softmax over c per (b,n), IN PLACE on fp16 qkv k-block [C,N].
// 512 threads, 16 warps x 32 rows. Grid BATCH*32.
// ---------------------------------------------------------------------------
__global__ __launch_bounds__(512) void ksoftmax_kernel() {
    int b = blockIdx.x >> 5;
    int n0 = (blockIdx.x & 31) * 32;
    __half* base = g_qkvf + (size_t)b * C3 * NTOK + (size_t)CH * NTOK + n0;
    int lane = threadIdx.x & 31, j = threadIdx.x >> 5;   // j in [0,16)

    float mx = -1e30f, sum = 0.f;
    for (int i = 0; i < 32; i++) {
        float v = __half2float(base[(size_t)(j * 32 + i) * NTOK + lane]);
        float nm = fmaxf(mx, v);
        sum = sum * __expf(mx - nm) + __expf(v - nm);
        mx = nm;
    }
    __shared__ float sM[16][32], sS[16][32];
    sM[j][lane] = mx; sS[j][lane] = sum;
    __syncthreads();
    if (j == 0) {
        float M = sM[0][lane], S = sS[0][lane];
#pragma unroll
        for (int t = 1; t < 16; t++) {
            float m2 = sM[t][lane], s2 = sS[t][lane];
            float nm = fmaxf(M, m2);
            S = S * __expf(M - nm) + s2 * __expf(m2 - nm);
            M = nm;
        }
        sM[0][lane] = M; sS[0][lane] = 1.f / S;
    }
    __syncthreads();
    float M = sM[0][lane], inv = sS[0][lane];
    for (int i = 0; i < 32; i++) {
        size_t idx = (size_t)(j * 32 + i) * NTOK + lane;
        base[idx] = __float2half_rn(__expf(__half2float(base[idx]) - M) * inv);
    }
}

// ---------------------------------------------------------------------------
// q softmax over n per (b,c): reads fp16 q rows, writes TRANSPOSED qT [N,C].
// Grid BATCH*32 blocks (16 c-rows each), 256 threads.
// ---------------------------------------------------------------------------
__global__ __launch_bounds__(256) void qsoftmax_kernel() {
    int b = blockIdx.x >> 5, c0 = (blockIdx.x & 31) * 16;
    const __half* base = g_qkvf + (size_t)b * C3 * NTOK;
    int t = threadIdx.x;
    int cr = t >> 4, sub = t & 15;
    const __half* rp = base + (size_t)(c0 + cr) * NTOK + sub * 64;

    float mx = -1e30f, sum = 0.f;
#pragma unroll
    for (int i = 0; i < 8; i++) {
        uint4 u = *reinterpret_cast<const uint4*>(rp + i * 8);
        const __half2* hp = reinterpret_cast<const __half2*>(&u);
#pragma unroll
        for (int q = 0; q < 4; q++) {
            float2 f = __half22float2(hp[q]);
            float m2 = fmaxf(f.x, f.y);
            float nm = fmaxf(mx, m2);
            sum = sum * __expf(mx - nm) + __expf(f.x - nm) + __expf(f.y - nm);
            mx = nm;
        }
    }
#pragma unroll
    for (int o = 8; o >= 1; o >>= 1) {
        float m2 = __shfl_xor_sync(0xFFFFFFFFu, mx, o);
        float s2 = __shfl_xor_sync(0xFFFFFFFFu, sum, o);
        float nm = fmaxf(mx, m2);
        sum = sum * __expf(mx - nm) + s2 * __expf(m2 - nm);
        mx = nm;
    }
    __shared__ float sM[16], sI[16];
    if (sub == 0) { sM[cr] = mx; sI[cr] = 1.f / sum; }
    __syncthreads();
    float M = sM[cr], inv = sI[cr];

    __shared__ __half th[64][24];
    for (int tn = 0; tn < 16; tn++) {
        uint2 u = *reinterpret_cast<const uint2*>(
            base + (size_t)(c0 + cr) * NTOK + tn * 64 + sub * 4);
        const __half2* hp = reinterpret_cast<const __half2*>(&u);
        float2 f0 = __half22float2(hp[0]), f1 = __half22float2(hp[1]);
        th[sub * 4 + 0][cr] = __float2half_rn(__expf(f0.x - M) * inv);
        th[sub * 4 + 1][cr] = __float2half_rn(__expf(f0.y - M) * inv);
        th[sub * 4 + 2][cr] = __float2half_rn(__expf(f1.x - M) * inv);
        th[sub * 4 + 3][cr] = __float2half_rn(__expf(f1.y - M) * inv);
        __syncthreads();
        if (t < 128) {
            int nl = t >> 1, chn = t & 1;
            size_t dst = ((size_t)b * NTOK + tn * 64 + nl) * CH + c0 + chn * 8;
            *reinterpret_cast<uint4*>(&g_qTh[dst]) = *reinterpret_cast<uint4*>(&th[nl][chn * 8]);
        }
        __syncthreads();
    }
}

// ---------------------------------------------------------------------------
// Launch
// ---------------------------------------------------------------------------
extern "C" void kernel_launch(void* const* d_in, const int* in_sizes, int n_in,
                              void* d_out, int out_size) {
    const float* x      = (const float*)d_in[0];
    const float* gn_w   = (const float*)d_in[1];
    const float* gn_b   = (const float*)d_in[2];
    const float* qkv_w  = (const float*)d_in[3];
    const float* qkv_b  = (const float*)d_in[4];
    const float* proj_w = (const float*)d_in[5];
    const float* proj_b = (const float*)d_in[6];
    float* out = (float*)d_out;

    void* p;
    cudaGetSymbolAddress(&p, g_xn);   float* xn   = (float*)p;
    cudaGetSymbolAddress(&p, g_qkvf); __half* qkvf = (__half*)p;
    cudaGetSymbolAddress(&p, g_xnTh); __half* xnTh = (__half*)p;
    cudaGetSymbolAddress(&p, g_w1f);  __half* w1f = (__half*)p;
    cudaGetSymbolAddress(&p, g_w2f);  __half* w2f = (__half*)p;
    cudaGetSymbolAddress(&p, g_qTh);  __half* qTh = (__half*)p;
    cudaGetSymbolAddress(&p, g_ch);   __half* ch = (__half*)p;
    cudaGetSymbolAddress(&p, g_o1h);  __half* o1h = (__half*)p;

    constexpr int SMB1 = (64 + 128) * 64 * 3;    // 36864 (MWT=1)
    constexpr int SMB2 = (128 + 128) * 64 * 3;   // 49152 (MWT=2)
    cudaFuncSetAttribute(gemmf16<2, 1>, cudaFuncAttributeMaxDynamicSharedMemorySize, SMB2);
    cudaFuncSetAttribute(gemmf16<1, 0>, cudaFuncAttributeMaxDynamicSharedMemorySize, SMB1);
    cudaFuncSetAttribute(gemmf16<2, 0>, cudaFuncAttributeMaxDynamicSharedMemorySize, SMB2);
    cudaFuncSetAttribute(gemmf16<2, 2>, cudaFuncAttributeMaxDynamicSharedMemorySize, SMB2);

    // 0) weight fp16 (single launch)
    conv_all_kernel<<<((C3 * CH + CH * CH) / 8 + 255) / 256, 256>>>(qkv_w, proj_w);

    // 1) GroupNorm (two-pass, full-chip grids)
    gn_sum_kernel<<<BATCH * GRP * 8, 256>>>(x);
    gn_norm_kernel<<<BATCH * GRP * 8, 256>>>(x, gn_w, gn_b);

    // 2) GEMM1 (MWT=2, EP1): qkv fp16 [3C,N] + bias. M=1536 N=1024 K=512
    gemmf16<2, 1><<<dim3(NTOK / 128, C3 / 128, BATCH), 256, SMB2>>>(
        w1f, xnTh, nullptr, qkvf,
        CH, CH, CH, NTOK,
        0LL, (long long)NTOK * CH, 0LL, (long long)C3 * NTOK,
        qkv_b, nullptr);

    // 3) softmaxes (k in place; q -> transposed plane)
    ksoftmax_kernel<<<BATCH * 32, 512>>>();
    qsoftmax_kernel<<<BATCH * 32, 256>>>();

    // 4) GEMM2 (MWT=1, EP0): ctx[d,c] = sum_n v[d,n]*k[c,n]. M=512 N=512 K=1024
    gemmf16<1, 0><<<dim3(CH / 128, CH / 64, BATCH), 256, SMB1>>>(
        qkvf + (size_t)2 * CH * NTOK, qkvf + (size_t)CH * NTOK, nullptr, ch,
        NTOK, NTOK, NTOK, CH,
        (long long)C3 * NTOK, (long long)C3 * NTOK, 0LL, (long long)CH * CH,
        nullptr, nullptr);

    // 5) GEMM3 (MWT=2, EP0): out1[n,d] = sum_c qT[n,c]*ctx[d,c]. M=1024 N=512 K=512
    gemmf16<2, 0><<<dim3(CH / 128, NTOK / 128, BATCH), 256, SMB2>>>(
        qTh, ch, nullptr, o1h,
        CH, CH, CH, CH,
        (long long)NTOK * CH, (long long)CH * CH, 0LL, (long long)NTOK * CH,
        nullptr, nullptr);

    // 6) GEMM4 (MWT=2, EP2): out[d,n] = proj(out1) + b + xn. M=512 N=1024 K=512
    gemmf16<2, 2><<<dim3(NTOK / 128, CH / 128, BATCH), 256, SMB2>>>(
        w2f, o1h, out, nullptr,
        CH, CH, CH, NTOK,
        0LL, (long long)NTOK * CH, (long long)CH * NTOK, 0LL,
        proj_b, xn);
}

// round 13
// speedup vs baseline: 5.0424x; 1.0441x over previous
#include <cuda_runtime.h>
#include <cuda_fp16.h>
#include <cstdint>

#define BATCH 8
#define CH    512
#define NTOK  1024
#define C3    1536
#define GRP   8
#define CPG   64
#define GSIZE 65536

// ---------------- scratch (device globals) ----------------
__device__ float g_xn  [BATCH * CH * NTOK];            // fp32 residual [B,C,N]
__device__ float g_gnp [BATCH * GRP * 8 * 2];          // gn partial sums
__device__ __half g_qkvf[BATCH * C3 * NTOK];           // qkv fp16 [B,3C,N]; k softmaxed in place
__device__ __half g_xnTh[BATCH * NTOK * CH];           // xn^T fp16 [B,N,C]
__device__ __half g_w1f[C3 * CH];                      // w1 fp16
__device__ __half g_w2f[CH * CH];                      // w2 fp16
__device__ __half g_qTh[BATCH * NTOK * CH];            // qT fp16 [N,C]
__device__ __half g_ctxT[BATCH * CH * CH];             // ctx^T fp16 [c,d]
__device__ __half g_m2[BATCH * CH * CH];               // M2 = w2*ctx fp16 [d,c]

// ---------------- helpers ----------------
__device__ __forceinline__ uint32_t smem_u32(const void* p) {
    uint32_t a;
    asm("{ .reg .u64 t; cvta.to.shared.u64 t, %1; cvt.u32.u64 %0, t; }" : "=r"(a) : "l"(p));
    return a;
}
__device__ __forceinline__ void mmaf16(float* c, uint32_t a0, uint32_t a1,
                                       uint32_t a2, uint32_t a3,
                                       uint32_t b0, uint32_t b1) {
    asm volatile(
        "mma.sync.aligned.m16n8k16.row.col.f32.f16.f16.f32 "
        "{%0,%1,%2,%3},{%4,%5,%6,%7},{%8,%9},{%0,%1,%2,%3};"
        : "+f"(c[0]), "+f"(c[1]), "+f"(c[2]), "+f"(c[3])
        : "r"(a0), "r"(a1), "r"(a2), "r"(a3), "r"(b0), "r"(b1));
}
__device__ __forceinline__ void ldm4(uint32_t& r0, uint32_t& r1, uint32_t& r2,
                                     uint32_t& r3, uint32_t a) {
    asm volatile("ldmatrix.sync.aligned.m8n8.x4.shared.b16 {%0,%1,%2,%3}, [%4];"
                 : "=r"(r0), "=r"(r1), "=r"(r2), "=r"(r3) : "r"(a));
}
#define CPA16(d, s) asm volatile("cp.async.cg.shared.global [%0], [%1], 16;" :: "r"(d), "l"(s))
#define CPCOMMIT()  asm volatile("cp.async.commit_group;")
#define CPWAIT1()   asm volatile("cp.async.wait_group 1;" ::: "memory")
#define CPWAIT0()   asm volatile("cp.async.wait_group 0;" ::: "memory")

// swizzled byte offset within a plane: row r (64B rows), 16B chunk c
__device__ __forceinline__ uint32_t swz(int r, int c) {
    return (uint32_t)(r * 64 + ((c ^ ((r >> 1) & 3)) << 4));
}

// ---------------------------------------------------------------------------
// fp16 single-pass tensor-core GEMM, 3-stage cp.async pipeline, swizzled smem.
// D[BM x 128] = sum_k A(m,k)*B(n,k), BM = 64*MWT.
// EP 0: fp16 plane, no bias.  EP 1: fp16 plane + bias[m].
// EP 2: fp32 + bias[m] + resid[m*ldc+n].
// ---------------------------------------------------------------------------
template <int MWT, int EP>
__global__ __launch_bounds__(256, (MWT == 1 ? 4 : 2)) void gemmf16(
    const __half* __restrict__ Ah, const __half* __restrict__ Bh,
    float* __restrict__ C, __half* __restrict__ Ch,
    int K, int lda, int ldb, int ldc,
    long long sA, long long sB, long long sC, long long sCp,
    const float* __restrict__ bias, const float* __restrict__ resid)
{
    constexpr int BM = 64 * MWT, BN = 128;
    constexpr int NMT = 2 * MWT;
    constexpr int BOB = BM * 64;
    constexpr int SSB = (BM + BN) * 64;

    extern __shared__ __align__(128) __half smbuf[];
    const uint32_t su = smem_u32(smbuf);
    const int tid = threadIdx.x;
    const int bz = blockIdx.z;
    Ah += (size_t)bz * sA;
    Bh += (size_t)bz * sB;
    const int m0 = blockIdx.y * BM, n0 = blockIdx.x * BN;

    const int lane = tid & 31, wid = tid >> 5;
    const int g = lane >> 2, tg = lane & 3;
    const int wm = (wid & 1) * 32 * MWT, wn = (wid >> 1) * 32;
    const int lr = lane & 15, lchunk = lane >> 4;

    float acc[NMT][4][4];
#pragma unroll
    for (int i = 0; i < NMT; i++)
#pragma unroll
        for (int j = 0; j < 4; j++)
#pragma unroll
            for (int q = 0; q < 4; q++) acc[i][j][q] = 0.f;

    auto fill = [&](int st, int k0) {
        uint32_t base = su + (uint32_t)(st * SSB);
#pragma unroll
        for (int i = 0; i < MWT; i++) {
            int idx = tid + 256 * i;
            int row = idx >> 2, ch = idx & 3;
            CPA16(base + swz(row, ch), Ah + (size_t)(m0 + row) * lda + k0 + ch * 8);
        }
#pragma unroll
        for (int i = 0; i < 2; i++) {
            int idx = tid + 256 * i;
            int row = idx >> 2, ch = idx & 3;
            CPA16(base + BOB + swz(row, ch), Bh + (size_t)(n0 + row) * ldb + k0 + ch * 8);
        }
        CPCOMMIT();
    };

    const int NC = K / 32;
    fill(0, 0);
    fill(1, 32);

    int st = 0;
    for (int c = 0; c < NC; c++) {
        if (c + 1 < NC) { CPWAIT1(); } else { CPWAIT0(); }
        __syncthreads();
        if (c + 2 < NC) {
            int ns = st + 2; if (ns >= 3) ns -= 3;
            fill(ns, (c + 2) * 32);
        }
        const uint32_t sb = su + (uint32_t)(st * SSB);

#pragma unroll
        for (int ks = 0; ks < 32; ks += 16) {
            const int kc = (ks >> 3) + lchunk;
            uint32_t Bf[8];
#pragma unroll
            for (int pr = 0; pr < 2; pr++) {
                int r = wn + pr * 16 + lr;
                ldm4(Bf[pr * 4 + 0], Bf[pr * 4 + 1], Bf[pr * 4 + 2], Bf[pr * 4 + 3],
                     sb + BOB + swz(r, kc));
            }
            uint32_t Af[NMT][4];
#pragma unroll
            for (int mt = 0; mt < NMT; mt++) {
                int r = wm + mt * 16 + lr;
                ldm4(Af[mt][0], Af[mt][1], Af[mt][2], Af[mt][3], sb + swz(r, kc));
            }
#pragma unroll
            for (int mt = 0; mt < NMT; mt++)
#pragma unroll
                for (int nt = 0; nt < 4; nt++) {
                    int i0 = (nt >> 1) * 4 + (nt & 1);
                    mmaf16(acc[mt][nt], Af[mt][0], Af[mt][1], Af[mt][2], Af[mt][3],
                           Bf[i0], Bf[i0 + 2]);
                }
        }
        if (++st == 3) st = 0;
    }

    // ---- epilogue ----
    if (EP <= 1) {
        __half* Chp = Ch + (size_t)bz * sCp;
#pragma unroll
        for (int mt = 0; mt < NMT; mt++) {
            int m = m0 + wm + mt * 16 + g;
            float bv0 = (EP == 1) ? bias[m] : 0.f;
            float bv1 = (EP == 1) ? bias[m + 8] : 0.f;
#pragma unroll
            for (int nt = 0; nt < 4; nt++) {
                int n = n0 + wn + nt * 8 + tg * 2;
                float* a = acc[mt][nt];
                size_t i0 = (size_t)m * ldc + n;
                size_t i1 = (size_t)(m + 8) * ldc + n;
                *reinterpret_cast<__half2*>(Chp + i0) =
                    __half2(__float2half_rn(a[0] + bv0), __float2half_rn(a[1] + bv0));
                *reinterpret_cast<__half2*>(Chp + i1) =
                    __half2(__float2half_rn(a[2] + bv1), __float2half_rn(a[3] + bv1));
            }
        }
    } else {
        float* Cp = C + (size_t)bz * sC;
        const float* R = resid + (size_t)bz * sC;
#pragma unroll
        for (int mt = 0; mt < NMT; mt++) {
            int m = m0 + wm + mt * 16 + g;
            float bv0 = bias[m], bv1 = bias[m + 8];
#pragma unroll
            for (int nt = 0; nt < 4; nt++) {
                int n = n0 + wn + nt * 8 + tg * 2;
                float* a = acc[mt][nt];
                size_t i0 = (size_t)m * ldc + n;
                size_t i1 = (size_t)(m + 8) * ldc + n;
                float2 r0 = *reinterpret_cast<const float2*>(R + i0);
                float2 r1 = *reinterpret_cast<const float2*>(R + i1);
                float2 o0, o1;
                o0.x = a[0] + bv0 + r0.x; o0.y = a[1] + bv0 + r0.y;
                o1.x = a[2] + bv1 + r1.x; o1.y = a[3] + bv1 + r1.y;
                *reinterpret_cast<float2*>(Cp + i0) = o0;
                *reinterpret_cast<float2*>(Cp + i1) = o1;
            }
        }
    }
}

// ---------------------------------------------------------------------------
// GroupNorm pass 1: partial sums. Grid 64*8 blocks (bg, slice), 256 thr.
// ---------------------------------------------------------------------------
__global__ __launch_bounds__(256) void gn_sum_kernel(const float* __restrict__ x) {
    int bg = blockIdx.x >> 3, slice = blockIdx.x & 7;
    const float4* xp = reinterpret_cast<const float4*>(
        x + (size_t)bg * GSIZE + slice * 8192);
    int t = threadIdx.x;
    float s = 0.f, sq = 0.f;
#pragma unroll
    for (int i = 0; i < 8; i++) {
        float4 v = xp[t + 256 * i];
        s  += v.x + v.y + v.z + v.w;
        sq += v.x * v.x + v.y * v.y + v.z * v.z + v.w * v.w;
    }
#pragma unroll
    for (int o = 16; o >= 1; o >>= 1) {
        s  += __shfl_xor_sync(0xFFFFFFFFu, s, o);
        sq += __shfl_xor_sync(0xFFFFFFFFu, sq, o);
    }
    __shared__ float rs[8], rq[8];
    if ((t & 31) == 0) { rs[t >> 5] = s; rq[t >> 5] = sq; }
    __syncthreads();
    if (t == 0) {
        float S = 0.f, Q = 0.f;
#pragma unroll
        for (int i = 0; i < 8; i++) { S += rs[i]; Q += rq[i]; }
        g_gnp[(bg * 8 + slice) * 2 + 0] = S;
        g_gnp[(bg * 8 + slice) * 2 + 1] = Q;
    }
}

// ---------------------------------------------------------------------------
// GroupNorm pass 2: normalize + fp32 residual + transposed fp16 plane.
// ---------------------------------------------------------------------------
__global__ __launch_bounds__(256) void gn_norm_kernel(const float* __restrict__ x,
                                                      const float* __restrict__ gamma,
                                                      const float* __restrict__ beta) {
    int bg = blockIdx.x >> 3, slice = blockIdx.x & 7;
    int b = bg >> 3, g = bg & 7;
    int n0 = slice * 128;
    int t = threadIdx.x;

    float S = 0.f, Q = 0.f;
#pragma unroll
    for (int i = 0; i < 8; i++) {
        S += g_gnp[(bg * 8 + i) * 2 + 0];
        Q += g_gnp[(bg * 8 + i) * 2 + 1];
    }
    float mean = S * (1.f / GSIZE);
    float var  = Q * (1.f / GSIZE) - mean * mean;
    float rstd = rsqrtf(var + 1e-5f);

    int c = t >> 2, sub = t & 3;
    float gm = gamma[g * CPG + c] * rstd;
    float bt = beta[g * CPG + c] - mean * gm;

    size_t rowoff = ((size_t)b * CH + g * CPG + c) * NTOK + n0;
    const float4* xp = reinterpret_cast<const float4*>(x + rowoff);
    float4* gp = reinterpret_cast<float4*>(g_xn + rowoff);

    __shared__ __half th[128][72];
#pragma unroll
    for (int i = 0; i < 8; i++) {
        int nq = sub * 8 + i;
        float4 v = xp[nq];
        v.x = v.x * gm + bt; v.y = v.y * gm + bt;
        v.z = v.z * gm + bt; v.w = v.w * gm + bt;
        gp[nq] = v;
        th[nq * 4 + 0][c] = __float2half_rn(v.x);
        th[nq * 4 + 1][c] = __float2half_rn(v.y);
        th[nq * 4 + 2][c] = __float2half_rn(v.z);
        th[nq * 4 + 3][c] = __float2half_rn(v.w);
    }
    __syncthreads();
#pragma unroll
    for (int it = 0; it < 4; it++) {
        int idx = t + 256 * it;
        int nl = idx >> 3, c8 = idx & 7;
        size_t dst = ((size_t)b * NTOK + n0 + nl) * CH + g * CPG + c8 * 8;
        *reinterpret_cast<uint4*>(&g_xnTh[dst]) = *reinterpret_cast<uint4*>(&th[nl][c8 * 8]);
    }
}

// ---------------------------------------------------------------------------
// Weight convert: both weights in one launch.
// ---------------------------------------------------------------------------
__global__ void conv_all_kernel(const float* __restrict__ w1, const float* __restrict__ w2) {
    int i = blockIdx.x * 256 + threadIdx.x;
    const int n1 = C3 * CH / 8, n2 = CH * CH / 8;
    if (i >= n1 + n2) return;
    const float* src = (i < n1) ? w1 : w2;
    __half* dst = (i < n1) ? g_w1f : g_w2f;
    int j = (i < n1) ? i : i - n1;
    const float4* s = reinterpret_cast<const float4*>(src) + j * 2;
    float4 v0 = s[0], v1 = s[1];
    __half hh[8];
    hh[0] = __float2half_rn(v0.x); hh[1] = __float2half_rn(v0.y);
    hh[2] = __float2half_rn(v0.z); hh[3] = __float2half_rn(v0.w);
    hh[4] = __float2half_rn(v1.x); hh[5] = __float2half_rn(v1.y);
    hh[6] = __float2half_rn(v1.z); hh[7] = __float2half_rn(v1.w);
    *reinterpret_cast<uint4*>(dst + (size_t)j * 8) = *reinterpret_cast<uint4*>(hh);
}

// ---------------------------------------------------------------------------
// k softmax over c per (b,n), IN PLACE on fp16 qkv k-block [C,N].
// ---------------------------------------------------------------------------
__global__ __launch_bounds__(512) void ksoftmax_kernel() {
    int b = blockIdx.x >> 5;
    int n0 = (blockIdx.x & 31) * 32;
    __half* base = g_qkvf + (size_t)b * C3 * NTOK + (size_t)CH * NTOK + n0;
    int lane = threadIdx.x & 31, j = threadIdx.x >> 5;

    float mx = -1e30f, sum = 0.f;
    for (int i = 0; i < 32; i++) {
        float v = __half2float(base[(size_t)(j * 32 + i) * NTOK + lane]);
        float nm = fmaxf(mx, v);
        sum = sum * __expf(mx - nm) + __expf(v - nm);
        mx = nm;
    }
    __shared__ float sM[16][32], sS[16][32];
    sM[j][lane] = mx; sS[j][lane] = sum;
    __syncthreads();
    if (j == 0) {
        float M = sM[0][lane], S = sS[0][lane];
#pragma unroll
        for (int t = 1; t < 16; t++) {
            float m2 = sM[t][lane], s2 = sS[t][lane];
            float nm = fmaxf(M, m2);
            S = S * __expf(M - nm) + s2 * __expf(m2 - nm);
            M = nm;
        }
        sM[0][lane] = M; sS[0][lane] = 1.f / S;
    }
    __syncthreads();
    float M = sM[0][lane], inv = sS[0][lane];
    for (int i = 0; i < 32; i++) {
        size_t idx = (size_t)(j * 32 + i) * NTOK + lane;
        base[idx] = __float2half_rn(__expf(__half2float(base[idx]) - M) * inv);
    }
}

// ---------------------------------------------------------------------------
// q softmax over n per (b,c): reads fp16 q rows, writes TRANSPOSED qT [N,C].
// ---------------------------------------------------------------------------
__global__ __launch_bounds__(256) void qsoftmax_kernel() {
    int b = blockIdx.x >> 5, c0 = (blockIdx.x & 31) * 16;
    const __half* base = g_qkvf + (size_t)b * C3 * NTOK;
    int t = threadIdx.x;
    int cr = t >> 4, sub = t & 15;
    const __half* rp = base + (size_t)(c0 + cr) * NTOK + sub * 64;

    float mx = -1e30f, sum = 0.f;
#pragma unroll
    for (int i = 0; i < 8; i++) {
        uint4 u = *reinterpret_cast<const uint4*>(rp + i * 8);
        const __half2* hp = reinterpret_cast<const __half2*>(&u);
#pragma unroll
        for (int q = 0; q < 4; q++) {
            float2 f = __half22float2(hp[q]);
            float m2 = fmaxf(f.x, f.y);
            float nm = fmaxf(mx, m2);
            sum = sum * __expf(mx - nm) + __expf(f.x - nm) + __expf(f.y - nm);
            mx = nm;
        }
    }
#pragma unroll
    for (int o = 8; o >= 1; o >>= 1) {
        float m2 = __shfl_xor_sync(0xFFFFFFFFu, mx, o);
        float s2 = __shfl_xor_sync(0xFFFFFFFFu, sum, o);
        float nm = fmaxf(mx, m2);
        sum = sum * __expf(mx - nm) + s2 * __expf(m2 - nm);
        mx = nm;
    }
    __shared__ float sM[16], sI[16];
    if (sub == 0) { sM[cr] = mx; sI[cr] = 1.f / sum; }
    __syncthreads();
    float M = sM[cr], inv = sI[cr];

    __shared__ __half th[64][24];
    for (int tn = 0; tn < 16; tn++) {
        uint2 u = *reinterpret_cast<const uint2*>(
            base + (size_t)(c0 + cr) * NTOK + tn * 64 + sub * 4);
        const __half2* hp = reinterpret_cast<const __half2*>(&u);
        float2 f0 = __half22float2(hp[0]), f1 = __half22float2(hp[1]);
        th[sub * 4 + 0][cr] = __float2half_rn(__expf(f0.x - M) * inv);
        th[sub * 4 + 1][cr] = __float2half_rn(__expf(f0.y - M) * inv);
        th[sub * 4 + 2][cr] = __float2half_rn(__expf(f1.x - M) * inv);
        th[sub * 4 + 3][cr] = __float2half_rn(__expf(f1.y - M) * inv);
        __syncthreads();
        if (t < 128) {
            int nl = t >> 1, chn = t & 1;
            size_t dst = ((size_t)b * NTOK + tn * 64 + nl) * CH + c0 + chn * 8;
            *reinterpret_cast<uint4*>(&g_qTh[dst]) = *reinterpret_cast<uint4*>(&th[nl][chn * 8]);
        }
        __syncthreads();
    }
}

// ---------------------------------------------------------------------------
// Launch
// ---------------------------------------------------------------------------
extern "C" void kernel_launch(void* const* d_in, const int* in_sizes, int n_in,
                              void* d_out, int out_size) {
    const float* x      = (const float*)d_in[0];
    const float* gn_w   = (const float*)d_in[1];
    const float* gn_b   = (const float*)d_in[2];
    const float* qkv_w  = (const float*)d_in[3];
    const float* qkv_b  = (const float*)d_in[4];
    const float* proj_w = (const float*)d_in[5];
    const float* proj_b = (const float*)d_in[6];
    float* out = (float*)d_out;

    void* p;
    cudaGetSymbolAddress(&p, g_xn);   float* xn   = (float*)p;
    cudaGetSymbolAddress(&p, g_qkvf); __half* qkvf = (__half*)p;
    cudaGetSymbolAddress(&p, g_xnTh); __half* xnTh = (__half*)p;
    cudaGetSymbolAddress(&p, g_w1f);  __half* w1f = (__half*)p;
    cudaGetSymbolAddress(&p, g_w2f);  __half* w2f = (__half*)p;
    cudaGetSymbolAddress(&p, g_qTh);  __half* qTh = (__half*)p;
    cudaGetSymbolAddress(&p, g_ctxT); __half* ctxT = (__half*)p;
    cudaGetSymbolAddress(&p, g_m2);   __half* m2 = (__half*)p;

    constexpr int SMB1 = (64 + 128) * 64 * 3;    // 36864 (MWT=1)
    constexpr int SMB2 = (128 + 128) * 64 * 3;   // 49152 (MWT=2)
    cudaFuncSetAttribute(gemmf16<2, 1>, cudaFuncAttributeMaxDynamicSharedMemorySize, SMB2);
    cudaFuncSetAttribute(gemmf16<1, 0>, cudaFuncAttributeMaxDynamicSharedMemorySize, SMB1);
    cudaFuncSetAttribute(gemmf16<2, 2>, cudaFuncAttributeMaxDynamicSharedMemorySize, SMB2);

    // 0) weight fp16 (single launch)
    conv_all_kernel<<<((C3 * CH + CH * CH) / 8 + 255) / 256, 256>>>(qkv_w, proj_w);

    // 1) GroupNorm (two-pass, full-chip grids)
    gn_sum_kernel<<<BATCH * GRP * 8, 256>>>(x);
    gn_norm_kernel<<<BATCH * GRP * 8, 256>>>(x, gn_w, gn_b);

    // 2) GEMM1 (MWT=2, EP1): qkv fp16 [3C,N] + bias. M=1536 N=1024 K=512
    gemmf16<2, 1><<<dim3(NTOK / 128, C3 / 128, BATCH), 256, SMB2>>>(
        w1f, xnTh, nullptr, qkvf,
        CH, CH, CH, NTOK,
        0LL, (long long)NTOK * CH, 0LL, (long long)C3 * NTOK,
        qkv_b, nullptr);

    // 3) softmaxes (k in place; q -> transposed plane)
    ksoftmax_kernel<<<BATCH * 32, 512>>>();
    qsoftmax_kernel<<<BATCH * 32, 256>>>();

    // 4) GEMM2 (MWT=1, EP0): ctxT[c,d] = sum_n k[c,n]*v[d,n]. M=512 N=512 K=1024
    //    A = k (softmaxed in place), B = v.
    gemmf16<1, 0><<<dim3(CH / 128, CH / 64, BATCH), 256, SMB1>>>(
        qkvf + (size_t)CH * NTOK, qkvf + (size_t)2 * CH * NTOK, nullptr, ctxT,
        NTOK, NTOK, NTOK, CH,
        (long long)C3 * NTOK, (long long)C3 * NTOK, 0LL, (long long)CH * CH,
        nullptr, nullptr);

    // 5) GEMM3' (MWT=1, EP0): M2[d,c] = sum_c' w2[d,c']*ctxT[c,c']. M=512 N=512 K=512
    gemmf16<1, 0><<<dim3(CH / 128, CH / 64, BATCH), 256, SMB1>>>(
        w2f, ctxT, nullptr, m2,
        CH, CH, CH, CH,
        0LL, (long long)CH * CH, 0LL, (long long)CH * CH,
        nullptr, nullptr);

    // 6) GEMM4' (MWT=2, EP2): out[d,n] = sum_c M2[d,c]*qT[n,c] + b + xn. M=512 N=1024 K=512
    gemmf16<2, 2><<<dim3(NTOK / 128, CH / 128, BATCH), 256, SMB2>>>(
        m2, qTh, out, nullptr,
        CH, CH, CH, NTOK,
        (long long)CH * CH, (long long)NTOK * CH, (long long)CH * NTOK, 0LL,
        proj_b, xn);
}

// round 14
// speedup vs baseline: 5.2773x; 1.0466x over previous
#include <cuda_runtime.h>
#include <cuda_fp16.h>
#include <cstdint>

#define BATCH 8
#define CH    512
#define NTOK  1024
#define C3    1536
#define GRP   8
#define CPG   64
#define GSIZE 65536

// ---------------- scratch (device globals) ----------------
__device__ float g_xn  [BATCH * CH * NTOK];            // fp32 residual [B,C,N]
__device__ float g_gnp [BATCH * GRP * 8 * 2];          // gn partial sums
__device__ __half g_qkvf[BATCH * C3 * NTOK];           // qkv fp16 [B,3C,N]; k softmaxed in place
__device__ __half g_xnTh[BATCH * NTOK * CH];           // xn^T fp16 [B,N,C]
__device__ __half g_w1f[C3 * CH];                      // w1 fp16
__device__ __half g_w2f[CH * CH];                      // w2 fp16
__device__ __half g_qTh[BATCH * NTOK * CH];            // qT fp16 [N,C]
__device__ __half g_ctxT[BATCH * CH * CH];             // ctx^T fp16 [c,d]
__device__ __half g_m2[BATCH * CH * CH];               // M2 = w2*ctx fp16 [d,c]

// ---------------- helpers ----------------
__device__ __forceinline__ uint32_t smem_u32(const void* p) {
    uint32_t a;
    asm("{ .reg .u64 t; cvta.to.shared.u64 t, %1; cvt.u32.u64 %0, t; }" : "=r"(a) : "l"(p));
    return a;
}
__device__ __forceinline__ void mmaf16(float* c, uint32_t a0, uint32_t a1,
                                       uint32_t a2, uint32_t a3,
                                       uint32_t b0, uint32_t b1) {
    asm volatile(
        "mma.sync.aligned.m16n8k16.row.col.f32.f16.f16.f32 "
        "{%0,%1,%2,%3},{%4,%5,%6,%7},{%8,%9},{%0,%1,%2,%3};"
        : "+f"(c[0]), "+f"(c[1]), "+f"(c[2]), "+f"(c[3])
        : "r"(a0), "r"(a1), "r"(a2), "r"(a3), "r"(b0), "r"(b1));
}
__device__ __forceinline__ void ldm4(uint32_t& r0, uint32_t& r1, uint32_t& r2,
                                     uint32_t& r3, uint32_t a) {
    asm volatile("ldmatrix.sync.aligned.m8n8.x4.shared.b16 {%0,%1,%2,%3}, [%4];"
                 : "=r"(r0), "=r"(r1), "=r"(r2), "=r"(r3) : "r"(a));
}
#define CPA16(d, s) asm volatile("cp.async.cg.shared.global [%0], [%1], 16;" :: "r"(d), "l"(s))
#define CPCOMMIT()  asm volatile("cp.async.commit_group;")
#define CPWAIT0()   asm volatile("cp.async.wait_group 0;" ::: "memory")

// swizzled byte offset: 128B rows, 16B chunk c (0..7), row r
__device__ __forceinline__ uint32_t swz(int r, int c) {
    return (uint32_t)(r * 128 + ((c ^ (r & 7)) << 4));
}

// ---------------------------------------------------------------------------
// fp16 single-pass tensor-core GEMM, BK=64, 2-stage cp.async double buffer.
// D[BM x 128] = sum_k A(m,k)*B(n,k), BM = 64*MWT.
// EP 0: fp16 plane, no bias.  EP 1: fp16 plane + bias[m].
// EP 2: fp32 + bias[m] + resid[m*ldc+n].
// ---------------------------------------------------------------------------
template <int MWT, int EP>
__global__ __launch_bounds__(256, (MWT == 1 ? 4 : 2)) void gemmf16(
    const __half* __restrict__ Ah, const __half* __restrict__ Bh,
    float* __restrict__ C, __half* __restrict__ Ch,
    int K, int lda, int ldb, int ldc,
    long long sA, long long sB, long long sC, long long sCp,
    const float* __restrict__ bias, const float* __restrict__ resid)
{
    constexpr int BM = 64 * MWT, BN = 128;
    constexpr int NMT = 2 * MWT;
    constexpr int BOB = BM * 128;               // B plane byte offset in stage
    constexpr int SSB = (BM + BN) * 128;        // stage bytes
    constexpr int ITA = (BM * 8) / 256;         // A fill iters (chunks of 16B)
    constexpr int ITB = (BN * 8) / 256;         // B fill iters

    extern __shared__ __align__(128) __half smbuf[];
    const uint32_t su = smem_u32(smbuf);
    const int tid = threadIdx.x;
    const int bz = blockIdx.z;
    Ah += (size_t)bz * sA;
    Bh += (size_t)bz * sB;
    const int m0 = blockIdx.y * BM, n0 = blockIdx.x * BN;

    const int lane = tid & 31, wid = tid >> 5;
    const int g = lane >> 2, tg = lane & 3;
    const int wm = (wid & 1) * 32 * MWT, wn = (wid >> 1) * 32;
    const int lr = lane & 15, lchunk = lane >> 4;

    float acc[NMT][4][4];
#pragma unroll
    for (int i = 0; i < NMT; i++)
#pragma unroll
        for (int j = 0; j < 4; j++)
#pragma unroll
            for (int q = 0; q < 4; q++) acc[i][j][q] = 0.f;

    auto fill = [&](int st, int k0) {
        uint32_t base = su + (uint32_t)(st * SSB);
#pragma unroll
        for (int i = 0; i < ITA; i++) {
            int idx = tid + 256 * i;
            int row = idx >> 3, ch = idx & 7;
            CPA16(base + swz(row, ch), Ah + (size_t)(m0 + row) * lda + k0 + ch * 8);
        }
#pragma unroll
        for (int i = 0; i < ITB; i++) {
            int idx = tid + 256 * i;
            int row = idx >> 3, ch = idx & 7;
            CPA16(base + BOB + swz(row, ch), Bh + (size_t)(n0 + row) * ldb + k0 + ch * 8);
        }
        CPCOMMIT();
    };

    const int NC = K / 64;
    fill(0, 0);

    for (int c = 0; c < NC; c++) {
        CPWAIT0();
        __syncthreads();
        if (c + 1 < NC) fill((c + 1) & 1, (c + 1) * 64);
        const uint32_t sb = su + (uint32_t)((c & 1) * SSB);

#pragma unroll
        for (int ks = 0; ks < 64; ks += 16) {
            const int kc = (ks >> 3) + lchunk;    // 0..7
            uint32_t Bf[8];
#pragma unroll
            for (int pr = 0; pr < 2; pr++) {
                int r = wn + pr * 16 + lr;
                ldm4(Bf[pr * 4 + 0], Bf[pr * 4 + 1], Bf[pr * 4 + 2], Bf[pr * 4 + 3],
                     sb + BOB + swz(r, kc));
            }
            uint32_t Af[NMT][4];
#pragma unroll
            for (int mt = 0; mt < NMT; mt++) {
                int r = wm + mt * 16 + lr;
                ldm4(Af[mt][0], Af[mt][1], Af[mt][2], Af[mt][3], sb + swz(r, kc));
            }
#pragma unroll
            for (int mt = 0; mt < NMT; mt++)
#pragma unroll
                for (int nt = 0; nt < 4; nt++) {
                    int i0 = (nt >> 1) * 4 + (nt & 1);
                    mmaf16(acc[mt][nt], Af[mt][0], Af[mt][1], Af[mt][2], Af[mt][3],
                           Bf[i0], Bf[i0 + 2]);
                }
        }
    }

    // ---- epilogue ----
    if (EP <= 1) {
        __half* Chp = Ch + (size_t)bz * sCp;
#pragma unroll
        for (int mt = 0; mt < NMT; mt++) {
            int m = m0 + wm + mt * 16 + g;
            float bv0 = (EP == 1) ? bias[m] : 0.f;
            float bv1 = (EP == 1) ? bias[m + 8] : 0.f;
#pragma unroll
            for (int nt = 0; nt < 4; nt++) {
                int n = n0 + wn + nt * 8 + tg * 2;
                float* a = acc[mt][nt];
                size_t i0 = (size_t)m * ldc + n;
                size_t i1 = (size_t)(m + 8) * ldc + n;
                *reinterpret_cast<__half2*>(Chp + i0) =
                    __half2(__float2half_rn(a[0] + bv0), __float2half_rn(a[1] + bv0));
                *reinterpret_cast<__half2*>(Chp + i1) =
                    __half2(__float2half_rn(a[2] + bv1), __float2half_rn(a[3] + bv1));
            }
        }
    } else {
        float* Cp = C + (size_t)bz * sC;
        const float* R = resid + (size_t)bz * sC;
#pragma unroll
        for (int mt = 0; mt < NMT; mt++) {
            int m = m0 + wm + mt * 16 + g;
            float bv0 = bias[m], bv1 = bias[m + 8];
#pragma unroll
            for (int nt = 0; nt < 4; nt++) {
                int n = n0 + wn + nt * 8 + tg * 2;
                float* a = acc[mt][nt];
                size_t i0 = (size_t)m * ldc + n;
                size_t i1 = (size_t)(m + 8) * ldc + n;
                float2 r0 = *reinterpret_cast<const float2*>(R + i0);
                float2 r1 = *reinterpret_cast<const float2*>(R + i1);
                float2 o0, o1;
                o0.x = a[0] + bv0 + r0.x; o0.y = a[1] + bv0 + r0.y;
                o1.x = a[2] + bv1 + r1.x; o1.y = a[3] + bv1 + r1.y;
                *reinterpret_cast<float2*>(Cp + i0) = o0;
                *reinterpret_cast<float2*>(Cp + i1) = o1;
            }
        }
    }
}

// ---------------------------------------------------------------------------
// GroupNorm pass 1: partial sums.
// ---------------------------------------------------------------------------
__global__ __launch_bounds__(256) void gn_sum_kernel(const float* __restrict__ x) {
    int bg = blockIdx.x >> 3, slice = blockIdx.x & 7;
    const float4* xp = reinterpret_cast<const float4*>(
        x + (size_t)bg * GSIZE + slice * 8192);
    int t = threadIdx.x;
    float s = 0.f, sq = 0.f;
#pragma unroll
    for (int i = 0; i < 8; i++) {
        float4 v = xp[t + 256 * i];
        s  += v.x + v.y + v.z + v.w;
        sq += v.x * v.x + v.y * v.y + v.z * v.z + v.w * v.w;
    }
#pragma unroll
    for (int o = 16; o >= 1; o >>= 1) {
        s  += __shfl_xor_sync(0xFFFFFFFFu, s, o);
        sq += __shfl_xor_sync(0xFFFFFFFFu, sq, o);
    }
    __shared__ float rs[8], rq[8];
    if ((t & 31) == 0) { rs[t >> 5] = s; rq[t >> 5] = sq; }
    __syncthreads();
    if (t == 0) {
        float S = 0.f, Q = 0.f;
#pragma unroll
        for (int i = 0; i < 8; i++) { S += rs[i]; Q += rq[i]; }
        g_gnp[(bg * 8 + slice) * 2 + 0] = S;
        g_gnp[(bg * 8 + slice) * 2 + 1] = Q;
    }
}

// ---------------------------------------------------------------------------
// GroupNorm pass 2: normalize + fp32 residual + transposed fp16 plane.
// ---------------------------------------------------------------------------
__global__ __launch_bounds__(256) void gn_norm_kernel(const float* __restrict__ x,
                                                      const float* __restrict__ gamma,
                                                      const float* __restrict__ beta) {
    int bg = blockIdx.x >> 3, slice = blockIdx.x & 7;
    int b = bg >> 3, g = bg & 7;
    int n0 = slice * 128;
    int t = threadIdx.x;

    float S = 0.f, Q = 0.f;
#pragma unroll
    for (int i = 0; i < 8; i++) {
        S += g_gnp[(bg * 8 + i) * 2 + 0];
        Q += g_gnp[(bg * 8 + i) * 2 + 1];
    }
    float mean = S * (1.f / GSIZE);
    float var  = Q * (1.f / GSIZE) - mean * mean;
    float rstd = rsqrtf(var + 1e-5f);

    int c = t >> 2, sub = t & 3;
    float gm = gamma[g * CPG + c] * rstd;
    float bt = beta[g * CPG + c] - mean * gm;

    size_t rowoff = ((size_t)b * CH + g * CPG + c) * NTOK + n0;
    const float4* xp = reinterpret_cast<const float4*>(x + rowoff);
    float4* gp = reinterpret_cast<float4*>(g_xn + rowoff);

    __shared__ __half th[128][72];
#pragma unroll
    for (int i = 0; i < 8; i++) {
        int nq = sub * 8 + i;
        float4 v = xp[nq];
        v.x = v.x * gm + bt; v.y = v.y * gm + bt;
        v.z = v.z * gm + bt; v.w = v.w * gm + bt;
        gp[nq] = v;
        th[nq * 4 + 0][c] = __float2half_rn(v.x);
        th[nq * 4 + 1][c] = __float2half_rn(v.y);
        th[nq * 4 + 2][c] = __float2half_rn(v.z);
        th[nq * 4 + 3][c] = __float2half_rn(v.w);
    }
    __syncthreads();
#pragma unroll
    for (int it = 0; it < 4; it++) {
        int idx = t + 256 * it;
        int nl = idx >> 3, c8 = idx & 7;
        size_t dst = ((size_t)b * NTOK + n0 + nl) * CH + g * CPG + c8 * 8;
        *reinterpret_cast<uint4*>(&g_xnTh[dst]) = *reinterpret_cast<uint4*>(&th[nl][c8 * 8]);
    }
}

// ---------------------------------------------------------------------------
// Weight convert: both weights in one launch.
// ---------------------------------------------------------------------------
__global__ void conv_all_kernel(const float* __restrict__ w1, const float* __restrict__ w2) {
    int i = blockIdx.x * 256 + threadIdx.x;
    const int n1 = C3 * CH / 8, n2 = CH * CH / 8;
    if (i >= n1 + n2) return;
    const float* src = (i < n1) ? w1 : w2;
    __half* dst = (i < n1) ? g_w1f : g_w2f;
    int j = (i < n1) ? i : i - n1;
    const float4* s = reinterpret_cast<const float4*>(src) + j * 2;
    float4 v0 = s[0], v1 = s[1];
    __half hh[8];
    hh[0] = __float2half_rn(v0.x); hh[1] = __float2half_rn(v0.y);
    hh[2] = __float2half_rn(v0.z); hh[3] = __float2half_rn(v0.w);
    hh[4] = __float2half_rn(v1.x); hh[5] = __float2half_rn(v1.y);
    hh[6] = __float2half_rn(v1.z); hh[7] = __float2half_rn(v1.w);
    *reinterpret_cast<uint4*>(dst + (size_t)j * 8) = *reinterpret_cast<uint4*>(hh);
}

// ---------------------------------------------------------------------------
// k softmax over c per (b,n), IN PLACE on fp16 qkv k-block [C,N].
// ---------------------------------------------------------------------------
__global__ __launch_bounds__(512) void ksoftmax_kernel() {
    int b = blockIdx.x >> 5;
    int n0 = (blockIdx.x & 31) * 32;
    __half* base = g_qkvf + (size_t)b * C3 * NTOK + (size_t)CH * NTOK + n0;
    int lane = threadIdx.x & 31, j = threadIdx.x >> 5;

    float mx = -1e30f, sum = 0.f;
    for (int i = 0; i < 32; i++) {
        float v = __half2float(base[(size_t)(j * 32 + i) * NTOK + lane]);
        float nm = fmaxf(mx, v);
        sum = sum * __expf(mx - nm) + __expf(v - nm);
        mx = nm;
    }
    __shared__ float sM[16][32], sS[16][32];
    sM[j][lane] = mx; sS[j][lane] = sum;
    __syncthreads();
    if (j == 0) {
        float M = sM[0][lane], S = sS[0][lane];
#pragma unroll
        for (int t = 1; t < 16; t++) {
            float m2 = sM[t][lane], s2 = sS[t][lane];
            float nm = fmaxf(M, m2);
            S = S * __expf(M - nm) + s2 * __expf(m2 - nm);
            M = nm;
        }
        sM[0][lane] = M; sS[0][lane] = 1.f / S;
    }
    __syncthreads();
    float M = sM[0][lane], inv = sS[0][lane];
    for (int i = 0; i < 32; i++) {
        size_t idx = (size_t)(j * 32 + i) * NTOK + lane;
        base[idx] = __float2half_rn(__expf(__half2float(base[idx]) - M) * inv);
    }
}

// ---------------------------------------------------------------------------
// q softmax over n per (b,c): reads fp16 q rows, writes TRANSPOSED qT [N,C].
// ---------------------------------------------------------------------------
__global__ __launch_bounds__(256) void qsoftmax_kernel() {
    int b = blockIdx.x >> 5, c0 = (blockIdx.x & 31) * 16;
    const __half* base = g_qkvf + (size_t)b * C3 * NTOK;
    int t = threadIdx.x;
    int cr = t >> 4, sub = t & 15;
    const __half* rp = base + (size_t)(c0 + cr) * NTOK + sub * 64;

    float mx = -1e30f, sum = 0.f;
#pragma unroll
    for (int i = 0; i < 8; i++) {
        uint4 u = *reinterpret_cast<const uint4*>(rp + i * 8);
        const __half2* hp = reinterpret_cast<const __half2*>(&u);
#pragma unroll
        for (int q = 0; q < 4; q++) {
            float2 f = __half22float2(hp[q]);
            float m2 = fmaxf(f.x, f.y);
            float nm = fmaxf(mx, m2);
            sum = sum * __expf(mx - nm) + __expf(f.x - nm) + __expf(f.y - nm);
            mx = nm;
        }
    }
#pragma unroll
    for (int o = 8; o >= 1; o >>= 1) {
        float m2 = __shfl_xor_sync(0xFFFFFFFFu, mx, o);
        float s2 = __shfl_xor_sync(0xFFFFFFFFu, sum, o);
        float nm = fmaxf(mx, m2);
        sum = sum * __expf(mx - nm) + s2 * __expf(m2 - nm);
        mx = nm;
    }
    __shared__ float sM[16], sI[16];
    if (sub == 0) { sM[cr] = mx; sI[cr] = 1.f / sum; }
    __syncthreads();
    float M = sM[cr], inv = sI[cr];

    __shared__ __half th[64][24];
    for (int tn = 0; tn < 16; tn++) {
        uint2 u = *reinterpret_cast<const uint2*>(
            base + (size_t)(c0 + cr) * NTOK + tn * 64 + sub * 4);
        const __half2* hp = reinterpret_cast<const __half2*>(&u);
        float2 f0 = __half22float2(hp[0]), f1 = __half22float2(hp[1]);
        th[sub * 4 + 0][cr] = __float2half_rn(__expf(f0.x - M) * inv);
        th[sub * 4 + 1][cr] = __float2half_rn(__expf(f0.y - M) * inv);
        th[sub * 4 + 2][cr] = __float2half_rn(__expf(f1.x - M) * inv);
        th[sub * 4 + 3][cr] = __float2half_rn(__expf(f1.y - M) * inv);
        __syncthreads();
        if (t < 128) {
            int nl = t >> 1, chn = t & 1;
            size_t dst = ((size_t)b * NTOK + tn * 64 + nl) * CH + c0 + chn * 8;
            *reinterpret_cast<uint4*>(&g_qTh[dst]) = *reinterpret_cast<uint4*>(&th[nl][chn * 8]);
        }
        __syncthreads();
    }
}

// ---------------------------------------------------------------------------
// Launch
// ---------------------------------------------------------------------------
extern "C" void kernel_launch(void* const* d_in, const int* in_sizes, int n_in,
                              void* d_out, int out_size) {
    const float* x      = (const float*)d_in[0];
    const float* gn_w   = (const float*)d_in[1];
    const float* gn_b   = (const float*)d_in[2];
    const float* qkv_w  = (const float*)d_in[3];
    const float* qkv_b  = (const float*)d_in[4];
    const float* proj_w = (const float*)d_in[5];
    const float* proj_b = (const float*)d_in[6];
    float* out = (float*)d_out;

    void* p;
    cudaGetSymbolAddress(&p, g_xn);   float* xn   = (float*)p;
    cudaGetSymbolAddress(&p, g_qkvf); __half* qkvf = (__half*)p;
    cudaGetSymbolAddress(&p, g_xnTh); __half* xnTh = (__half*)p;
    cudaGetSymbolAddress(&p, g_w1f);  __half* w1f = (__half*)p;
    cudaGetSymbolAddress(&p, g_w2f);  __half* w2f = (__half*)p;
    cudaGetSymbolAddress(&p, g_qTh);  __half* qTh = (__half*)p;
    cudaGetSymbolAddress(&p, g_ctxT); __half* ctxT = (__half*)p;
    cudaGetSymbolAddress(&p, g_m2);   __half* m2 = (__half*)p;

    constexpr int SMB1 = (64 + 128) * 128 * 2;    // 49152 (MWT=1)
    constexpr int SMB2 = (128 + 128) * 128 * 2;   // 65536 (MWT=2)
    cudaFuncSetAttribute(gemmf16<2, 1>, cudaFuncAttributeMaxDynamicSharedMemorySize, SMB2);
    cudaFuncSetAttribute(gemmf16<1, 0>, cudaFuncAttributeMaxDynamicSharedMemorySize, SMB1);
    cudaFuncSetAttribute(gemmf16<2, 2>, cudaFuncAttributeMaxDynamicSharedMemorySize, SMB2);

    // 0) weight fp16 (single launch)
    conv_all_kernel<<<((C3 * CH + CH * CH) / 8 + 255) / 256, 256>>>(qkv_w, proj_w);

    // 1) GroupNorm (two-pass, full-chip grids)
    gn_sum_kernel<<<BATCH * GRP * 8, 256>>>(x);
    gn_norm_kernel<<<BATCH * GRP * 8, 256>>>(x, gn_w, gn_b);

    // 2) GEMM1 (MWT=2, EP1): qkv fp16 [3C,N] + bias. M=1536 N=1024 K=512
    gemmf16<2, 1><<<dim3(NTOK / 128, C3 / 128, BATCH), 256, SMB2>>>(
        w1f, xnTh, nullptr, qkvf,
        CH, CH, CH, NTOK,
        0LL, (long long)NTOK * CH, 0LL, (long long)C3 * NTOK,
        qkv_b, nullptr);

    // 3) softmaxes (k in place; q -> transposed plane)
    ksoftmax_kernel<<<BATCH * 32, 512>>>();
    qsoftmax_kernel<<<BATCH * 32, 256>>>();

    // 4) GEMM2 (MWT=1, EP0): ctxT[c,d] = sum_n k[c,n]*v[d,n]. M=512 N=512 K=1024
    gemmf16<1, 0><<<dim3(CH / 128, CH / 64, BATCH), 256, SMB1>>>(
        qkvf + (size_t)CH * NTOK, qkvf + (size_t)2 * CH * NTOK, nullptr, ctxT,
        NTOK, NTOK, NTOK, CH,
        (long long)C3 * NTOK, (long long)C3 * NTOK, 0LL, (long long)CH * CH,
        nullptr, nullptr);

    // 5) GEMM3' (MWT=1, EP0): M2[d,c] = sum_c' w2[d,c']*ctxT[c,c']. M=512 N=512 K=512
    gemmf16<1, 0><<<dim3(CH / 128, CH / 64, BATCH), 256, SMB1>>>(
        w2f, ctxT, nullptr, m2,
        CH, CH, CH, CH,
        0LL, (long long)CH * CH, 0LL, (long long)CH * CH,
        nullptr, nullptr);

    // 6) GEMM4' (MWT=2, EP2): out[d,n] = sum_c M2[d,c]*qT[n,c] + b + xn. M=512 N=1024 K=512
    gemmf16<2, 2><<<dim3(NTOK / 128, CH / 128, BATCH), 256, SMB2>>>(
        m2, qTh, out, nullptr,
        CH, CH, CH, NTOK,
        (long long)CH * CH, (long long)NTOK * CH, (long long)CH * NTOK, 0LL,
        proj_b, xn);
}

// round 15
// speedup vs baseline: 5.4709x; 1.0367x over previous
#include <cuda_runtime.h>
#include <cuda_fp16.h>
#include <cstdint>

#define BATCH 8
#define CH    512
#define NTOK  1024
#define C3    1536
#define GRP   8
#define CPG   64
#define GSIZE 65536

// ---------------- scratch (device globals) ----------------
__device__ float g_xn  [BATCH * CH * NTOK];            // fp32 residual [B,C,N]
__device__ float g_gnp [BATCH * GRP * 8 * 2];          // gn partial sums
__device__ __half g_qkvf[BATCH * C3 * NTOK];           // qkv fp16 [B,3C,N]; k softmaxed in place
__device__ __half g_xnTh[BATCH * NTOK * CH];           // xn^T fp16 [B,N,C]
__device__ __half g_w1f[C3 * CH];                      // w1 fp16
__device__ __half g_w2f[CH * CH];                      // w2 fp16
__device__ __half g_qTh[BATCH * NTOK * CH];            // qT fp16 [N,C]
__device__ __half g_ctxT[BATCH * CH * CH];             // ctx^T fp16 [c,d]
__device__ __half g_m2[BATCH * CH * CH];               // M2 = w2*ctx fp16 [d,c]

// ---------------- helpers ----------------
__device__ __forceinline__ uint32_t smem_u32(const void* p) {
    uint32_t a;
    asm("{ .reg .u64 t; cvta.to.shared.u64 t, %1; cvt.u32.u64 %0, t; }" : "=r"(a) : "l"(p));
    return a;
}
__device__ __forceinline__ void mmaf16(float* c, uint32_t a0, uint32_t a1,
                                       uint32_t a2, uint32_t a3,
                                       uint32_t b0, uint32_t b1) {
    asm volatile(
        "mma.sync.aligned.m16n8k16.row.col.f32.f16.f16.f32 "
        "{%0,%1,%2,%3},{%4,%5,%6,%7},{%8,%9},{%0,%1,%2,%3};"
        : "+f"(c[0]), "+f"(c[1]), "+f"(c[2]), "+f"(c[3])
        : "r"(a0), "r"(a1), "r"(a2), "r"(a3), "r"(b0), "r"(b1));
}
__device__ __forceinline__ void ldm4(uint32_t& r0, uint32_t& r1, uint32_t& r2,
                                     uint32_t& r3, uint32_t a) {
    asm volatile("ldmatrix.sync.aligned.m8n8.x4.shared.b16 {%0,%1,%2,%3}, [%4];"
                 : "=r"(r0), "=r"(r1), "=r"(r2), "=r"(r3) : "r"(a));
}
#define CPA16(d, s) asm volatile("cp.async.cg.shared.global [%0], [%1], 16;" :: "r"(d), "l"(s))
#define CPCOMMIT()  asm volatile("cp.async.commit_group;")
#define CPWAIT0()   asm volatile("cp.async.wait_group 0;" ::: "memory")

// swizzled byte offset: 128B rows, 16B chunk c (0..7), row r
__device__ __forceinline__ uint32_t swz(int r, int c) {
    return (uint32_t)(r * 128 + ((c ^ (r & 7)) << 4));
}

// ---------------------------------------------------------------------------
// fp16 single-pass tensor-core GEMM, BK=64, 2-stage cp.async double buffer.
// D[BM x 128] = sum_k A(m,k)*B(n,k), BM = 64*MWT.
// EP 0: fp16 plane, no bias.  EP 1: fp16 plane + bias[m].
// EP 2: fp32 + bias[m] + resid[m*ldc+n].
// ---------------------------------------------------------------------------
template <int MWT, int EP>
__global__ __launch_bounds__(256, (MWT == 1 ? 4 : 2)) void gemmf16(
    const __half* __restrict__ Ah, const __half* __restrict__ Bh,
    float* __restrict__ C, __half* __restrict__ Ch,
    int K, int lda, int ldb, int ldc,
    long long sA, long long sB, long long sC, long long sCp,
    const float* __restrict__ bias, const float* __restrict__ resid)
{
    constexpr int BM = 64 * MWT, BN = 128;
    constexpr int NMT = 2 * MWT;
    constexpr int BOB = BM * 128;
    constexpr int SSB = (BM + BN) * 128;
    constexpr int ITA = (BM * 8) / 256;
    constexpr int ITB = (BN * 8) / 256;

    extern __shared__ __align__(128) __half smbuf[];
    const uint32_t su = smem_u32(smbuf);
    const int tid = threadIdx.x;
    const int bz = blockIdx.z;
    Ah += (size_t)bz * sA;
    Bh += (size_t)bz * sB;
    const int m0 = blockIdx.y * BM, n0 = blockIdx.x * BN;

    const int lane = tid & 31, wid = tid >> 5;
    const int g = lane >> 2, tg = lane & 3;
    const int wm = (wid & 1) * 32 * MWT, wn = (wid >> 1) * 32;
    const int lr = lane & 15, lchunk = lane >> 4;

    float acc[NMT][4][4];
#pragma unroll
    for (int i = 0; i < NMT; i++)
#pragma unroll
        for (int j = 0; j < 4; j++)
#pragma unroll
            for (int q = 0; q < 4; q++) acc[i][j][q] = 0.f;

    auto fill = [&](int st, int k0) {
        uint32_t base = su + (uint32_t)(st * SSB);
#pragma unroll
        for (int i = 0; i < ITA; i++) {
            int idx = tid + 256 * i;
            int row = idx >> 3, ch = idx & 7;
            CPA16(base + swz(row, ch), Ah + (size_t)(m0 + row) * lda + k0 + ch * 8);
        }
#pragma unroll
        for (int i = 0; i < ITB; i++) {
            int idx = tid + 256 * i;
            int row = idx >> 3, ch = idx & 7;
            CPA16(base + BOB + swz(row, ch), Bh + (size_t)(n0 + row) * ldb + k0 + ch * 8);
        }
        CPCOMMIT();
    };

    const int NC = K / 64;
    fill(0, 0);

    for (int c = 0; c < NC; c++) {
        CPWAIT0();
        __syncthreads();
        if (c + 1 < NC) fill((c + 1) & 1, (c + 1) * 64);
        const uint32_t sb = su + (uint32_t)((c & 1) * SSB);

#pragma unroll
        for (int ks = 0; ks < 64; ks += 16) {
            const int kc = (ks >> 3) + lchunk;
            uint32_t Bf[8];
#pragma unroll
            for (int pr = 0; pr < 2; pr++) {
                int r = wn + pr * 16 + lr;
                ldm4(Bf[pr * 4 + 0], Bf[pr * 4 + 1], Bf[pr * 4 + 2], Bf[pr * 4 + 3],
                     sb + BOB + swz(r, kc));
            }
            uint32_t Af[NMT][4];
#pragma unroll
            for (int mt = 0; mt < NMT; mt++) {
                int r = wm + mt * 16 + lr;
                ldm4(Af[mt][0], Af[mt][1], Af[mt][2], Af[mt][3], sb + swz(r, kc));
            }
#pragma unroll
            for (int mt = 0; mt < NMT; mt++)
#pragma unroll
                for (int nt = 0; nt < 4; nt++) {
                    int i0 = (nt >> 1) * 4 + (nt & 1);
                    mmaf16(acc[mt][nt], Af[mt][0], Af[mt][1], Af[mt][2], Af[mt][3],
                           Bf[i0], Bf[i0 + 2]);
                }
        }
    }

    // ---- epilogue ----
    if (EP <= 1) {
        __half* Chp = Ch + (size_t)bz * sCp;
#pragma unroll
        for (int mt = 0; mt < NMT; mt++) {
            int m = m0 + wm + mt * 16 + g;
            float bv0 = (EP == 1) ? bias[m] : 0.f;
            float bv1 = (EP == 1) ? bias[m + 8] : 0.f;
#pragma unroll
            for (int nt = 0; nt < 4; nt++) {
                int n = n0 + wn + nt * 8 + tg * 2;
                float* a = acc[mt][nt];
                size_t i0 = (size_t)m * ldc + n;
                size_t i1 = (size_t)(m + 8) * ldc + n;
                *reinterpret_cast<__half2*>(Chp + i0) =
                    __half2(__float2half_rn(a[0] + bv0), __float2half_rn(a[1] + bv0));
                *reinterpret_cast<__half2*>(Chp + i1) =
                    __half2(__float2half_rn(a[2] + bv1), __float2half_rn(a[3] + bv1));
            }
        }
    } else {
        float* Cp = C + (size_t)bz * sC;
        const float* R = resid + (size_t)bz * sC;
#pragma unroll
        for (int mt = 0; mt < NMT; mt++) {
            int m = m0 + wm + mt * 16 + g;
            float bv0 = bias[m], bv1 = bias[m + 8];
#pragma unroll
            for (int nt = 0; nt < 4; nt++) {
                int n = n0 + wn + nt * 8 + tg * 2;
                float* a = acc[mt][nt];
                size_t i0 = (size_t)m * ldc + n;
                size_t i1 = (size_t)(m + 8) * ldc + n;
                float2 r0 = *reinterpret_cast<const float2*>(R + i0);
                float2 r1 = *reinterpret_cast<const float2*>(R + i1);
                float2 o0, o1;
                o0.x = a[0] + bv0 + r0.x; o0.y = a[1] + bv0 + r0.y;
                o1.x = a[2] + bv1 + r1.x; o1.y = a[3] + bv1 + r1.y;
                *reinterpret_cast<float2*>(Cp + i0) = o0;
                *reinterpret_cast<float2*>(Cp + i1) = o1;
            }
        }
    }
}

// ---------------------------------------------------------------------------
// Fused pre-pass: blocks 0..511 = gn partial sums; blocks 512..1023 = weight
// conversion (w1, w2 -> fp16). 256 threads.
// ---------------------------------------------------------------------------
__global__ __launch_bounds__(256) void pre_kernel(const float* __restrict__ x,
                                                  const float* __restrict__ w1,
                                                  const float* __restrict__ w2) {
    int t = threadIdx.x;
    if (blockIdx.x < 512) {
        int bg = blockIdx.x >> 3, slice = blockIdx.x & 7;
        const float4* xp = reinterpret_cast<const float4*>(
            x + (size_t)bg * GSIZE + slice * 8192);
        float s = 0.f, sq = 0.f;
#pragma unroll
        for (int i = 0; i < 8; i++) {
            float4 v = xp[t + 256 * i];
            s  += v.x + v.y + v.z + v.w;
            sq += v.x * v.x + v.y * v.y + v.z * v.z + v.w * v.w;
        }
#pragma unroll
        for (int o = 16; o >= 1; o >>= 1) {
            s  += __shfl_xor_sync(0xFFFFFFFFu, s, o);
            sq += __shfl_xor_sync(0xFFFFFFFFu, sq, o);
        }
        __shared__ float rs[8], rq[8];
        if ((t & 31) == 0) { rs[t >> 5] = s; rq[t >> 5] = sq; }
        __syncthreads();
        if (t == 0) {
            float S = 0.f, Q = 0.f;
#pragma unroll
            for (int i = 0; i < 8; i++) { S += rs[i]; Q += rq[i]; }
            g_gnp[(bg * 8 + slice) * 2 + 0] = S;
            g_gnp[(bg * 8 + slice) * 2 + 1] = Q;
        }
    } else {
        int i = (blockIdx.x - 512) * 256 + t;
        const int n1 = C3 * CH / 8;
        const float* src = (i < n1) ? w1 : w2;
        __half* dst = (i < n1) ? g_w1f : g_w2f;
        int j = (i < n1) ? i : i - n1;
        const float4* s = reinterpret_cast<const float4*>(src) + j * 2;
        float4 v0 = s[0], v1 = s[1];
        __half hh[8];
        hh[0] = __float2half_rn(v0.x); hh[1] = __float2half_rn(v0.y);
        hh[2] = __float2half_rn(v0.z); hh[3] = __float2half_rn(v0.w);
        hh[4] = __float2half_rn(v1.x); hh[5] = __float2half_rn(v1.y);
        hh[6] = __float2half_rn(v1.z); hh[7] = __float2half_rn(v1.w);
        *reinterpret_cast<uint4*>(dst + (size_t)j * 8) = *reinterpret_cast<uint4*>(hh);
    }
}

// ---------------------------------------------------------------------------
// GroupNorm pass 2: normalize + fp32 residual + transposed fp16 plane.
// ---------------------------------------------------------------------------
__global__ __launch_bounds__(256) void gn_norm_kernel(const float* __restrict__ x,
                                                      const float* __restrict__ gamma,
                                                      const float* __restrict__ beta) {
    int bg = blockIdx.x >> 3, slice = blockIdx.x & 7;
    int b = bg >> 3, g = bg & 7;
    int n0 = slice * 128;
    int t = threadIdx.x;

    float S = 0.f, Q = 0.f;
#pragma unroll
    for (int i = 0; i < 8; i++) {
        S += g_gnp[(bg * 8 + i) * 2 + 0];
        Q += g_gnp[(bg * 8 + i) * 2 + 1];
    }
    float mean = S * (1.f / GSIZE);
    float var  = Q * (1.f / GSIZE) - mean * mean;
    float rstd = rsqrtf(var + 1e-5f);

    int c = t >> 2, sub = t & 3;
    float gm = gamma[g * CPG + c] * rstd;
    float bt = beta[g * CPG + c] - mean * gm;

    size_t rowoff = ((size_t)b * CH + g * CPG + c) * NTOK + n0;
    const float4* xp = reinterpret_cast<const float4*>(x + rowoff);
    float4* gp = reinterpret_cast<float4*>(g_xn + rowoff);

    __shared__ __half th[128][72];
#pragma unroll
    for (int i = 0; i < 8; i++) {
        int nq = sub * 8 + i;
        float4 v = xp[nq];
        v.x = v.x * gm + bt; v.y = v.y * gm + bt;
        v.z = v.z * gm + bt; v.w = v.w * gm + bt;
        gp[nq] = v;
        th[nq * 4 + 0][c] = __float2half_rn(v.x);
        th[nq * 4 + 1][c] = __float2half_rn(v.y);
        th[nq * 4 + 2][c] = __float2half_rn(v.z);
        th[nq * 4 + 3][c] = __float2half_rn(v.w);
    }
    __syncthreads();
#pragma unroll
    for (int it = 0; it < 4; it++) {
        int idx = t + 256 * it;
        int nl = idx >> 3, c8 = idx & 7;
        size_t dst = ((size_t)b * NTOK + n0 + nl) * CH + g * CPG + c8 * 8;
        *reinterpret_cast<uint4*>(&g_xnTh[dst]) = *reinterpret_cast<uint4*>(&th[nl][c8 * 8]);
    }
}

// ---------------------------------------------------------------------------
// Fused softmax kernel, 512 threads.
// Blocks 0..255: k softmax over c per (b,n), IN PLACE on fp16 k block [C,N].
// Blocks 256..511: q softmax over n per (b,c), warp-per-channel, writes qT.
// ---------------------------------------------------------------------------
__global__ __launch_bounds__(512) void softmax_kernel() {
    int t = threadIdx.x;
    if (blockIdx.x < 256) {
        // ---- k softmax ----
        int b = blockIdx.x >> 5;
        int n0 = (blockIdx.x & 31) * 32;
        __half* base = g_qkvf + (size_t)b * C3 * NTOK + (size_t)CH * NTOK + n0;
        int lane = t & 31, j = t >> 5;

        float mx = -1e30f, sum = 0.f;
        for (int i = 0; i < 32; i++) {
            float v = __half2float(base[(size_t)(j * 32 + i) * NTOK + lane]);
            float nm = fmaxf(mx, v);
            sum = sum * __expf(mx - nm) + __expf(v - nm);
            mx = nm;
        }
        __shared__ float sM[16][32], sS[16][32];
        sM[j][lane] = mx; sS[j][lane] = sum;
        __syncthreads();
        if (j == 0) {
            float M = sM[0][lane], S = sS[0][lane];
#pragma unroll
            for (int w = 1; w < 16; w++) {
                float m2 = sM[w][lane], s2 = sS[w][lane];
                float nm = fmaxf(M, m2);
                S = S * __expf(M - nm) + s2 * __expf(m2 - nm);
                M = nm;
            }
            sM[0][lane] = M; sS[0][lane] = 1.f / S;
        }
        __syncthreads();
        float M = sM[0][lane], inv = sS[0][lane];
        for (int i = 0; i < 32; i++) {
            size_t idx = (size_t)(j * 32 + i) * NTOK + lane;
            base[idx] = __float2half_rn(__expf(__half2float(base[idx]) - M) * inv);
        }
    } else {
        // ---- q softmax: warp w handles channel c0+w ----
        int bid = blockIdx.x - 256;
        int b = bid >> 5, c0 = (bid & 31) * 16;
        const __half* base = g_qkvf + (size_t)b * C3 * NTOK;
        int w = t >> 5, lane = t & 31;
        const __half* row = base + (size_t)(c0 + w) * NTOK;

        float mx = -1e30f, sum = 0.f;
#pragma unroll
        for (int i = 0; i < 4; i++) {
            uint4 u = *reinterpret_cast<const uint4*>(row + (i * 32 + lane) * 8);
            const __half2* hp = reinterpret_cast<const __half2*>(&u);
#pragma unroll
            for (int q = 0; q < 4; q++) {
                float2 f = __half22float2(hp[q]);
                float m2 = fmaxf(f.x, f.y);
                float nm = fmaxf(mx, m2);
                sum = sum * __expf(mx - nm) + __expf(f.x - nm) + __expf(f.y - nm);
                mx = nm;
            }
        }
#pragma unroll
        for (int o = 16; o >= 1; o >>= 1) {
            float m2 = __shfl_xor_sync(0xFFFFFFFFu, mx, o);
            float s2 = __shfl_xor_sync(0xFFFFFFFFu, sum, o);
            float nm = fmaxf(mx, m2);
            sum = sum * __expf(mx - nm) + s2 * __expf(m2 - nm);
            mx = nm;
        }
        float M = mx, inv = 1.f / sum;

        __shared__ __half th[64][24];
        for (int tn = 0; tn < 16; tn++) {
            float v0 = __half2float(row[tn * 64 + lane]);
            float v1 = __half2float(row[tn * 64 + 32 + lane]);
            th[lane][w]      = __float2half_rn(__expf(v0 - M) * inv);
            th[lane + 32][w] = __float2half_rn(__expf(v1 - M) * inv);
            __syncthreads();
            if (t < 128) {
                int nl = t >> 1, chn = t & 1;
                size_t dst = ((size_t)b * NTOK + tn * 64 + nl) * CH + c0 + chn * 8;
                *reinterpret_cast<uint4*>(&g_qTh[dst]) =
                    *reinterpret_cast<uint4*>(&th[nl][chn * 8]);
            }
            __syncthreads();
        }
    }
}

// ---------------------------------------------------------------------------
// Launch
// ---------------------------------------------------------------------------
extern "C" void kernel_launch(void* const* d_in, const int* in_sizes, int n_in,
                              void* d_out, int out_size) {
    const float* x      = (const float*)d_in[0];
    const float* gn_w   = (const float*)d_in[1];
    const float* gn_b   = (const float*)d_in[2];
    const float* qkv_w  = (const float*)d_in[3];
    const float* qkv_b  = (const float*)d_in[4];
    const float* proj_w = (const float*)d_in[5];
    const float* proj_b = (const float*)d_in[6];
    float* out = (float*)d_out;

    void* p;
    cudaGetSymbolAddress(&p, g_xn);   float* xn   = (float*)p;
    cudaGetSymbolAddress(&p, g_qkvf); __half* qkvf = (__half*)p;
    cudaGetSymbolAddress(&p, g_xnTh); __half* xnTh = (__half*)p;
    cudaGetSymbolAddress(&p, g_w1f);  __half* w1f = (__half*)p;
    cudaGetSymbolAddress(&p, g_w2f);  __half* w2f = (__half*)p;
    cudaGetSymbolAddress(&p, g_qTh);  __half* qTh = (__half*)p;
    cudaGetSymbolAddress(&p, g_ctxT); __half* ctxT = (__half*)p;
    cudaGetSymbolAddress(&p, g_m2);   __half* m2 = (__half*)p;

    constexpr int SMB1 = (64 + 128) * 128 * 2;    // 49152 (MWT=1)
    constexpr int SMB2 = (128 + 128) * 128 * 2;   // 65536 (MWT=2)
    cudaFuncSetAttribute(gemmf16<2, 1>, cudaFuncAttributeMaxDynamicSharedMemorySize, SMB2);
    cudaFuncSetAttribute(gemmf16<1, 0>, cudaFuncAttributeMaxDynamicSharedMemorySize, SMB1);
    cudaFuncSetAttribute(gemmf16<2, 2>, cudaFuncAttributeMaxDynamicSharedMemorySize, SMB2);

    // 1) fused gn partial sums + weight conversion
    pre_kernel<<<1024, 256>>>(x, qkv_w, proj_w);

    // 2) GroupNorm normalize
    gn_norm_kernel<<<BATCH * GRP * 8, 256>>>(x, gn_w, gn_b);

    // 3) GEMM1 (MWT=2, EP1): qkv fp16 [3C,N] + bias. M=1536 N=1024 K=512
    gemmf16<2, 1><<<dim3(NTOK / 128, C3 / 128, BATCH), 256, SMB2>>>(
        w1f, xnTh, nullptr, qkvf,
        CH, CH, CH, NTOK,
        0LL, (long long)NTOK * CH, 0LL, (long long)C3 * NTOK,
        qkv_b, nullptr);

    // 4) fused softmaxes (k in place; q -> transposed plane)
    softmax_kernel<<<512, 512>>>();

    // 5) GEMM2 (MWT=1, EP0): ctxT[c,d] = sum_n k[c,n]*v[d,n]. M=512 N=512 K=1024
    gemmf16<1, 0><<<dim3(CH / 128, CH / 64, BATCH), 256, SMB1>>>(
        qkvf + (size_t)CH * NTOK, qkvf + (size_t)2 * CH * NTOK, nullptr, ctxT,
        NTOK, NTOK, NTOK, CH,
        (long long)C3 * NTOK, (long long)C3 * NTOK, 0LL, (long long)CH * CH,
        nullptr, nullptr);

    // 6) GEMM3' (MWT=1, EP0): M2[d,c] = sum_c' w2[d,c']*ctxT[c,c']. M=512 N=512 K=512
    gemmf16<1, 0><<<dim3(CH / 128, CH / 64, BATCH), 256, SMB1>>>(
        w2f, ctxT, nullptr, m2,
        CH, CH, CH, CH,
        0LL, (long long)CH * CH, 0LL, (long long)CH * CH,
        nullptr, nullptr);

    // 7) GEMM4' (MWT=2, EP2): out[d,n] = sum_c M2[d,c]*qT[n,c] + b + xn. M=512 N=1024 K=512
    gemmf16<2, 2><<<dim3(NTOK / 128, CH / 128, BATCH), 256, SMB2>>>(
        m2, qTh, out, nullptr,
        CH, CH, CH, NTOK,
        (long long)CH * CH, (long long)NTOK * CH, (long long)CH * NTOK, 0LL,
        proj_b, xn);
}

// round 16
// speedup vs baseline: 5.5482x; 1.0141x over previous
#include <cuda_runtime.h>
#include <cuda_fp16.h>
#include <cstdint>

#define BATCH 8
#define CH    512
#define NTOK  1024
#define C3    1536
#define GRP   8
#define CPG   64
#define GSIZE 65536

// ---------------- scratch (device globals) ----------------
__device__ float g_xn  [BATCH * CH * NTOK];            // fp32 residual [B,C,N]
__device__ float g_gnp [BATCH * GRP * 8 * 2];          // gn partial sums
__device__ __half g_qkvf[BATCH * C3 * NTOK];           // qkv fp16 [B,3C,N]; k softmaxed in place
__device__ __half g_xnTh[BATCH * NTOK * CH];           // xn^T fp16 [B,N,C]
__device__ __half g_w1f[C3 * CH];                      // w1 fp16
__device__ __half g_w2f[CH * CH];                      // w2 fp16
__device__ __half g_qTh[BATCH * NTOK * CH];            // qT fp16 [N,C]
__device__ __half g_ctxT[BATCH * CH * CH];             // ctx^T fp16 [c,d]
__device__ __half g_m2[BATCH * CH * CH];               // M2 = w2*ctx fp16 [d,c]

// ---------------- helpers ----------------
__device__ __forceinline__ uint32_t smem_u32(const void* p) {
    uint32_t a;
    asm("{ .reg .u64 t; cvta.to.shared.u64 t, %1; cvt.u32.u64 %0, t; }" : "=r"(a) : "l"(p));
    return a;
}
__device__ __forceinline__ void mmaf16(float* c, uint32_t a0, uint32_t a1,
                                       uint32_t a2, uint32_t a3,
                                       uint32_t b0, uint32_t b1) {
    asm volatile(
        "mma.sync.aligned.m16n8k16.row.col.f32.f16.f16.f32 "
        "{%0,%1,%2,%3},{%4,%5,%6,%7},{%8,%9},{%0,%1,%2,%3};"
        : "+f"(c[0]), "+f"(c[1]), "+f"(c[2]), "+f"(c[3])
        : "r"(a0), "r"(a1), "r"(a2), "r"(a3), "r"(b0), "r"(b1));
}
__device__ __forceinline__ void ldm4(uint32_t& r0, uint32_t& r1, uint32_t& r2,
                                     uint32_t& r3, uint32_t a) {
    asm volatile("ldmatrix.sync.aligned.m8n8.x4.shared.b16 {%0,%1,%2,%3}, [%4];"
                 : "=r"(r0), "=r"(r1), "=r"(r2), "=r"(r3) : "r"(a));
}
#define CPA16(d, s) asm volatile("cp.async.cg.shared.global [%0], [%1], 16;" :: "r"(d), "l"(s))
#define CPCOMMIT()  asm volatile("cp.async.commit_group;")
#define CPWAIT0()   asm volatile("cp.async.wait_group 0;" ::: "memory")

// swizzled byte offset: 128B rows, 16B chunk c (0..7), row r
__device__ __forceinline__ uint32_t swz(int r, int c) {
    return (uint32_t)(r * 128 + ((c ^ (r & 7)) << 4));
}

// ---------------------------------------------------------------------------
// fp16 single-pass tensor-core GEMM, BK=64, 2-stage cp.async double buffer.
// ---------------------------------------------------------------------------
template <int MWT, int EP>
__global__ __launch_bounds__(256, (MWT == 1 ? 4 : 2)) void gemmf16(
    const __half* __restrict__ Ah, const __half* __restrict__ Bh,
    float* __restrict__ C, __half* __restrict__ Ch,
    int K, int lda, int ldb, int ldc,
    long long sA, long long sB, long long sC, long long sCp,
    const float* __restrict__ bias, const float* __restrict__ resid)
{
    constexpr int BM = 64 * MWT, BN = 128;
    constexpr int NMT = 2 * MWT;
    constexpr int BOB = BM * 128;
    constexpr int SSB = (BM + BN) * 128;
    constexpr int ITA = (BM * 8) / 256;
    constexpr int ITB = (BN * 8) / 256;

    extern __shared__ __align__(128) __half smbuf[];
    const uint32_t su = smem_u32(smbuf);
    const int tid = threadIdx.x;
    const int bz = blockIdx.z;
    Ah += (size_t)bz * sA;
    Bh += (size_t)bz * sB;
    const int m0 = blockIdx.y * BM, n0 = blockIdx.x * BN;

    const int lane = tid & 31, wid = tid >> 5;
    const int g = lane >> 2, tg = lane & 3;
    const int wm = (wid & 1) * 32 * MWT, wn = (wid >> 1) * 32;
    const int lr = lane & 15, lchunk = lane >> 4;

    float acc[NMT][4][4];
#pragma unroll
    for (int i = 0; i < NMT; i++)
#pragma unroll
        for (int j = 0; j < 4; j++)
#pragma unroll
            for (int q = 0; q < 4; q++) acc[i][j][q] = 0.f;

    auto fill = [&](int st, int k0) {
        uint32_t base = su + (uint32_t)(st * SSB);
#pragma unroll
        for (int i = 0; i < ITA; i++) {
            int idx = tid + 256 * i;
            int row = idx >> 3, ch = idx & 7;
            CPA16(base + swz(row, ch), Ah + (size_t)(m0 + row) * lda + k0 + ch * 8);
        }
#pragma unroll
        for (int i = 0; i < ITB; i++) {
            int idx = tid + 256 * i;
            int row = idx >> 3, ch = idx & 7;
            CPA16(base + BOB + swz(row, ch), Bh + (size_t)(n0 + row) * ldb + k0 + ch * 8);
        }
        CPCOMMIT();
    };

    const int NC = K / 64;
    fill(0, 0);

    for (int c = 0; c < NC; c++) {
        CPWAIT0();
        __syncthreads();
        if (c + 1 < NC) fill((c + 1) & 1, (c + 1) * 64);
        const uint32_t sb = su + (uint32_t)((c & 1) * SSB);

#pragma unroll
        for (int ks = 0; ks < 64; ks += 16) {
            const int kc = (ks >> 3) + lchunk;
            uint32_t Bf[8];
#pragma unroll
            for (int pr = 0; pr < 2; pr++) {
                int r = wn + pr * 16 + lr;
                ldm4(Bf[pr * 4 + 0], Bf[pr * 4 + 1], Bf[pr * 4 + 2], Bf[pr * 4 + 3],
                     sb + BOB + swz(r, kc));
            }
            uint32_t Af[NMT][4];
#pragma unroll
            for (int mt = 0; mt < NMT; mt++) {
                int r = wm + mt * 16 + lr;
                ldm4(Af[mt][0], Af[mt][1], Af[mt][2], Af[mt][3], sb + swz(r, kc));
            }
#pragma unroll
            for (int mt = 0; mt < NMT; mt++)
#pragma unroll
                for (int nt = 0; nt < 4; nt++) {
                    int i0 = (nt >> 1) * 4 + (nt & 1);
                    mmaf16(acc[mt][nt], Af[mt][0], Af[mt][1], Af[mt][2], Af[mt][3],
                           Bf[i0], Bf[i0 + 2]);
                }
        }
    }

    // ---- epilogue ----
    if (EP <= 1) {
        __half* Chp = Ch + (size_t)bz * sCp;
#pragma unroll
        for (int mt = 0; mt < NMT; mt++) {
            int m = m0 + wm + mt * 16 + g;
            float bv0 = (EP == 1) ? bias[m] : 0.f;
            float bv1 = (EP == 1) ? bias[m + 8] : 0.f;
#pragma unroll
            for (int nt = 0; nt < 4; nt++) {
                int n = n0 + wn + nt * 8 + tg * 2;
                float* a = acc[mt][nt];
                size_t i0 = (size_t)m * ldc + n;
                size_t i1 = (size_t)(m + 8) * ldc + n;
                *reinterpret_cast<__half2*>(Chp + i0) =
                    __half2(__float2half_rn(a[0] + bv0), __float2half_rn(a[1] + bv0));
                *reinterpret_cast<__half2*>(Chp + i1) =
                    __half2(__float2half_rn(a[2] + bv1), __float2half_rn(a[3] + bv1));
            }
        }
    } else {
        float* Cp = C + (size_t)bz * sC;
        const float* R = resid + (size_t)bz * sC;
#pragma unroll
        for (int mt = 0; mt < NMT; mt++) {
            int m = m0 + wm + mt * 16 + g;
            float bv0 = bias[m], bv1 = bias[m + 8];
#pragma unroll
            for (int nt = 0; nt < 4; nt++) {
                int n = n0 + wn + nt * 8 + tg * 2;
                float* a = acc[mt][nt];
                size_t i0 = (size_t)m * ldc + n;
                size_t i1 = (size_t)(m + 8) * ldc + n;
                float2 r0 = *reinterpret_cast<const float2*>(R + i0);
                float2 r1 = *reinterpret_cast<const float2*>(R + i1);
                float2 o0, o1;
                o0.x = a[0] + bv0 + r0.x; o0.y = a[1] + bv0 + r0.y;
                o1.x = a[2] + bv1 + r1.x; o1.y = a[3] + bv1 + r1.y;
                *reinterpret_cast<float2*>(Cp + i0) = o0;
                *reinterpret_cast<float2*>(Cp + i1) = o1;
            }
        }
    }
}

// ---------------------------------------------------------------------------
// Fused pre-pass: blocks 0..511 = gn partial sums; blocks 512..1023 = weight
// conversion. 256 threads.
// ---------------------------------------------------------------------------
__global__ __launch_bounds__(256) void pre_kernel(const float* __restrict__ x,
                                                  const float* __restrict__ w1,
                                                  const float* __restrict__ w2) {
    int t = threadIdx.x;
    if (blockIdx.x < 512) {
        int bg = blockIdx.x >> 3, slice = blockIdx.x & 7;
        const float4* xp = reinterpret_cast<const float4*>(
            x + (size_t)bg * GSIZE + slice * 8192);
        float s = 0.f, sq = 0.f;
#pragma unroll
        for (int i = 0; i < 8; i++) {
            float4 v = xp[t + 256 * i];
            s  += v.x + v.y + v.z + v.w;
            sq += v.x * v.x + v.y * v.y + v.z * v.z + v.w * v.w;
        }
#pragma unroll
        for (int o = 16; o >= 1; o >>= 1) {
            s  += __shfl_xor_sync(0xFFFFFFFFu, s, o);
            sq += __shfl_xor_sync(0xFFFFFFFFu, sq, o);
        }
        __shared__ float rs[8], rq[8];
        if ((t & 31) == 0) { rs[t >> 5] = s; rq[t >> 5] = sq; }
        __syncthreads();
        if (t == 0) {
            float S = 0.f, Q = 0.f;
#pragma unroll
            for (int i = 0; i < 8; i++) { S += rs[i]; Q += rq[i]; }
            g_gnp[(bg * 8 + slice) * 2 + 0] = S;
            g_gnp[(bg * 8 + slice) * 2 + 1] = Q;
        }
    } else {
        int i = (blockIdx.x - 512) * 256 + t;
        const int n1 = C3 * CH / 8;
        const float* src = (i < n1) ? w1 : w2;
        __half* dst = (i < n1) ? g_w1f : g_w2f;
        int j = (i < n1) ? i : i - n1;
        const float4* s = reinterpret_cast<const float4*>(src) + j * 2;
        float4 v0 = s[0], v1 = s[1];
        __half hh[8];
        hh[0] = __float2half_rn(v0.x); hh[1] = __float2half_rn(v0.y);
        hh[2] = __float2half_rn(v0.z); hh[3] = __float2half_rn(v0.w);
        hh[4] = __float2half_rn(v1.x); hh[5] = __float2half_rn(v1.y);
        hh[6] = __float2half_rn(v1.z); hh[7] = __float2half_rn(v1.w);
        *reinterpret_cast<uint4*>(dst + (size_t)j * 8) = *reinterpret_cast<uint4*>(hh);
    }
}

// ---------------------------------------------------------------------------
// GroupNorm pass 2: normalize + fp32 residual + transposed fp16 plane.
// ---------------------------------------------------------------------------
__global__ __launch_bounds__(256) void gn_norm_kernel(const float* __restrict__ x,
                                                      const float* __restrict__ gamma,
                                                      const float* __restrict__ beta) {
    int bg = blockIdx.x >> 3, slice = blockIdx.x & 7;
    int b = bg >> 3, g = bg & 7;
    int n0 = slice * 128;
    int t = threadIdx.x;

    float S = 0.f, Q = 0.f;
#pragma unroll
    for (int i = 0; i < 8; i++) {
        S += g_gnp[(bg * 8 + i) * 2 + 0];
        Q += g_gnp[(bg * 8 + i) * 2 + 1];
    }
    float mean = S * (1.f / GSIZE);
    float var  = Q * (1.f / GSIZE) - mean * mean;
    float rstd = rsqrtf(var + 1e-5f);

    int c = t >> 2, sub = t & 3;
    float gm = gamma[g * CPG + c] * rstd;
    float bt = beta[g * CPG + c] - mean * gm;

    size_t rowoff = ((size_t)b * CH + g * CPG + c) * NTOK + n0;
    const float4* xp = reinterpret_cast<const float4*>(x + rowoff);
    float4* gp = reinterpret_cast<float4*>(g_xn + rowoff);

    __shared__ __half th[128][72];
#pragma unroll
    for (int i = 0; i < 8; i++) {
        int nq = sub * 8 + i;
        float4 v = xp[nq];
        v.x = v.x * gm + bt; v.y = v.y * gm + bt;
        v.z = v.z * gm + bt; v.w = v.w * gm + bt;
        gp[nq] = v;
        th[nq * 4 + 0][c] = __float2half_rn(v.x);
        th[nq * 4 + 1][c] = __float2half_rn(v.y);
        th[nq * 4 + 2][c] = __float2half_rn(v.z);
        th[nq * 4 + 3][c] = __float2half_rn(v.w);
    }
    __syncthreads();
#pragma unroll
    for (int it = 0; it < 4; it++) {
        int idx = t + 256 * it;
        int nl = idx >> 3, c8 = idx & 7;
        size_t dst = ((size_t)b * NTOK + n0 + nl) * CH + g * CPG + c8 * 8;
        *reinterpret_cast<uint4*>(&g_xnTh[dst]) = *reinterpret_cast<uint4*>(&th[nl][c8 * 8]);
    }
}

// ---------------------------------------------------------------------------
// Fused softmax kernel, 512 threads.
// Blocks 0..127: k softmax over c per (b,n), IN PLACE, vectorized __half2.
//   Block = (b, 64 n-columns); lane owns 2 columns; warp j rows j*32..j*32+31.
// Blocks 128..383: q softmax over n per (b,c), warp-per-channel, writes qT.
// ---------------------------------------------------------------------------
__global__ __launch_bounds__(512) void softmax_kernel() {
    int t = threadIdx.x;
    if (blockIdx.x < 128) {
        // ---- k softmax (vectorized) ----
        int b = blockIdx.x >> 4;
        int n0 = (blockIdx.x & 15) * 64;
        __half* base = g_qkvf + (size_t)b * C3 * NTOK + (size_t)CH * NTOK + n0;
        int lane = t & 31, j = t >> 5;

        float mx0 = -1e30f, s0 = 0.f, mx1 = -1e30f, s1 = 0.f;
        for (int i = 0; i < 32; i++) {
            __half2 h = *reinterpret_cast<const __half2*>(
                base + (size_t)(j * 32 + i) * NTOK + lane * 2);
            float2 f = __half22float2(h);
            float nm0 = fmaxf(mx0, f.x);
            s0 = s0 * __expf(mx0 - nm0) + __expf(f.x - nm0);
            mx0 = nm0;
            float nm1 = fmaxf(mx1, f.y);
            s1 = s1 * __expf(mx1 - nm1) + __expf(f.y - nm1);
            mx1 = nm1;
        }
        __shared__ float sM[16][64], sS[16][64];
        sM[j][lane * 2] = mx0; sS[j][lane * 2] = s0;
        sM[j][lane * 2 + 1] = mx1; sS[j][lane * 2 + 1] = s1;
        __syncthreads();
        if (t < 64) {
            float M = sM[0][t], S = sS[0][t];
#pragma unroll
            for (int w = 1; w < 16; w++) {
                float m2 = sM[w][t], s2 = sS[w][t];
                float nm = fmaxf(M, m2);
                S = S * __expf(M - nm) + s2 * __expf(m2 - nm);
                M = nm;
            }
            sM[0][t] = M; sS[0][t] = 1.f / S;
        }
        __syncthreads();
        float M0 = sM[0][lane * 2], I0 = sS[0][lane * 2];
        float M1 = sM[0][lane * 2 + 1], I1 = sS[0][lane * 2 + 1];
        for (int i = 0; i < 32; i++) {
            __half2* p = reinterpret_cast<__half2*>(
                base + (size_t)(j * 32 + i) * NTOK + lane * 2);
            float2 f = __half22float2(*p);
            *p = __half2(__float2half_rn(__expf(f.x - M0) * I0),
                         __float2half_rn(__expf(f.y - M1) * I1));
        }
    } else {
        // ---- q softmax: warp w handles channel c0+w ----
        int bid = blockIdx.x - 128;
        int b = bid >> 5, c0 = (bid & 31) * 16;
        const __half* base = g_qkvf + (size_t)b * C3 * NTOK;
        int w = t >> 5, lane = t & 31;
        const __half* row = base + (size_t)(c0 + w) * NTOK;

        float mx = -1e30f, sum = 0.f;
#pragma unroll
        for (int i = 0; i < 4; i++) {
            uint4 u = *reinterpret_cast<const uint4*>(row + (i * 32 + lane) * 8);
            const __half2* hp = reinterpret_cast<const __half2*>(&u);
#pragma unroll
            for (int q = 0; q < 4; q++) {
                float2 f = __half22float2(hp[q]);
                float m2 = fmaxf(f.x, f.y);
                float nm = fmaxf(mx, m2);
                sum = sum * __expf(mx - nm) + __expf(f.x - nm) + __expf(f.y - nm);
                mx = nm;
            }
        }
#pragma unroll
        for (int o = 16; o >= 1; o >>= 1) {
            float m2 = __shfl_xor_sync(0xFFFFFFFFu, mx, o);
            float s2 = __shfl_xor_sync(0xFFFFFFFFu, sum, o);
            float nm = fmaxf(mx, m2);
            sum = sum * __expf(mx - nm) + s2 * __expf(m2 - nm);
            mx = nm;
        }
        float M = mx, inv = 1.f / sum;

        __shared__ __half th[256][24];
        for (int seg = 0; seg < 4; seg++) {
#pragma unroll
            for (int i = 0; i < 8; i++) {
                int tok = i * 32 + lane;                 // 0..255
                float v = __half2float(row[seg * 256 + tok]);
                th[tok][w] = __float2half_rn(__expf(v - M) * inv);
            }
            __syncthreads();
            {
                int nl = t >> 1, chn = t & 1;            // 256 tokens x 2 chunks
                size_t dst = ((size_t)b * NTOK + seg * 256 + nl) * CH + c0 + chn * 8;
                *reinterpret_cast<uint4*>(&g_qTh[dst]) =
                    *reinterpret_cast<uint4*>(&th[nl][chn * 8]);
            }
            __syncthreads();
        }
    }
}

// ---------------------------------------------------------------------------
// Launch
// ---------------------------------------------------------------------------
extern "C" void kernel_launch(void* const* d_in, const int* in_sizes, int n_in,
                              void* d_out, int out_size) {
    const float* x      = (const float*)d_in[0];
    const float* gn_w   = (const float*)d_in[1];
    const float* gn_b   = (const float*)d_in[2];
    const float* qkv_w  = (const float*)d_in[3];
    const float* qkv_b  = (const float*)d_in[4];
    const float* proj_w = (const float*)d_in[5];
    const float* proj_b = (const float*)d_in[6];
    float* out = (float*)d_out;

    void* p;
    cudaGetSymbolAddress(&p, g_xn);   float* xn   = (float*)p;
    cudaGetSymbolAddress(&p, g_qkvf); __half* qkvf = (__half*)p;
    cudaGetSymbolAddress(&p, g_xnTh); __half* xnTh = (__half*)p;
    cudaGetSymbolAddress(&p, g_w1f);  __half* w1f = (__half*)p;
    cudaGetSymbolAddress(&p, g_w2f);  __half* w2f = (__half*)p;
    cudaGetSymbolAddress(&p, g_qTh);  __half* qTh = (__half*)p;
    cudaGetSymbolAddress(&p, g_ctxT); __half* ctxT = (__half*)p;
    cudaGetSymbolAddress(&p, g_m2);   __half* m2 = (__half*)p;

    constexpr int SMB1 = (64 + 128) * 128 * 2;    // 49152 (MWT=1)
    constexpr int SMB2 = (128 + 128) * 128 * 2;   // 65536 (MWT=2)
    cudaFuncSetAttribute(gemmf16<2, 1>, cudaFuncAttributeMaxDynamicSharedMemorySize, SMB2);
    cudaFuncSetAttribute(gemmf16<1, 0>, cudaFuncAttributeMaxDynamicSharedMemorySize, SMB1);
    cudaFuncSetAttribute(gemmf16<2, 2>, cudaFuncAttributeMaxDynamicSharedMemorySize, SMB2);

    // 1) fused gn partial sums + weight conversion
    pre_kernel<<<1024, 256>>>(x, qkv_w, proj_w);

    // 2) GroupNorm normalize
    gn_norm_kernel<<<BATCH * GRP * 8, 256>>>(x, gn_w, gn_b);

    // 3) GEMM1 (MWT=2, EP1): qkv fp16 [3C,N] + bias. M=1536 N=1024 K=512
    gemmf16<2, 1><<<dim3(NTOK / 128, C3 / 128, BATCH), 256, SMB2>>>(
        w1f, xnTh, nullptr, qkvf,
        CH, CH, CH, NTOK,
        0LL, (long long)NTOK * CH, 0LL, (long long)C3 * NTOK,
        qkv_b, nullptr);

    // 4) fused softmaxes (k in place, vectorized; q -> transposed plane)
    softmax_kernel<<<384, 512>>>();

    // 5) GEMM2 (MWT=1, EP0): ctxT[c,d] = sum_n k[c,n]*v[d,n]. M=512 N=512 K=1024
    gemmf16<1, 0><<<dim3(CH / 128, CH / 64, BATCH), 256, SMB1>>>(
        qkvf + (size_t)CH * NTOK, qkvf + (size_t)2 * CH * NTOK, nullptr, ctxT,
        NTOK, NTOK, NTOK, CH,
        (long long)C3 * NTOK, (long long)C3 * NTOK, 0LL, (long long)CH * CH,
        nullptr, nullptr);

    // 6) GEMM3' (MWT=1, EP0): M2[d,c] = sum_c' w2[d,c']*ctxT[c,c']. M=512 N=512 K=512
    gemmf16<1, 0><<<dim3(CH / 128, CH / 64, BATCH), 256, SMB1>>>(
        w2f, ctxT, nullptr, m2,
        CH, CH, CH, CH,
        0LL, (long long)CH * CH, 0LL, (long long)CH * CH,
        nullptr, nullptr);

    // 7) GEMM4' (MWT=2, EP2): out[d,n] = sum_c M2[d,c]*qT[n,c] + b + xn. M=512 N=1024 K=512
    gemmf16<2, 2><<<dim3(NTOK / 128, CH / 128, BATCH), 256, SMB2>>>(
        m2, qTh, out, nullptr,
        CH, CH, CH, NTOK,
        (long long)CH * CH, (long long)NTOK * CH, (long long)CH * NTOK, 0LL,
        proj_b, xn);
}

// round 17
// speedup vs baseline: 5.6615x; 1.0204x over previous
#include <cuda_runtime.h>
#include <cuda_fp16.h>
#include <cstdint>

#define BATCH 8
#define CH    512
#define NTOK  1024
#define C3    1536
#define GRP   8
#define CPG   64
#define GSIZE 65536

// ---------------- scratch (device globals) ----------------
__device__ float g_xn  [BATCH * CH * NTOK];            // fp32 residual [B,C,N]
__device__ float g_gnp [BATCH * GRP * 8 * 2];          // gn partial sums
__device__ __half g_qkvf[BATCH * C3 * NTOK];           // qkv fp16 [B,3C,N]; k softmaxed in place
__device__ __half g_xnTh[BATCH * NTOK * CH];           // xn^T fp16 [B,N,C]
__device__ __half g_w1f[C3 * CH];                      // w1 fp16
__device__ __half g_w2f[CH * CH];                      // w2 fp16
__device__ __half g_qTh[BATCH * NTOK * CH];            // qT fp16 [N,C]
__device__ __half g_ctxT[BATCH * CH * CH];             // ctx^T fp16 [c,d]
__device__ __half g_m2[BATCH * CH * CH];               // M2 = w2*ctx fp16 [d,c]

// ---------------- helpers ----------------
__device__ __forceinline__ uint32_t smem_u32(const void* p) {
    uint32_t a;
    asm("{ .reg .u64 t; cvta.to.shared.u64 t, %1; cvt.u32.u64 %0, t; }" : "=r"(a) : "l"(p));
    return a;
}
__device__ __forceinline__ void mmaf16(float* c, uint32_t a0, uint32_t a1,
                                       uint32_t a2, uint32_t a3,
                                       uint32_t b0, uint32_t b1) {
    asm volatile(
        "mma.sync.aligned.m16n8k16.row.col.f32.f16.f16.f32 "
        "{%0,%1,%2,%3},{%4,%5,%6,%7},{%8,%9},{%0,%1,%2,%3};"
        : "+f"(c[0]), "+f"(c[1]), "+f"(c[2]), "+f"(c[3])
        : "r"(a0), "r"(a1), "r"(a2), "r"(a3), "r"(b0), "r"(b1));
}
__device__ __forceinline__ void ldm4(uint32_t& r0, uint32_t& r1, uint32_t& r2,
                                     uint32_t& r3, uint32_t a) {
    asm volatile("ldmatrix.sync.aligned.m8n8.x4.shared.b16 {%0,%1,%2,%3}, [%4];"
                 : "=r"(r0), "=r"(r1), "=r"(r2), "=r"(r3) : "r"(a));
}
#define CPA16(d, s) asm volatile("cp.async.cg.shared.global [%0], [%1], 16;" :: "r"(d), "l"(s))
#define CPCOMMIT()  asm volatile("cp.async.commit_group;")
#define CPWAIT1()   asm volatile("cp.async.wait_group 1;" ::: "memory")
#define CPWAIT0()   asm volatile("cp.async.wait_group 0;" ::: "memory")

// swizzled byte offset: 128B rows, 16B chunk c (0..7), row r
__device__ __forceinline__ uint32_t swz(int r, int c) {
    return (uint32_t)(r * 128 + ((c ^ (r & 7)) << 4));
}

// ---------------------------------------------------------------------------
// fp16 single-pass tensor-core GEMM, BK=64, 3-stage cp.async pipeline.
// D[BM x 128] = sum_k A(m,k)*B(n,k), BM = 64*MWT.
// EP 0: fp16 plane, no bias.  EP 1: fp16 plane + bias[m].
// EP 2: fp32 + bias[m] + resid[m*ldc+n].
// ---------------------------------------------------------------------------
template <int MWT, int EP>
__global__ __launch_bounds__(256, (MWT == 1 ? 3 : 2)) void gemmf16(
    const __half* __restrict__ Ah, const __half* __restrict__ Bh,
    float* __restrict__ C, __half* __restrict__ Ch,
    int K, int lda, int ldb, int ldc,
    long long sA, long long sB, long long sC, long long sCp,
    const float* __restrict__ bias, const float* __restrict__ resid)
{
    constexpr int BM = 64 * MWT, BN = 128;
    constexpr int NMT = 2 * MWT;
    constexpr int BOB = BM * 128;
    constexpr int SSB = (BM + BN) * 128;
    constexpr int ITA = (BM * 8) / 256;
    constexpr int ITB = (BN * 8) / 256;

    extern __shared__ __align__(128) __half smbuf[];
    const uint32_t su = smem_u32(smbuf);
    const int tid = threadIdx.x;
    const int bz = blockIdx.z;
    Ah += (size_t)bz * sA;
    Bh += (size_t)bz * sB;
    const int m0 = blockIdx.y * BM, n0 = blockIdx.x * BN;

    const int lane = tid & 31, wid = tid >> 5;
    const int g = lane >> 2, tg = lane & 3;
    const int wm = (wid & 1) * 32 * MWT, wn = (wid >> 1) * 32;
    const int lr = lane & 15, lchunk = lane >> 4;

    float acc[NMT][4][4];
#pragma unroll
    for (int i = 0; i < NMT; i++)
#pragma unroll
        for (int j = 0; j < 4; j++)
#pragma unroll
            for (int q = 0; q < 4; q++) acc[i][j][q] = 0.f;

    auto fill = [&](int st, int k0) {
        uint32_t base = su + (uint32_t)(st * SSB);
#pragma unroll
        for (int i = 0; i < ITA; i++) {
            int idx = tid + 256 * i;
            int row = idx >> 3, ch = idx & 7;
            CPA16(base + swz(row, ch), Ah + (size_t)(m0 + row) * lda + k0 + ch * 8);
        }
#pragma unroll
        for (int i = 0; i < ITB; i++) {
            int idx = tid + 256 * i;
            int row = idx >> 3, ch = idx & 7;
            CPA16(base + BOB + swz(row, ch), Bh + (size_t)(n0 + row) * ldb + k0 + ch * 8);
        }
        CPCOMMIT();
    };

    const int NC = K / 64;
    fill(0, 0);
    if (NC > 1) fill(1, 64);

    int st = 0;
    for (int c = 0; c < NC; c++) {
        if (c + 1 < NC) { CPWAIT1(); } else { CPWAIT0(); }
        __syncthreads();
        if (c + 2 < NC) {
            int ns = st + 2; if (ns >= 3) ns -= 3;
            fill(ns, (c + 2) * 64);
        }
        const uint32_t sb = su + (uint32_t)(st * SSB);

#pragma unroll
        for (int ks = 0; ks < 64; ks += 16) {
            const int kc = (ks >> 3) + lchunk;
            uint32_t Bf[8];
#pragma unroll
            for (int pr = 0; pr < 2; pr++) {
                int r = wn + pr * 16 + lr;
                ldm4(Bf[pr * 4 + 0], Bf[pr * 4 + 1], Bf[pr * 4 + 2], Bf[pr * 4 + 3],
                     sb + BOB + swz(r, kc));
            }
            uint32_t Af[NMT][4];
#pragma unroll
            for (int mt = 0; mt < NMT; mt++) {
                int r = wm + mt * 16 + lr;
                ldm4(Af[mt][0], Af[mt][1], Af[mt][2], Af[mt][3], sb + swz(r, kc));
            }
#pragma unroll
            for (int mt = 0; mt < NMT; mt++)
#pragma unroll
                for (int nt = 0; nt < 4; nt++) {
                    int i0 = (nt >> 1) * 4 + (nt & 1);
                    mmaf16(acc[mt][nt], Af[mt][0], Af[mt][1], Af[mt][2], Af[mt][3],
                           Bf[i0], Bf[i0 + 2]);
                }
        }
        if (++st == 3) st = 0;
    }

    // ---- epilogue ----
    if (EP <= 1) {
        __half* Chp = Ch + (size_t)bz * sCp;
#pragma unroll
        for (int mt = 0; mt < NMT; mt++) {
            int m = m0 + wm + mt * 16 + g;
            float bv0 = (EP == 1) ? bias[m] : 0.f;
            float bv1 = (EP == 1) ? bias[m + 8] : 0.f;
#pragma unroll
            for (int nt = 0; nt < 4; nt++) {
                int n = n0 + wn + nt * 8 + tg * 2;
                float* a = acc[mt][nt];
                size_t i0 = (size_t)m * ldc + n;
                size_t i1 = (size_t)(m + 8) * ldc + n;
                *reinterpret_cast<__half2*>(Chp + i0) =
                    __half2(__float2half_rn(a[0] + bv0), __float2half_rn(a[1] + bv0));
                *reinterpret_cast<__half2*>(Chp + i1) =
                    __half2(__float2half_rn(a[2] + bv1), __float2half_rn(a[3] + bv1));
            }
        }
    } else {
        float* Cp = C + (size_t)bz * sC;
        const float* R = resid + (size_t)bz * sC;
#pragma unroll
        for (int mt = 0; mt < NMT; mt++) {
            int m = m0 + wm + mt * 16 + g;
            float bv0 = bias[m], bv1 = bias[m + 8];
#pragma unroll
            for (int nt = 0; nt < 4; nt++) {
                int n = n0 + wn + nt * 8 + tg * 2;
                float* a = acc[mt][nt];
                size_t i0 = (size_t)m * ldc + n;
                size_t i1 = (size_t)(m + 8) * ldc + n;
                float2 r0 = *reinterpret_cast<const float2*>(R + i0);
                float2 r1 = *reinterpret_cast<const float2*>(R + i1);
                float2 o0, o1;
                o0.x = a[0] + bv0 + r0.x; o0.y = a[1] + bv0 + r0.y;
                o1.x = a[2] + bv1 + r1.x; o1.y = a[3] + bv1 + r1.y;
                *reinterpret_cast<float2*>(Cp + i0) = o0;
                *reinterpret_cast<float2*>(Cp + i1) = o1;
            }
        }
    }
}

// ---------------------------------------------------------------------------
// Fused pre-pass: blocks 0..511 = gn partial sums; blocks 512..1023 = weight
// conversion. 256 threads.
// ---------------------------------------------------------------------------
__global__ __launch_bounds__(256) void pre_kernel(const float* __restrict__ x,
                                                  const float* __restrict__ w1,
                                                  const float* __restrict__ w2) {
    int t = threadIdx.x;
    if (blockIdx.x < 512) {
        int bg = blockIdx.x >> 3, slice = blockIdx.x & 7;
        const float4* xp = reinterpret_cast<const float4*>(
            x + (size_t)bg * GSIZE + slice * 8192);
        float s = 0.f, sq = 0.f;
#pragma unroll
        for (int i = 0; i < 8; i++) {
            float4 v = xp[t + 256 * i];
            s  += v.x + v.y + v.z + v.w;
            sq += v.x * v.x + v.y * v.y + v.z * v.z + v.w * v.w;
        }
#pragma unroll
        for (int o = 16; o >= 1; o >>= 1) {
            s  += __shfl_xor_sync(0xFFFFFFFFu, s, o);
            sq += __shfl_xor_sync(0xFFFFFFFFu, sq, o);
        }
        __shared__ float rs[8], rq[8];
        if ((t & 31) == 0) { rs[t >> 5] = s; rq[t >> 5] = sq; }
        __syncthreads();
        if (t == 0) {
            float S = 0.f, Q = 0.f;
#pragma unroll
            for (int i = 0; i < 8; i++) { S += rs[i]; Q += rq[i]; }
            g_gnp[(bg * 8 + slice) * 2 + 0] = S;
            g_gnp[(bg * 8 + slice) * 2 + 1] = Q;
        }
    } else {
        int i = (blockIdx.x - 512) * 256 + t;
        const int n1 = C3 * CH / 8;
        const float* src = (i < n1) ? w1 : w2;
        __half* dst = (i < n1) ? g_w1f : g_w2f;
        int j = (i < n1) ? i : i - n1;
        const float4* s = reinterpret_cast<const float4*>(src) + j * 2;
        float4 v0 = s[0], v1 = s[1];
        __half hh[8];
        hh[0] = __float2half_rn(v0.x); hh[1] = __float2half_rn(v0.y);
        hh[2] = __float2half_rn(v0.z); hh[3] = __float2half_rn(v0.w);
        hh[4] = __float2half_rn(v1.x); hh[5] = __float2half_rn(v1.y);
        hh[6] = __float2half_rn(v1.z); hh[7] = __float2half_rn(v1.w);
        *reinterpret_cast<uint4*>(dst + (size_t)j * 8) = *reinterpret_cast<uint4*>(hh);
    }
}

// ---------------------------------------------------------------------------
// GroupNorm pass 2: normalize + fp32 residual + transposed fp16 plane.
// ---------------------------------------------------------------------------
__global__ __launch_bounds__(256) void gn_norm_kernel(const float* __restrict__ x,
                                                      const float* __restrict__ gamma,
                                                      const float* __restrict__ beta) {
    int bg = blockIdx.x >> 3, slice = blockIdx.x & 7;
    int b = bg >> 3, g = bg & 7;
    int n0 = slice * 128;
    int t = threadIdx.x;

    float S = 0.f, Q = 0.f;
#pragma unroll
    for (int i = 0; i < 8; i++) {
        S += g_gnp[(bg * 8 + i) * 2 + 0];
        Q += g_gnp[(bg * 8 + i) * 2 + 1];
    }
    float mean = S * (1.f / GSIZE);
    float var  = Q * (1.f / GSIZE) - mean * mean;
    float rstd = rsqrtf(var + 1e-5f);

    int c = t >> 2, sub = t & 3;
    float gm = gamma[g * CPG + c] * rstd;
    float bt = beta[g * CPG + c] - mean * gm;

    size_t rowoff = ((size_t)b * CH + g * CPG + c) * NTOK + n0;
    const float4* xp = reinterpret_cast<const float4*>(x + rowoff);
    float4* gp = reinterpret_cast<float4*>(g_xn + rowoff);

    __shared__ __half th[128][72];
#pragma unroll
    for (int i = 0; i < 8; i++) {
        int nq = sub * 8 + i;
        float4 v = xp[nq];
        v.x = v.x * gm + bt; v.y = v.y * gm + bt;
        v.z = v.z * gm + bt; v.w = v.w * gm + bt;
        gp[nq] = v;
        th[nq * 4 + 0][c] = __float2half_rn(v.x);
        th[nq * 4 + 1][c] = __float2half_rn(v.y);
        th[nq * 4 + 2][c] = __float2half_rn(v.z);
        th[nq * 4 + 3][c] = __float2half_rn(v.w);
    }
    __syncthreads();
#pragma unroll
    for (int it = 0; it < 4; it++) {
        int idx = t + 256 * it;
        int nl = idx >> 3, c8 = idx & 7;
        size_t dst = ((size_t)b * NTOK + n0 + nl) * CH + g * CPG + c8 * 8;
        *reinterpret_cast<uint4*>(&g_xnTh[dst]) = *reinterpret_cast<uint4*>(&th[nl][c8 * 8]);
    }
}

// ---------------------------------------------------------------------------
// Fused softmax kernel, 512 threads.
// Blocks 0..127: k softmax, register-resident: one gmem read, one exp/element.
// Blocks 128..383: q softmax over n per (b,c), warp-per-channel, writes qT.
// ---------------------------------------------------------------------------
__global__ __launch_bounds__(512) void softmax_kernel() {
    int t = threadIdx.x;
    if (blockIdx.x < 128) {
        // ---- k softmax: block = (b, 64 n-cols); lane owns 2 cols; warp j
        //      owns rows j*32..j*32+31. Values held in registers.
        int b = blockIdx.x >> 4;
        int n0 = (blockIdx.x & 15) * 64;
        __half* base = g_qkvf + (size_t)b * C3 * NTOK + (size_t)CH * NTOK + n0
                     + (size_t)(t >> 5) * 32 * NTOK + (t & 31) * 2;
        int lane = t & 31;

        __half2 vals[32];
        float mx0 = -1e30f, mx1 = -1e30f;
#pragma unroll
        for (int i = 0; i < 32; i++) {
            vals[i] = *reinterpret_cast<const __half2*>(base + (size_t)i * NTOK);
            float2 f = __half22float2(vals[i]);
            mx0 = fmaxf(mx0, f.x);
            mx1 = fmaxf(mx1, f.y);
        }
        __shared__ float sM[16][64], sS[16][64];
        int j = t >> 5;
        sM[j][lane * 2] = mx0; sM[j][lane * 2 + 1] = mx1;
        __syncthreads();
        if (t < 64) {
            float M = sM[0][t];
#pragma unroll
            for (int w = 1; w < 16; w++) M = fmaxf(M, sM[w][t]);
            sM[0][t] = M;
        }
        __syncthreads();
        float M0 = sM[0][lane * 2], M1 = sM[0][lane * 2 + 1];
        float s0 = 0.f, s1 = 0.f;
#pragma unroll
        for (int i = 0; i < 32; i++) {
            float2 f = __half22float2(vals[i]);
            float e0 = __expf(f.x - M0), e1 = __expf(f.y - M1);
            s0 += e0; s1 += e1;
            vals[i] = __half2(__float2half_rn(e0), __float2half_rn(e1));
        }
        sS[j][lane * 2] = s0; sS[j][lane * 2 + 1] = s1;
        __syncthreads();
        if (t < 64) {
            float S = sS[0][t];
#pragma unroll
            for (int w = 1; w < 16; w++) S += sS[w][t];
            sS[0][t] = 1.f / S;
        }
        __syncthreads();
        __half2 inv = __half2(__float2half_rn(sS[0][lane * 2]),
                              __float2half_rn(sS[0][lane * 2 + 1]));
#pragma unroll
        for (int i = 0; i < 32; i++) {
            *reinterpret_cast<__half2*>(base + (size_t)i * NTOK) = __hmul2(vals[i], inv);
        }
    } else {
        // ---- q softmax: warp w handles channel c0+w ----
        int bid = blockIdx.x - 128;
        int b = bid >> 5, c0 = (bid & 31) * 16;
        const __half* base = g_qkvf + (size_t)b * C3 * NTOK;
        int w = t >> 5, lane = t & 31;
        const __half* row = base + (size_t)(c0 + w) * NTOK;

        float mx = -1e30f, sum = 0.f;
#pragma unroll
        for (int i = 0; i < 4; i++) {
            uint4 u = *reinterpret_cast<const uint4*>(row + (i * 32 + lane) * 8);
            const __half2* hp = reinterpret_cast<const __half2*>(&u);
#pragma unroll
            for (int q = 0; q < 4; q++) {
                float2 f = __half22float2(hp[q]);
                float m2 = fmaxf(f.x, f.y);
                float nm = fmaxf(mx, m2);
                sum = sum * __expf(mx - nm) + __expf(f.x - nm) + __expf(f.y - nm);
                mx = nm;
            }
        }
#pragma unroll
        for (int o = 16; o >= 1; o >>= 1) {
            float m2 = __shfl_xor_sync(0xFFFFFFFFu, mx, o);
            float s2 = __shfl_xor_sync(0xFFFFFFFFu, sum, o);
            float nm = fmaxf(mx, m2);
            sum = sum * __expf(mx - nm) + s2 * __expf(m2 - nm);
            mx = nm;
        }
        float M = mx, inv = 1.f / sum;

        __shared__ __half th[256][24];
        for (int seg = 0; seg < 4; seg++) {
#pragma unroll
            for (int i = 0; i < 8; i++) {
                int tok = i * 32 + lane;
                float v = __half2float(row[seg * 256 + tok]);
                th[tok][w] = __float2half_rn(__expf(v - M) * inv);
            }
            __syncthreads();
            {
                int nl = t >> 1, chn = t & 1;
                size_t dst = ((size_t)b * NTOK + seg * 256 + nl) * CH + c0 + chn * 8;
                *reinterpret_cast<uint4*>(&g_qTh[dst]) =
                    *reinterpret_cast<uint4*>(&th[nl][chn * 8]);
            }
            __syncthreads();
        }
    }
}

// ---------------------------------------------------------------------------
// Launch
// ---------------------------------------------------------------------------
extern "C" void kernel_launch(void* const* d_in, const int* in_sizes, int n_in,
                              void* d_out, int out_size) {
    const float* x      = (const float*)d_in[0];
    const float* gn_w   = (const float*)d_in[1];
    const float* gn_b   = (const float*)d_in[2];
    const float* qkv_w  = (const float*)d_in[3];
    const float* qkv_b  = (const float*)d_in[4];
    const float* proj_w = (const float*)d_in[5];
    const float* proj_b = (const float*)d_in[6];
    float* out = (float*)d_out;

    void* p;
    cudaGetSymbolAddress(&p, g_xn);   float* xn   = (float*)p;
    cudaGetSymbolAddress(&p, g_qkvf); __half* qkvf = (__half*)p;
    cudaGetSymbolAddress(&p, g_xnTh); __half* xnTh = (__half*)p;
    cudaGetSymbolAddress(&p, g_w1f);  __half* w1f = (__half*)p;
    cudaGetSymbolAddress(&p, g_w2f);  __half* w2f = (__half*)p;
    cudaGetSymbolAddress(&p, g_qTh);  __half* qTh = (__half*)p;
    cudaGetSymbolAddress(&p, g_ctxT); __half* ctxT = (__half*)p;
    cudaGetSymbolAddress(&p, g_m2);   __half* m2 = (__half*)p;

    constexpr int SMB1 = (64 + 128) * 128 * 3;    // 73728 (MWT=1, 3 stages)
    constexpr int SMB2 = (128 + 128) * 128 * 3;   // 98304 (MWT=2, 3 stages)
    cudaFuncSetAttribute(gemmf16<2, 1>, cudaFuncAttributeMaxDynamicSharedMemorySize, SMB2);
    cudaFuncSetAttribute(gemmf16<1, 0>, cudaFuncAttributeMaxDynamicSharedMemorySize, SMB1);
    cudaFuncSetAttribute(gemmf16<2, 2>, cudaFuncAttributeMaxDynamicSharedMemorySize, SMB2);

    // 1) fused gn partial sums + weight conversion
    pre_kernel<<<1024, 256>>>(x, qkv_w, proj_w);

    // 2) GroupNorm normalize
    gn_norm_kernel<<<BATCH * GRP * 8, 256>>>(x, gn_w, gn_b);

    // 3) GEMM1 (MWT=2, EP1): qkv fp16 [3C,N] + bias. M=1536 N=1024 K=512
    gemmf16<2, 1><<<dim3(NTOK / 128, C3 / 128, BATCH), 256, SMB2>>>(
        w1f, xnTh, nullptr, qkvf,
        CH, CH, CH, NTOK,
        0LL, (long long)NTOK * CH, 0LL, (long long)C3 * NTOK,
        qkv_b, nullptr);

    // 4) fused softmaxes (k register-resident in place; q -> transposed plane)
    softmax_kernel<<<384, 512>>>();

    // 5) GEMM2 (MWT=1, EP0): ctxT[c,d] = sum_n k[c,n]*v[d,n]. M=512 N=512 K=1024
    gemmf16<1, 0><<<dim3(CH / 128, CH / 64, BATCH), 256, SMB1>>>(
        qkvf + (size_t)CH * NTOK, qkvf + (size_t)2 * CH * NTOK, nullptr, ctxT,
        NTOK, NTOK, NTOK, CH,
        (long long)C3 * NTOK, (long long)C3 * NTOK, 0LL, (long long)CH * CH,
        nullptr, nullptr);

    // 6) GEMM3' (MWT=1, EP0): M2[d,c] = sum_c' w2[d,c']*ctxT[c,c']. M=512 N=512 K=512
    gemmf16<1, 0><<<dim3(CH / 128, CH / 64, BATCH), 256, SMB1>>>(
        w2f, ctxT, nullptr, m2,
        CH, CH, CH, CH,
        0LL, (long long)CH * CH, 0LL, (long long)CH * CH,
        nullptr, nullptr);

    // 7) GEMM4' (MWT=2, EP2): out[d,n] = sum_c M2[d,c]*qT[n,c] + b + xn. M=512 N=1024 K=512
    gemmf16<2, 2><<<dim3(NTOK / 128, CH / 128, BATCH), 256, SMB2>>>(
        m2, qTh, out, nullptr,
        CH, CH, CH, NTOK,
        (long long)CH * CH, (long long)NTOK * CH, (long long)CH * NTOK, 0LL,
        proj_b, xn);
}